// round 3
// baseline (speedup 1.0000x reference)
#include <cuda_runtime.h>
#include <cuda_bf16.h>
#include <math.h>

// ---------------------------------------------------------------------------
// Problem constants
// ---------------------------------------------------------------------------
#define BB 4
#define TT 128
#define DD 256
#define FF_ 1024
#define NH 8
#define HD_ATT 32
#define VOCAB 32000
#define MD 128
#define MH_ 4
#define HD_ 32
#define IFACE 516       // MH*(4*HD+1)
#define CDIM 384        // D + MD
#define BT (BB*TT)      // 512

// ---------------------------------------------------------------------------
// Scratch (device globals; no allocation allowed)
// ---------------------------------------------------------------------------
__device__ float g_x  [BT*DD];
__device__ float g_h  [BT*DD];
__device__ float g_qkv[BT*3*DD];
__device__ float g_att[BT*DD];
__device__ float g_ff [BT*FF_];
__device__ float g_hf [BT*DD];
__device__ float g_Hif[BT*IFACE];
__device__ float g_rv [BT*MD];
__device__ float g_c  [BT*CDIM];

// ---------------------------------------------------------------------------
// Embedding: x = tok_emb[seq] + pos_emb[:T]
// ---------------------------------------------------------------------------
__global__ void embed_kernel(const int* __restrict__ seq,
                             const float* __restrict__ tok,
                             const float* __restrict__ pos,
                             float* __restrict__ x)
{
    int bt = blockIdx.x;
    int d  = threadIdx.x;
    int t  = bt & (TT-1);
    x[bt*DD + d] = tok[(long)seq[bt]*DD + d] + pos[t*DD + d];
}

// ---------------------------------------------------------------------------
// LayerNorm over D=256, one block per row, 256 threads
// ---------------------------------------------------------------------------
__global__ void ln_kernel(const float* __restrict__ x,
                          const float* __restrict__ g,
                          const float* __restrict__ b,
                          float* __restrict__ o)
{
    int row = blockIdx.x;
    int tid = threadIdx.x;
    __shared__ float red[8];
    float v = x[row*DD + tid];
    float s = v;
    #pragma unroll
    for (int k = 16; k; k >>= 1) s += __shfl_xor_sync(0xffffffffu, s, k);
    if ((tid & 31) == 0) red[tid >> 5] = s;
    __syncthreads();
    float mean = 0.f;
    #pragma unroll
    for (int i = 0; i < 8; i++) mean += red[i];
    mean *= (1.f/256.f);
    __syncthreads();
    float d = v - mean;
    float s2 = d*d;
    #pragma unroll
    for (int k = 16; k; k >>= 1) s2 += __shfl_xor_sync(0xffffffffu, s2, k);
    if ((tid & 31) == 0) red[tid >> 5] = s2;
    __syncthreads();
    float var = 0.f;
    #pragma unroll
    for (int i = 0; i < 8; i++) var += red[i];
    var *= (1.f/256.f);
    o[row*DD + tid] = d * rsqrtf(var + 1e-5f) * g[tid] + b[tid];
}

// ---------------------------------------------------------------------------
// Register-blocked SGEMM: C[M,N] = A[M,K] @ B[K,N] (+bias) (gelu) (+residual)
// BM=64 fixed, BK=16, 256 threads.  M must be a multiple of 64, K of 16.
// ---------------------------------------------------------------------------
template<int BN, int TM, int TN, bool GELU>
__global__ __launch_bounds__(256) void sgemm_kernel(
    int M, int N, int K,
    const float* __restrict__ A, int lda,
    const float* __restrict__ B, int ldb,
    float* __restrict__ C, int ldc,
    const float* __restrict__ bias,
    const float* __restrict__ residual)
{
    constexpr int BM = 64, BK = 16;
    constexpr int TCOLS = BN / TN;
    __shared__ float As[BK][BM];
    __shared__ float Bs[BK][BN];
    const int tid = threadIdx.x;
    const int m0 = blockIdx.y * BM;
    const int n0 = blockIdx.x * BN;
    const int tr = tid / TCOLS;
    const int tc = tid % TCOLS;
    float acc[TM][TN];
    #pragma unroll
    for (int i = 0; i < TM; i++)
        #pragma unroll
        for (int j = 0; j < TN; j++) acc[i][j] = 0.f;

    const int ar = tid >> 2;
    const int ac = (tid & 3) * 4;

    for (int k0 = 0; k0 < K; k0 += BK) {
        // A tile (64x16), store transposed As[k][m]
        float4 a4 = *reinterpret_cast<const float4*>(A + (long)(m0 + ar)*lda + k0 + ac);
        As[ac+0][ar] = a4.x; As[ac+1][ar] = a4.y;
        As[ac+2][ar] = a4.z; As[ac+3][ar] = a4.w;
        // B tile (16xBN), column-guarded (N multiple of 4 in all uses)
        #pragma unroll
        for (int i = 0; i < (BK*BN)/1024; i++) {
            int idx = tid + i*256;
            int r = idx / (BN/4);
            int c = (idx % (BN/4)) * 4;
            float4 b4 = make_float4(0.f, 0.f, 0.f, 0.f);
            if (n0 + c < N)
                b4 = *reinterpret_cast<const float4*>(B + (long)(k0 + r)*ldb + n0 + c);
            *reinterpret_cast<float4*>(&Bs[r][c]) = b4;
        }
        __syncthreads();
        #pragma unroll
        for (int kk = 0; kk < BK; kk++) {
            float a[TM], bb[TN];
            #pragma unroll
            for (int i = 0; i < TM; i += 4) {
                float4 t4 = *reinterpret_cast<const float4*>(&As[kk][tr*TM + i]);
                a[i] = t4.x; a[i+1] = t4.y; a[i+2] = t4.z; a[i+3] = t4.w;
            }
            #pragma unroll
            for (int j = 0; j < TN; j += 4) {
                float4 t4 = *reinterpret_cast<const float4*>(&Bs[kk][tc*TN + j]);
                bb[j] = t4.x; bb[j+1] = t4.y; bb[j+2] = t4.z; bb[j+3] = t4.w;
            }
            #pragma unroll
            for (int i = 0; i < TM; i++)
                #pragma unroll
                for (int j = 0; j < TN; j++)
                    acc[i][j] += a[i]*bb[j];
        }
        __syncthreads();
    }
    #pragma unroll
    for (int i = 0; i < TM; i++) {
        int row = m0 + tr*TM + i;
        #pragma unroll
        for (int j = 0; j < TN; j++) {
            int col = n0 + tc*TN + j;
            if (col < N) {
                float v = acc[i][j];
                if (bias) v += bias[col];
                if (GELU) {
                    float u = v;
                    float tt = 0.7978845608028654f * (u + 0.044715f*u*u*u);
                    v = 0.5f*u*(1.f + tanhf(tt));
                }
                if (residual) v += residual[(long)row*ldc + col];
                C[(long)row*ldc + col] = v;
            }
        }
    }
}

// ---------------------------------------------------------------------------
// Causal attention, one block per (head, batch), one thread per query.
// ---------------------------------------------------------------------------
__global__ __launch_bounds__(128) void attention_kernel(
    const float* __restrict__ qkv, float* __restrict__ att_out)
{
    int h = blockIdx.x;   // 0..7
    int b = blockIdx.y;   // 0..3
    int t = threadIdx.x;  // 0..127
    __shared__ float Ks[TT][HD_ATT];
    __shared__ float Vs[TT][HD_ATT];
    const float scale = 0.17677669529663687f;  // 1/sqrt(32)

    const float* base = qkv + (long)(b*TT + t)*(3*DD) + h*HD_ATT;
    float q[HD_ATT];
    #pragma unroll
    for (int d = 0; d < HD_ATT; d++) q[d] = base[d];
    #pragma unroll
    for (int d = 0; d < HD_ATT; d++) Ks[t][d] = base[DD   + d];
    #pragma unroll
    for (int d = 0; d < HD_ATT; d++) Vs[t][d] = base[2*DD + d];
    __syncthreads();

    float mmax = -1e30f;
    for (int k = 0; k < TT; k++) {
        float s = 0.f;
        #pragma unroll
        for (int d = 0; d < HD_ATT; d++) s += q[d]*Ks[k][d];
        s *= scale;
        if (k <= t) mmax = fmaxf(mmax, s);
    }
    float l = 0.f;
    float acc[HD_ATT];
    #pragma unroll
    for (int d = 0; d < HD_ATT; d++) acc[d] = 0.f;
    for (int k = 0; k < TT; k++) {
        float s = 0.f;
        #pragma unroll
        for (int d = 0; d < HD_ATT; d++) s += q[d]*Ks[k][d];
        float p = (k <= t) ? __expf(s*scale - mmax) : 0.f;
        l += p;
        #pragma unroll
        for (int d = 0; d < HD_ATT; d++) acc[d] += p*Vs[k][d];
    }
    float inv = 1.f / l;
    float* out = att_out + (long)(b*TT + t)*DD + h*HD_ATT;
    #pragma unroll
    for (int d = 0; d < HD_ATT; d++) out[d] = acc[d]*inv;
}

// ---------------------------------------------------------------------------
// Memory scan (collapsed).
//
// M0 = 0 in the reference, so at every step all slot scores are exactly tied
// => top-k threshold selects ALL slots => softmax weights are exactly 1/512
// => all M rows stay identical. The whole (MH,512,HD) memory collapses to one
// 128-float vector m per batch:
//   rv_store[t] = rv
//   iface      = Hpart[b,t] + rv @ W_iface[256:384]  (only wv/erase/gate cols)
//   rv        += m
//   m          = m*(1 - sigmoid(erase)/512) + sigmoid(gate)*(1/512)*wv
// Keys/top-k never influence the result (uniform softmax regardless).
// 4 blocks (one per batch), 320 threads; GEMV weights held in registers.
// ---------------------------------------------------------------------------
__global__ __launch_bounds__(320) void scan_kernel(
    const float* __restrict__ Hif,
    const float* __restrict__ W_iface,
    float* __restrict__ rv_out)
{
    int b   = blockIdx.x;
    int tid = threadIdx.x;
    __shared__ float rv_s[MD];
    __shared__ float m_s[MD];
    __shared__ float if_s[260];

    float w[128];
    int gcol = 0;
    if (tid < 260) {
        gcol = (tid/65)*129 + 64 + (tid%65);   // wv/erase/add_gate columns only
        #pragma unroll
        for (int k = 0; k < 128; k++)
            w[k] = W_iface[(long)(256 + k)*IFACE + gcol];
    }
    if (tid < MD) { rv_s[tid] = 0.f; m_s[tid] = 0.f; }
    __syncthreads();

    for (int t = 0; t < TT; t++) {
        if (tid < MD)
            rv_out[(long)(b*TT + t)*MD + tid] = rv_s[tid];  // carry-in rv
        if (tid < 260) {
            float acc = Hif[(long)(b*TT + t)*IFACE + gcol];
            #pragma unroll
            for (int k = 0; k < 128; k++)
                acc += rv_s[k]*w[k];
            if_s[tid] = acc;
        }
        __syncthreads();
        if (tid < MD) {
            int h = tid >> 5;
            int d = tid & 31;
            int base = h*65;
            float wv = if_s[base + d];
            float er = 1.f / (1.f + __expf(-if_s[base + 32 + d]));
            float ag = 1.f / (1.f + __expf(-if_s[base + 64]));
            float mo = m_s[tid];
            rv_s[tid] = rv_s[tid] + mo;
            m_s[tid]  = mo * (1.f - er*(1.f/512.f)) + (ag*(1.f/512.f))*wv;
        }
        __syncthreads();
    }
}

// ---------------------------------------------------------------------------
// Build C = [hf | rv]  (512 x 384)
// ---------------------------------------------------------------------------
__global__ void concat_kernel(const float* __restrict__ hf,
                              const float* __restrict__ rv,
                              float* __restrict__ c)
{
    int bt = blockIdx.x;
    int j  = threadIdx.x;  // 0..383
    c[bt*CDIM + j] = (j < DD) ? hf[bt*DD + j] : rv[bt*MD + (j - DD)];
}

// ---------------------------------------------------------------------------
// Launch
// ---------------------------------------------------------------------------
extern "C" void kernel_launch(void* const* d_in, const int* in_sizes, int n_in,
                              void* d_out, int out_size)
{
    const int*   seq   = (const int*)  d_in[0];
    const float* tok   = (const float*)d_in[1];
    const float* pos   = (const float*)d_in[2];
    const float* Wqkv  = (const float*)d_in[3];
    const float* Wo    = (const float*)d_in[4];
    const float* ln1g  = (const float*)d_in[5];
    const float* ln1b  = (const float*)d_in[6];
    const float* ln2g  = (const float*)d_in[7];
    const float* ln2b  = (const float*)d_in[8];
    const float* W1    = (const float*)d_in[9];
    const float* b1    = (const float*)d_in[10];
    const float* W2    = (const float*)d_in[11];
    const float* b2    = (const float*)d_in[12];
    const float* lnfg  = (const float*)d_in[13];
    const float* lnfb  = (const float*)d_in[14];
    const float* Wlog  = (const float*)d_in[15];
    const float* blog  = (const float*)d_in[16];
    const float* Wif   = (const float*)d_in[17];
    const float* bif   = (const float*)d_in[18];
    float* out = (float*)d_out;

    float *gx, *gh, *gqkv, *gatt, *gff, *ghf, *gHif, *grv, *gc;
    cudaGetSymbolAddress((void**)&gx,   g_x);
    cudaGetSymbolAddress((void**)&gh,   g_h);
    cudaGetSymbolAddress((void**)&gqkv, g_qkv);
    cudaGetSymbolAddress((void**)&gatt, g_att);
    cudaGetSymbolAddress((void**)&gff,  g_ff);
    cudaGetSymbolAddress((void**)&ghf,  g_hf);
    cudaGetSymbolAddress((void**)&gHif, g_Hif);
    cudaGetSymbolAddress((void**)&grv,  g_rv);
    cudaGetSymbolAddress((void**)&gc,   g_c);

    embed_kernel<<<BT, DD>>>(seq, tok, pos, gx);

    for (int l = 0; l < 2; l++) {
        ln_kernel<<<BT, DD>>>(gx, ln1g + l*DD, ln1b + l*DD, gh);
        sgemm_kernel<64,4,4,false><<<dim3(12, 8), 256>>>(
            BT, 3*DD, DD, gh, DD, Wqkv + (long)l*DD*3*DD, 3*DD,
            gqkv, 3*DD, nullptr, nullptr);
        attention_kernel<<<dim3(NH, BB), TT>>>(gqkv, gatt);
        sgemm_kernel<64,4,4,false><<<dim3(4, 8), 256>>>(
            BT, DD, DD, gatt, DD, Wo + (long)l*DD*DD, DD,
            gx, DD, nullptr, gx);
        ln_kernel<<<BT, DD>>>(gx, ln2g + l*DD, ln2b + l*DD, gh);
        sgemm_kernel<128,8,4,true><<<dim3(8, 8), 256>>>(
            BT, FF_, DD, gh, DD, W1 + (long)l*DD*FF_, FF_,
            gff, FF_, b1 + l*FF_, nullptr);
        sgemm_kernel<64,4,4,false><<<dim3(4, 8), 256>>>(
            BT, DD, FF_, gff, FF_, W2 + (long)l*FF_*DD, DD,
            gx, DD, b2 + l*DD, gx);
    }

    ln_kernel<<<BT, DD>>>(gx, lnfg, lnfb, ghf);

    // H-part of the interface: hf @ W_iface[0:256] + b_iface
    sgemm_kernel<64,4,4,false><<<dim3((IFACE + 63)/64, 8), 256>>>(
        BT, IFACE, DD, ghf, DD, Wif, IFACE, gHif, IFACE, bif, nullptr);

    scan_kernel<<<BB, 320>>>(gHif, Wif, grv);

    concat_kernel<<<BT, CDIM>>>(ghf, grv, gc);

    // logits = C @ W_logits + b_logits   (dominant GEMM: 512x32000x384)
    sgemm_kernel<128,8,4,false><<<dim3(VOCAB/128, 8), 256>>>(
        BT, VOCAB, CDIM, gc, CDIM, Wlog, VOCAB, out, VOCAB, blog, nullptr);
}

// round 4
// speedup vs baseline: 1.0570x; 1.0570x over previous
#include <cuda_runtime.h>
#include <cuda_bf16.h>
#include <math.h>

// ---------------------------------------------------------------------------
// Problem constants
// ---------------------------------------------------------------------------
#define BB 4
#define TT 128
#define DD 256
#define FF_ 1024
#define NH 8
#define HD_ATT 32
#define VOCAB 32000
#define MD 128
#define IFACE 516       // MH*(4*HD+1)
#define CDIM 384        // D + MD
#define BT (BB*TT)      // 512

// ---------------------------------------------------------------------------
// Scratch (device globals; no allocation allowed)
// ---------------------------------------------------------------------------
__device__ float g_x  [BT*DD];
__device__ float g_h  [BT*DD];
__device__ float g_qkv[BT*3*DD];
__device__ float g_att[BT*DD];
__device__ float g_ff [BT*FF_];
__device__ float g_hf [BT*DD];
__device__ float g_Hif[BT*IFACE];
__device__ float g_rv [BT*MD];
__device__ float g_c  [BT*CDIM];

// ---------------------------------------------------------------------------
// Embedding: x = tok_emb[seq] + pos_emb[:T]
// ---------------------------------------------------------------------------
__global__ void embed_kernel(const int* __restrict__ seq,
                             const float* __restrict__ tok,
                             const float* __restrict__ pos,
                             float* __restrict__ x)
{
    int bt = blockIdx.x;
    int d  = threadIdx.x;
    int t  = bt & (TT-1);
    x[bt*DD + d] = tok[(long)seq[bt]*DD + d] + pos[t*DD + d];
}

// ---------------------------------------------------------------------------
// LayerNorm over D=256, one block per row, 256 threads
// ---------------------------------------------------------------------------
__global__ void ln_kernel(const float* __restrict__ x,
                          const float* __restrict__ g,
                          const float* __restrict__ b,
                          float* __restrict__ o)
{
    int row = blockIdx.x;
    int tid = threadIdx.x;
    __shared__ float red[8];
    float v = x[row*DD + tid];
    float s = v;
    #pragma unroll
    for (int k = 16; k; k >>= 1) s += __shfl_xor_sync(0xffffffffu, s, k);
    if ((tid & 31) == 0) red[tid >> 5] = s;
    __syncthreads();
    float mean = 0.f;
    #pragma unroll
    for (int i = 0; i < 8; i++) mean += red[i];
    mean *= (1.f/256.f);
    __syncthreads();
    float d = v - mean;
    float s2 = d*d;
    #pragma unroll
    for (int k = 16; k; k >>= 1) s2 += __shfl_xor_sync(0xffffffffu, s2, k);
    if ((tid & 31) == 0) red[tid >> 5] = s2;
    __syncthreads();
    float var = 0.f;
    #pragma unroll
    for (int i = 0; i < 8; i++) var += red[i];
    var *= (1.f/256.f);
    o[row*DD + tid] = d * rsqrtf(var + 1e-5f) * g[tid] + b[tid];
}

// ---------------------------------------------------------------------------
// Small SGEMM (transformer GEMMs): BM=64, BK=16, 256 threads
// ---------------------------------------------------------------------------
template<int BN, int TM, int TN, bool GELU>
__global__ __launch_bounds__(256) void sgemm_kernel(
    int M, int N, int K,
    const float* __restrict__ A, int lda,
    const float* __restrict__ B, int ldb,
    float* __restrict__ C, int ldc,
    const float* __restrict__ bias,
    const float* __restrict__ residual)
{
    constexpr int BM = 64, BK = 16;
    constexpr int TCOLS = BN / TN;
    __shared__ float As[BK][BM];
    __shared__ float Bs[BK][BN];
    const int tid = threadIdx.x;
    const int m0 = blockIdx.y * BM;
    const int n0 = blockIdx.x * BN;
    const int tr = tid / TCOLS;
    const int tc = tid % TCOLS;
    float acc[TM][TN];
    #pragma unroll
    for (int i = 0; i < TM; i++)
        #pragma unroll
        for (int j = 0; j < TN; j++) acc[i][j] = 0.f;

    const int ar = tid >> 2;
    const int ac = (tid & 3) * 4;

    for (int k0 = 0; k0 < K; k0 += BK) {
        float4 a4 = *reinterpret_cast<const float4*>(A + (long)(m0 + ar)*lda + k0 + ac);
        As[ac+0][ar] = a4.x; As[ac+1][ar] = a4.y;
        As[ac+2][ar] = a4.z; As[ac+3][ar] = a4.w;
        #pragma unroll
        for (int i = 0; i < (BK*BN)/1024; i++) {
            int idx = tid + i*256;
            int r = idx / (BN/4);
            int c = (idx % (BN/4)) * 4;
            float4 b4 = make_float4(0.f, 0.f, 0.f, 0.f);
            if (n0 + c < N)
                b4 = *reinterpret_cast<const float4*>(B + (long)(k0 + r)*ldb + n0 + c);
            *reinterpret_cast<float4*>(&Bs[r][c]) = b4;
        }
        __syncthreads();
        #pragma unroll
        for (int kk = 0; kk < BK; kk++) {
            float a[TM], bb[TN];
            #pragma unroll
            for (int i = 0; i < TM; i += 4) {
                float4 t4 = *reinterpret_cast<const float4*>(&As[kk][tr*TM + i]);
                a[i] = t4.x; a[i+1] = t4.y; a[i+2] = t4.z; a[i+3] = t4.w;
            }
            #pragma unroll
            for (int j = 0; j < TN; j += 4) {
                float4 t4 = *reinterpret_cast<const float4*>(&Bs[kk][tc*TN + j]);
                bb[j] = t4.x; bb[j+1] = t4.y; bb[j+2] = t4.z; bb[j+3] = t4.w;
            }
            #pragma unroll
            for (int i = 0; i < TM; i++)
                #pragma unroll
                for (int j = 0; j < TN; j++)
                    acc[i][j] += a[i]*bb[j];
        }
        __syncthreads();
    }
    #pragma unroll
    for (int i = 0; i < TM; i++) {
        int row = m0 + tr*TM + i;
        #pragma unroll
        for (int j = 0; j < TN; j++) {
            int col = n0 + tc*TN + j;
            if (col < N) {
                float v = acc[i][j];
                if (bias) v += bias[col];
                if (GELU) {
                    float u = v;
                    float tt = 0.7978845608028654f * (u + 0.044715f*u*u*u);
                    v = 0.5f*u*(1.f + tanhf(tt));
                }
                if (residual) v += residual[(long)row*ldc + col];
                C[(long)row*ldc + col] = v;
            }
        }
    }
}

// ---------------------------------------------------------------------------
// Big SGEMM (logits): 128x128 tiles, BK=8, double-buffered, 256 threads.
// Requires M%128==0, N%128==0, K%8==0 (holds: 512, 32000, 384).
// ---------------------------------------------------------------------------
__global__ __launch_bounds__(256) void sgemm_big(
    int K,
    const float* __restrict__ A, int lda,
    const float* __restrict__ B, int ldb,
    float* __restrict__ C, int ldc,
    const float* __restrict__ bias)
{
    __shared__ float As[2][8][128];
    __shared__ float Bs[2][8][128];
    const int tid = threadIdx.x;
    const int m0 = blockIdx.y * 128;
    const int n0 = blockIdx.x * 128;
    const int tr = tid >> 4;        // 0..15
    const int tc = tid & 15;        // 0..15

    const int arow = tid >> 1;          // 0..127
    const int acol = (tid & 1) << 2;    // 0 or 4
    const int brow = tid >> 5;          // 0..7
    const int bcol = (tid & 31) << 2;   // 0..124

    const float* Aptr = A + (long)(m0 + arow)*lda + acol;
    const float* Bptr = B + (long)brow*ldb + n0 + bcol;

    float acc[8][8];
    #pragma unroll
    for (int i = 0; i < 8; i++)
        #pragma unroll
        for (int j = 0; j < 8; j++) acc[i][j] = 0.f;

    // preload tile 0
    {
        float4 a4 = *reinterpret_cast<const float4*>(Aptr);
        float4 b4 = *reinterpret_cast<const float4*>(Bptr);
        As[0][acol+0][arow] = a4.x; As[0][acol+1][arow] = a4.y;
        As[0][acol+2][arow] = a4.z; As[0][acol+3][arow] = a4.w;
        *reinterpret_cast<float4*>(&Bs[0][brow][bcol]) = b4;
    }
    __syncthreads();

    int buf = 0;
    for (int k0 = 0; k0 < K; k0 += 8) {
        float4 a4n, b4n;
        const bool more = (k0 + 8) < K;
        if (more) {
            a4n = *reinterpret_cast<const float4*>(Aptr + k0 + 8);
            b4n = *reinterpret_cast<const float4*>(Bptr + (long)(k0 + 8)*ldb);
        }
        #pragma unroll
        for (int kk = 0; kk < 8; kk++) {
            float a[8], bb[8];
            float4 t;
            t = *reinterpret_cast<const float4*>(&As[buf][kk][tr*8]);
            a[0]=t.x; a[1]=t.y; a[2]=t.z; a[3]=t.w;
            t = *reinterpret_cast<const float4*>(&As[buf][kk][tr*8+4]);
            a[4]=t.x; a[5]=t.y; a[6]=t.z; a[7]=t.w;
            t = *reinterpret_cast<const float4*>(&Bs[buf][kk][tc*8]);
            bb[0]=t.x; bb[1]=t.y; bb[2]=t.z; bb[3]=t.w;
            t = *reinterpret_cast<const float4*>(&Bs[buf][kk][tc*8+4]);
            bb[4]=t.x; bb[5]=t.y; bb[6]=t.z; bb[7]=t.w;
            #pragma unroll
            for (int i = 0; i < 8; i++)
                #pragma unroll
                for (int j = 0; j < 8; j++)
                    acc[i][j] += a[i]*bb[j];
        }
        if (more) {
            As[buf^1][acol+0][arow] = a4n.x; As[buf^1][acol+1][arow] = a4n.y;
            As[buf^1][acol+2][arow] = a4n.z; As[buf^1][acol+3][arow] = a4n.w;
            *reinterpret_cast<float4*>(&Bs[buf^1][brow][bcol]) = b4n;
        }
        __syncthreads();
        buf ^= 1;
    }

    #pragma unroll
    for (int i = 0; i < 8; i++) {
        int row = m0 + tr*8 + i;
        float* crow = C + (long)row*ldc + n0 + tc*8;
        float4 o0, o1;
        o0.x = acc[i][0] + bias[n0 + tc*8 + 0];
        o0.y = acc[i][1] + bias[n0 + tc*8 + 1];
        o0.z = acc[i][2] + bias[n0 + tc*8 + 2];
        o0.w = acc[i][3] + bias[n0 + tc*8 + 3];
        o1.x = acc[i][4] + bias[n0 + tc*8 + 4];
        o1.y = acc[i][5] + bias[n0 + tc*8 + 5];
        o1.z = acc[i][6] + bias[n0 + tc*8 + 6];
        o1.w = acc[i][7] + bias[n0 + tc*8 + 7];
        *reinterpret_cast<float4*>(crow)     = o0;
        *reinterpret_cast<float4*>(crow + 4) = o1;
    }
}

// ---------------------------------------------------------------------------
// Causal attention v2: block = (head, batch, q-chunk of 16). 128 threads.
// Single pass: scores staged in smem, warp-shfl softmax, conflict-free pads.
// ---------------------------------------------------------------------------
#define QC 16
__global__ __launch_bounds__(128) void attention_kernel(
    const float* __restrict__ qkv, float* __restrict__ att_out)
{
    __shared__ float Ks[TT][36];      // pad 36: conflict-free float4 reads
    __shared__ float Vs[TT][32];
    __shared__ float Ps[QC][129];     // pad 129: conflict-free P reads
    const int h  = blockIdx.x;
    const int b  = blockIdx.y;
    const int qc = blockIdx.z;
    const int tid = threadIdx.x;
    const float scale = 0.17677669529663687f;   // 1/sqrt(32)

    // Load K/V rows (one row per thread)
    {
        const float* kp = qkv + (long)(b*TT + tid)*(3*DD) + DD + h*HD_ATT;
        const float* vp = kp + DD;
        #pragma unroll
        for (int d = 0; d < 32; d += 4) {
            *reinterpret_cast<float4*>(&Ks[tid][d]) = *reinterpret_cast<const float4*>(kp + d);
            *reinterpret_cast<float4*>(&Vs[tid][d]) = *reinterpret_cast<const float4*>(vp + d);
        }
    }
    __syncthreads();

    const int q = tid >> 3;           // 0..15
    const int j = tid & 7;            // 0..7
    const int qglob = qc*QC + q;

    // Query row in registers
    float qv[32];
    {
        const float* qp = qkv + (long)(b*TT + qglob)*(3*DD) + h*HD_ATT;
        #pragma unroll
        for (int d = 0; d < 32; d += 4) {
            float4 t = *reinterpret_cast<const float4*>(qp + d);
            qv[d]=t.x; qv[d+1]=t.y; qv[d+2]=t.z; qv[d+3]=t.w;
        }
    }

    // Scores for keys k = kk*8 + j
    float s[16];
    float mmax = -1e30f;
    #pragma unroll
    for (int kk = 0; kk < 16; kk++) {
        int k = kk*8 + j;
        float acc = 0.f;
        #pragma unroll
        for (int d = 0; d < 32; d += 4) {
            float4 kv = *reinterpret_cast<const float4*>(&Ks[k][d]);
            acc += qv[d]*kv.x + qv[d+1]*kv.y + qv[d+2]*kv.z + qv[d+3]*kv.w;
        }
        s[kk] = (k <= qglob) ? acc*scale : -1e30f;
        mmax = fmaxf(mmax, s[kk]);
    }
    #pragma unroll
    for (int o = 1; o < 8; o <<= 1)
        mmax = fmaxf(mmax, __shfl_xor_sync(0xffffffffu, mmax, o));

    float l = 0.f;
    #pragma unroll
    for (int kk = 0; kk < 16; kk++) {
        float p = __expf(s[kk] - mmax);   // masked: exp(-huge) -> 0
        l += p;
        Ps[q][kk*8 + j] = p;
    }
    #pragma unroll
    for (int o = 1; o < 8; o <<= 1)
        l += __shfl_xor_sync(0xffffffffu, l, o);
    float linv = 1.f / l;
    __syncthreads();

    // Output dims j*4 .. j*4+3
    float ox=0.f, oy=0.f, oz=0.f, ow=0.f;
    #pragma unroll 4
    for (int k = 0; k < TT; k++) {
        float p = Ps[q][k];
        float4 v = *reinterpret_cast<const float4*>(&Vs[k][j*4]);
        ox += p*v.x; oy += p*v.y; oz += p*v.z; ow += p*v.w;
    }
    float4 o4 = make_float4(ox*linv, oy*linv, oz*linv, ow*linv);
    *reinterpret_cast<float4*>(att_out + (long)(b*TT + qglob)*DD + h*HD_ATT + j*4) = o4;
}

// ---------------------------------------------------------------------------
// Memory scan (collapsed — see derivation in round 2: M0=0 makes all slot
// scores tied forever, top-k selects all, softmax = 1/512 uniform).
// ---------------------------------------------------------------------------
__global__ __launch_bounds__(320) void scan_kernel(
    const float* __restrict__ Hif,
    const float* __restrict__ W_iface,
    float* __restrict__ rv_out)
{
    int b   = blockIdx.x;
    int tid = threadIdx.x;
    __shared__ float rv_s[MD];
    __shared__ float m_s[MD];
    __shared__ float if_s[260];

    float w[128];
    int gcol = 0;
    if (tid < 260) {
        gcol = (tid/65)*129 + 64 + (tid%65);   // wv/erase/add_gate columns only
        #pragma unroll
        for (int k = 0; k < 128; k++)
            w[k] = W_iface[(long)(256 + k)*IFACE + gcol];
    }
    if (tid < MD) { rv_s[tid] = 0.f; m_s[tid] = 0.f; }
    __syncthreads();

    for (int t = 0; t < TT; t++) {
        if (tid < MD)
            rv_out[(long)(b*TT + t)*MD + tid] = rv_s[tid];  // carry-in rv
        if (tid < 260) {
            float acc = Hif[(long)(b*TT + t)*IFACE + gcol];
            #pragma unroll
            for (int k = 0; k < 128; k++)
                acc += rv_s[k]*w[k];
            if_s[tid] = acc;
        }
        __syncthreads();
        if (tid < MD) {
            int hh = tid >> 5;
            int d  = tid & 31;
            int base = hh*65;
            float wv = if_s[base + d];
            float er = 1.f / (1.f + __expf(-if_s[base + 32 + d]));
            float ag = 1.f / (1.f + __expf(-if_s[base + 64]));
            float mo = m_s[tid];
            rv_s[tid] = rv_s[tid] + mo;
            m_s[tid]  = mo * (1.f - er*(1.f/512.f)) + (ag*(1.f/512.f))*wv;
        }
        __syncthreads();
    }
}

// ---------------------------------------------------------------------------
// Build C = [hf | rv]  (512 x 384)
// ---------------------------------------------------------------------------
__global__ void concat_kernel(const float* __restrict__ hf,
                              const float* __restrict__ rv,
                              float* __restrict__ c)
{
    int bt = blockIdx.x;
    int j  = threadIdx.x;  // 0..383
    c[bt*CDIM + j] = (j < DD) ? hf[bt*DD + j] : rv[bt*MD + (j - DD)];
}

// ---------------------------------------------------------------------------
// Launch
// ---------------------------------------------------------------------------
extern "C" void kernel_launch(void* const* d_in, const int* in_sizes, int n_in,
                              void* d_out, int out_size)
{
    const int*   seq   = (const int*)  d_in[0];
    const float* tok   = (const float*)d_in[1];
    const float* pos   = (const float*)d_in[2];
    const float* Wqkv  = (const float*)d_in[3];
    const float* Wo    = (const float*)d_in[4];
    const float* ln1g  = (const float*)d_in[5];
    const float* ln1b  = (const float*)d_in[6];
    const float* ln2g  = (const float*)d_in[7];
    const float* ln2b  = (const float*)d_in[8];
    const float* W1    = (const float*)d_in[9];
    const float* b1    = (const float*)d_in[10];
    const float* W2    = (const float*)d_in[11];
    const float* b2    = (const float*)d_in[12];
    const float* lnfg  = (const float*)d_in[13];
    const float* lnfb  = (const float*)d_in[14];
    const float* Wlog  = (const float*)d_in[15];
    const float* blog  = (const float*)d_in[16];
    const float* Wif   = (const float*)d_in[17];
    const float* bif   = (const float*)d_in[18];
    float* out = (float*)d_out;

    float *gx, *gh, *gqkv, *gatt, *gff, *ghf, *gHif, *grv, *gc;
    cudaGetSymbolAddress((void**)&gx,   g_x);
    cudaGetSymbolAddress((void**)&gh,   g_h);
    cudaGetSymbolAddress((void**)&gqkv, g_qkv);
    cudaGetSymbolAddress((void**)&gatt, g_att);
    cudaGetSymbolAddress((void**)&gff,  g_ff);
    cudaGetSymbolAddress((void**)&ghf,  g_hf);
    cudaGetSymbolAddress((void**)&gHif, g_Hif);
    cudaGetSymbolAddress((void**)&grv,  g_rv);
    cudaGetSymbolAddress((void**)&gc,   g_c);

    embed_kernel<<<BT, DD>>>(seq, tok, pos, gx);

    for (int l = 0; l < 2; l++) {
        ln_kernel<<<BT, DD>>>(gx, ln1g + l*DD, ln1b + l*DD, gh);
        sgemm_kernel<64,4,4,false><<<dim3(12, 8), 256>>>(
            BT, 3*DD, DD, gh, DD, Wqkv + (long)l*DD*3*DD, 3*DD,
            gqkv, 3*DD, nullptr, nullptr);
        attention_kernel<<<dim3(NH, BB, TT/QC), 128>>>(gqkv, gatt);
        sgemm_kernel<64,4,4,false><<<dim3(4, 8), 256>>>(
            BT, DD, DD, gatt, DD, Wo + (long)l*DD*DD, DD,
            gx, DD, nullptr, gx);
        ln_kernel<<<BT, DD>>>(gx, ln2g + l*DD, ln2b + l*DD, gh);
        sgemm_kernel<64,4,4,true><<<dim3(16, 8), 256>>>(
            BT, FF_, DD, gh, DD, W1 + (long)l*DD*FF_, FF_,
            gff, FF_, b1 + l*FF_, nullptr);
        sgemm_kernel<64,4,4,false><<<dim3(4, 8), 256>>>(
            BT, DD, FF_, gff, FF_, W2 + (long)l*FF_*DD, DD,
            gx, DD, b2 + l*DD, gx);
    }

    ln_kernel<<<BT, DD>>>(gx, lnfg, lnfb, ghf);

    // H-part of the interface: hf @ W_iface[0:256] + b_iface
    sgemm_kernel<64,4,4,false><<<dim3((IFACE + 63)/64, 8), 256>>>(
        BT, IFACE, DD, ghf, DD, Wif, IFACE, gHif, IFACE, bif, nullptr);

    scan_kernel<<<BB, 320>>>(gHif, Wif, grv);

    concat_kernel<<<BT, CDIM>>>(ghf, grv, gc);

    // logits = C @ W_logits + b_logits   (dominant GEMM: 512x32000x384)
    sgemm_big<<<dim3(VOCAB/128, BT/128), 256>>>(
        CDIM, gc, CDIM, Wlog, VOCAB, out, VOCAB, blog);
}

// round 5
// speedup vs baseline: 1.4619x; 1.3830x over previous
#include <cuda_runtime.h>
#include <cuda_bf16.h>
#include <math.h>

// ---------------------------------------------------------------------------
// Problem constants
// ---------------------------------------------------------------------------
#define BB 4
#define TT 128
#define DD 256
#define FF_ 1024
#define NH 8
#define HD_ATT 32
#define VOCAB 32000
#define MD 128
#define IFACE 516       // MH*(4*HD+1)
#define CDIM 384        // D + MD
#define BT (BB*TT)      // 512

// ---------------------------------------------------------------------------
// Scratch (device globals; no allocation allowed)
// ---------------------------------------------------------------------------
__device__ float g_x  [BT*DD];
__device__ float g_h  [BT*DD];
__device__ float g_qkv[BT*3*DD];
__device__ float g_att[BT*DD];
__device__ float g_ff [BT*FF_];
__device__ float g_hf [BT*DD];
__device__ float g_Hif[BT*IFACE];
__device__ float g_rv [BT*MD];
__device__ float g_c  [BT*CDIM];

// ---------------------------------------------------------------------------
// Embedding: x = tok_emb[seq] + pos_emb[:T]
// ---------------------------------------------------------------------------
__global__ void embed_kernel(const int* __restrict__ seq,
                             const float* __restrict__ tok,
                             const float* __restrict__ pos,
                             float* __restrict__ x)
{
    int bt = blockIdx.x;
    int d  = threadIdx.x;
    int t  = bt & (TT-1);
    x[bt*DD + d] = tok[(long)seq[bt]*DD + d] + pos[t*DD + d];
}

// ---------------------------------------------------------------------------
// LayerNorm over D=256, one block per row, 256 threads
// ---------------------------------------------------------------------------
__global__ void ln_kernel(const float* __restrict__ x,
                          const float* __restrict__ g,
                          const float* __restrict__ b,
                          float* __restrict__ o)
{
    int row = blockIdx.x;
    int tid = threadIdx.x;
    __shared__ float red[8];
    float v = x[row*DD + tid];
    float s = v;
    #pragma unroll
    for (int k = 16; k; k >>= 1) s += __shfl_xor_sync(0xffffffffu, s, k);
    if ((tid & 31) == 0) red[tid >> 5] = s;
    __syncthreads();
    float mean = 0.f;
    #pragma unroll
    for (int i = 0; i < 8; i++) mean += red[i];
    mean *= (1.f/256.f);
    __syncthreads();
    float d = v - mean;
    float s2 = d*d;
    #pragma unroll
    for (int k = 16; k; k >>= 1) s2 += __shfl_xor_sync(0xffffffffu, s2, k);
    if ((tid & 31) == 0) red[tid >> 5] = s2;
    __syncthreads();
    float var = 0.f;
    #pragma unroll
    for (int i = 0; i < 8; i++) var += red[i];
    var *= (1.f/256.f);
    o[row*DD + tid] = d * rsqrtf(var + 1e-5f) * g[tid] + b[tid];
}

// ---------------------------------------------------------------------------
// Small SGEMM (transformer GEMMs): BM=64, BK=16, 256 threads
// ---------------------------------------------------------------------------
template<int BN, int TM, int TN, bool GELU>
__global__ __launch_bounds__(256) void sgemm_kernel(
    int M, int N, int K,
    const float* __restrict__ A, int lda,
    const float* __restrict__ B, int ldb,
    float* __restrict__ C, int ldc,
    const float* __restrict__ bias,
    const float* __restrict__ residual)
{
    constexpr int BM = 64, BK = 16;
    constexpr int TCOLS = BN / TN;
    __shared__ float As[BK][BM];
    __shared__ float Bs[BK][BN];
    const int tid = threadIdx.x;
    const int m0 = blockIdx.y * BM;
    const int n0 = blockIdx.x * BN;
    const int tr = tid / TCOLS;
    const int tc = tid % TCOLS;
    float acc[TM][TN];
    #pragma unroll
    for (int i = 0; i < TM; i++)
        #pragma unroll
        for (int j = 0; j < TN; j++) acc[i][j] = 0.f;

    const int ar = tid >> 2;
    const int ac = (tid & 3) * 4;

    for (int k0 = 0; k0 < K; k0 += BK) {
        float4 a4 = *reinterpret_cast<const float4*>(A + (long)(m0 + ar)*lda + k0 + ac);
        As[ac+0][ar] = a4.x; As[ac+1][ar] = a4.y;
        As[ac+2][ar] = a4.z; As[ac+3][ar] = a4.w;
        #pragma unroll
        for (int i = 0; i < (BK*BN)/1024; i++) {
            int idx = tid + i*256;
            int r = idx / (BN/4);
            int c = (idx % (BN/4)) * 4;
            float4 b4 = make_float4(0.f, 0.f, 0.f, 0.f);
            if (n0 + c < N)
                b4 = *reinterpret_cast<const float4*>(B + (long)(k0 + r)*ldb + n0 + c);
            *reinterpret_cast<float4*>(&Bs[r][c]) = b4;
        }
        __syncthreads();
        #pragma unroll
        for (int kk = 0; kk < BK; kk++) {
            float a[TM], bb[TN];
            #pragma unroll
            for (int i = 0; i < TM; i += 4) {
                float4 t4 = *reinterpret_cast<const float4*>(&As[kk][tr*TM + i]);
                a[i] = t4.x; a[i+1] = t4.y; a[i+2] = t4.z; a[i+3] = t4.w;
            }
            #pragma unroll
            for (int j = 0; j < TN; j += 4) {
                float4 t4 = *reinterpret_cast<const float4*>(&Bs[kk][tc*TN + j]);
                bb[j] = t4.x; bb[j+1] = t4.y; bb[j+2] = t4.z; bb[j+3] = t4.w;
            }
            #pragma unroll
            for (int i = 0; i < TM; i++)
                #pragma unroll
                for (int j = 0; j < TN; j++)
                    acc[i][j] += a[i]*bb[j];
        }
        __syncthreads();
    }
    #pragma unroll
    for (int i = 0; i < TM; i++) {
        int row = m0 + tr*TM + i;
        #pragma unroll
        for (int j = 0; j < TN; j++) {
            int col = n0 + tc*TN + j;
            if (col < N) {
                float v = acc[i][j];
                if (bias) v += bias[col];
                if (GELU) {
                    float u = v;
                    float tt = 0.7978845608028654f * (u + 0.044715f*u*u*u);
                    v = 0.5f*u*(1.f + tanhf(tt));
                }
                if (residual) v += residual[(long)row*ldc + col];
                C[(long)row*ldc + col] = v;
            }
        }
    }
}

// ---------------------------------------------------------------------------
// TF32 tensor-core GEMM for logits: C[512,32000] = A[512,384] @ B[384,32000]
// Block tile 128x128, K-tile 32, 8 warps (2x4), warp tile 64x32, m16n8k8.
// A/B converted to tf32 at smem-store time. Padded smem strides (36 / 136)
// are conflict-free for the mma fragment lane mappings and 16B-divisible.
// ---------------------------------------------------------------------------
__device__ __forceinline__ unsigned f2tf32(float x) {
    unsigned r;
    asm("cvt.rna.tf32.f32 %0, %1;" : "=r"(r) : "f"(x));
    return r;
}

__global__ __launch_bounds__(256) void gemm_tf32_kernel(
    const float* __restrict__ A,     // [512 x 384]
    const float* __restrict__ B,     // [384 x 32000]
    float* __restrict__ C,           // [512 x 32000]
    const float* __restrict__ bias)  // [32000]
{
    __shared__ float As[128][36];    // [m][k], stride 36: conflict-free frags
    __shared__ float Bs[32][136];    // [k][n], stride 136: conflict-free frags

    const int tid  = threadIdx.x;
    const int lane = tid & 31;
    const int wid  = tid >> 5;
    const int wm   = (wid >> 2) * 64;   // warp m offset (0 or 64)
    const int wn   = (wid & 3) * 32;    // warp n offset (0,32,64,96)
    const int m0   = blockIdx.y * 128;
    const int n0   = blockIdx.x * 128;

    float acc[16][4];
    #pragma unroll
    for (int i = 0; i < 16; i++)
        #pragma unroll
        for (int j = 0; j < 4; j++) acc[i][j] = 0.f;

    const int g  = lane >> 2;   // 0..7
    const int tg = lane & 3;    // 0..3

    #pragma unroll 1
    for (int k0 = 0; k0 < CDIM; k0 += 32) {
        // ---- fill As (128x32) ----
        #pragma unroll
        for (int i = 0; i < 4; i++) {
            int idx = i*256 + tid;
            int r  = idx >> 3;
            int c4 = (idx & 7) << 2;
            float4 v = *reinterpret_cast<const float4*>(A + (long)(m0 + r)*CDIM + k0 + c4);
            float4 w;
            w.x = __uint_as_float(f2tf32(v.x));
            w.y = __uint_as_float(f2tf32(v.y));
            w.z = __uint_as_float(f2tf32(v.z));
            w.w = __uint_as_float(f2tf32(v.w));
            *reinterpret_cast<float4*>(&As[r][c4]) = w;
        }
        // ---- fill Bs (32x128) ----
        #pragma unroll
        for (int i = 0; i < 4; i++) {
            int idx = i*256 + tid;
            int r  = idx >> 5;
            int c4 = (idx & 31) << 2;
            float4 v = *reinterpret_cast<const float4*>(B + (long)(k0 + r)*VOCAB + n0 + c4);
            float4 w;
            w.x = __uint_as_float(f2tf32(v.x));
            w.y = __uint_as_float(f2tf32(v.y));
            w.z = __uint_as_float(f2tf32(v.z));
            w.w = __uint_as_float(f2tf32(v.w));
            *reinterpret_cast<float4*>(&Bs[r][c4]) = w;
        }
        __syncthreads();

        #pragma unroll
        for (int ks = 0; ks < 32; ks += 8) {
            unsigned af[4][4];
            #pragma unroll
            for (int mt = 0; mt < 4; mt++) {
                int mr = wm + mt*16 + g;
                af[mt][0] = __float_as_uint(As[mr  ][ks + tg    ]);
                af[mt][1] = __float_as_uint(As[mr+8][ks + tg    ]);
                af[mt][2] = __float_as_uint(As[mr  ][ks + tg + 4]);
                af[mt][3] = __float_as_uint(As[mr+8][ks + tg + 4]);
            }
            unsigned bf[4][2];
            #pragma unroll
            for (int nt = 0; nt < 4; nt++) {
                int nc = wn + nt*8 + g;
                bf[nt][0] = __float_as_uint(Bs[ks + tg    ][nc]);
                bf[nt][1] = __float_as_uint(Bs[ks + tg + 4][nc]);
            }
            #pragma unroll
            for (int mt = 0; mt < 4; mt++)
                #pragma unroll
                for (int nt = 0; nt < 4; nt++) {
                    float* c = acc[mt*4 + nt];
                    asm volatile(
                        "mma.sync.aligned.m16n8k8.row.col.f32.tf32.tf32.f32 "
                        "{%0,%1,%2,%3}, {%4,%5,%6,%7}, {%8,%9}, {%0,%1,%2,%3};"
                        : "+f"(c[0]), "+f"(c[1]), "+f"(c[2]), "+f"(c[3])
                        : "r"(af[mt][0]), "r"(af[mt][1]), "r"(af[mt][2]), "r"(af[mt][3]),
                          "r"(bf[nt][0]), "r"(bf[nt][1]));
                }
        }
        __syncthreads();
    }

    // ---- epilogue: C = acc + bias ----
    #pragma unroll
    for (int nt = 0; nt < 4; nt++) {
        int n = n0 + wn + nt*8 + 2*tg;
        float2 bz = *reinterpret_cast<const float2*>(bias + n);
        #pragma unroll
        for (int mt = 0; mt < 4; mt++) {
            int m = m0 + wm + mt*16 + g;
            float* c = acc[mt*4 + nt];
            float2 o0 = make_float2(c[0] + bz.x, c[1] + bz.y);
            float2 o1 = make_float2(c[2] + bz.x, c[3] + bz.y);
            *reinterpret_cast<float2*>(C + (long)m*VOCAB + n)     = o0;
            *reinterpret_cast<float2*>(C + (long)(m+8)*VOCAB + n) = o1;
        }
    }
}

// ---------------------------------------------------------------------------
// Causal attention v2: block = (head, batch, q-chunk of 16). 128 threads.
// ---------------------------------------------------------------------------
#define QC 16
__global__ __launch_bounds__(128) void attention_kernel(
    const float* __restrict__ qkv, float* __restrict__ att_out)
{
    __shared__ float Ks[TT][36];
    __shared__ float Vs[TT][32];
    __shared__ float Ps[QC][129];
    const int h  = blockIdx.x;
    const int b  = blockIdx.y;
    const int qc = blockIdx.z;
    const int tid = threadIdx.x;
    const float scale = 0.17677669529663687f;

    {
        const float* kp = qkv + (long)(b*TT + tid)*(3*DD) + DD + h*HD_ATT;
        const float* vp = kp + DD;
        #pragma unroll
        for (int d = 0; d < 32; d += 4) {
            *reinterpret_cast<float4*>(&Ks[tid][d]) = *reinterpret_cast<const float4*>(kp + d);
            *reinterpret_cast<float4*>(&Vs[tid][d]) = *reinterpret_cast<const float4*>(vp + d);
        }
    }
    __syncthreads();

    const int q = tid >> 3;
    const int j = tid & 7;
    const int qglob = qc*QC + q;

    float qv[32];
    {
        const float* qp = qkv + (long)(b*TT + qglob)*(3*DD) + h*HD_ATT;
        #pragma unroll
        for (int d = 0; d < 32; d += 4) {
            float4 t = *reinterpret_cast<const float4*>(qp + d);
            qv[d]=t.x; qv[d+1]=t.y; qv[d+2]=t.z; qv[d+3]=t.w;
        }
    }

    float s[16];
    float mmax = -1e30f;
    #pragma unroll
    for (int kk = 0; kk < 16; kk++) {
        int k = kk*8 + j;
        float acc = 0.f;
        #pragma unroll
        for (int d = 0; d < 32; d += 4) {
            float4 kv = *reinterpret_cast<const float4*>(&Ks[k][d]);
            acc += qv[d]*kv.x + qv[d+1]*kv.y + qv[d+2]*kv.z + qv[d+3]*kv.w;
        }
        s[kk] = (k <= qglob) ? acc*scale : -1e30f;
        mmax = fmaxf(mmax, s[kk]);
    }
    #pragma unroll
    for (int o = 1; o < 8; o <<= 1)
        mmax = fmaxf(mmax, __shfl_xor_sync(0xffffffffu, mmax, o));

    float l = 0.f;
    #pragma unroll
    for (int kk = 0; kk < 16; kk++) {
        float p = __expf(s[kk] - mmax);
        l += p;
        Ps[q][kk*8 + j] = p;
    }
    #pragma unroll
    for (int o = 1; o < 8; o <<= 1)
        l += __shfl_xor_sync(0xffffffffu, l, o);
    float linv = 1.f / l;
    __syncthreads();

    float ox=0.f, oy=0.f, oz=0.f, ow=0.f;
    #pragma unroll 4
    for (int k = 0; k < TT; k++) {
        float p = Ps[q][k];
        float4 v = *reinterpret_cast<const float4*>(&Vs[k][j*4]);
        ox += p*v.x; oy += p*v.y; oz += p*v.z; ow += p*v.w;
    }
    float4 o4 = make_float4(ox*linv, oy*linv, oz*linv, ow*linv);
    *reinterpret_cast<float4*>(att_out + (long)(b*TT + qglob)*DD + h*HD_ATT + j*4) = o4;
}

// ---------------------------------------------------------------------------
// Memory scan (collapsed — M0=0 makes all slot scores tied forever,
// top-k selects all, softmax = 1/512 uniform; memory collapses to one
// 128-float vector per batch).
// ---------------------------------------------------------------------------
__global__ __launch_bounds__(320) void scan_kernel(
    const float* __restrict__ Hif,
    const float* __restrict__ W_iface,
    float* __restrict__ rv_out)
{
    int b   = blockIdx.x;
    int tid = threadIdx.x;
    __shared__ float rv_s[MD];
    __shared__ float m_s[MD];
    __shared__ float if_s[260];

    float w[128];
    int gcol = 0;
    if (tid < 260) {
        gcol = (tid/65)*129 + 64 + (tid%65);
        #pragma unroll
        for (int k = 0; k < 128; k++)
            w[k] = W_iface[(long)(256 + k)*IFACE + gcol];
    }
    if (tid < MD) { rv_s[tid] = 0.f; m_s[tid] = 0.f; }
    __syncthreads();

    for (int t = 0; t < TT; t++) {
        if (tid < MD)
            rv_out[(long)(b*TT + t)*MD + tid] = rv_s[tid];
        if (tid < 260) {
            float acc = Hif[(long)(b*TT + t)*IFACE + gcol];
            #pragma unroll
            for (int k = 0; k < 128; k++)
                acc += rv_s[k]*w[k];
            if_s[tid] = acc;
        }
        __syncthreads();
        if (tid < MD) {
            int hh = tid >> 5;
            int d  = tid & 31;
            int base = hh*65;
            float wv = if_s[base + d];
            float er = 1.f / (1.f + __expf(-if_s[base + 32 + d]));
            float ag = 1.f / (1.f + __expf(-if_s[base + 64]));
            float mo = m_s[tid];
            rv_s[tid] = rv_s[tid] + mo;
            m_s[tid]  = mo * (1.f - er*(1.f/512.f)) + (ag*(1.f/512.f))*wv;
        }
        __syncthreads();
    }
}

// ---------------------------------------------------------------------------
// Build C = [hf | rv]  (512 x 384)
// ---------------------------------------------------------------------------
__global__ void concat_kernel(const float* __restrict__ hf,
                              const float* __restrict__ rv,
                              float* __restrict__ c)
{
    int bt = blockIdx.x;
    int j  = threadIdx.x;
    c[bt*CDIM + j] = (j < DD) ? hf[bt*DD + j] : rv[bt*MD + (j - DD)];
}

// ---------------------------------------------------------------------------
// Launch
// ---------------------------------------------------------------------------
extern "C" void kernel_launch(void* const* d_in, const int* in_sizes, int n_in,
                              void* d_out, int out_size)
{
    const int*   seq   = (const int*)  d_in[0];
    const float* tok   = (const float*)d_in[1];
    const float* pos   = (const float*)d_in[2];
    const float* Wqkv  = (const float*)d_in[3];
    const float* Wo    = (const float*)d_in[4];
    const float* ln1g  = (const float*)d_in[5];
    const float* ln1b  = (const float*)d_in[6];
    const float* ln2g  = (const float*)d_in[7];
    const float* ln2b  = (const float*)d_in[8];
    const float* W1    = (const float*)d_in[9];
    const float* b1    = (const float*)d_in[10];
    const float* W2    = (const float*)d_in[11];
    const float* b2    = (const float*)d_in[12];
    const float* lnfg  = (const float*)d_in[13];
    const float* lnfb  = (const float*)d_in[14];
    const float* Wlog  = (const float*)d_in[15];
    const float* blog  = (const float*)d_in[16];
    const float* Wif   = (const float*)d_in[17];
    const float* bif   = (const float*)d_in[18];
    float* out = (float*)d_out;

    float *gx, *gh, *gqkv, *gatt, *gff, *ghf, *gHif, *grv, *gc;
    cudaGetSymbolAddress((void**)&gx,   g_x);
    cudaGetSymbolAddress((void**)&gh,   g_h);
    cudaGetSymbolAddress((void**)&gqkv, g_qkv);
    cudaGetSymbolAddress((void**)&gatt, g_att);
    cudaGetSymbolAddress((void**)&gff,  g_ff);
    cudaGetSymbolAddress((void**)&ghf,  g_hf);
    cudaGetSymbolAddress((void**)&gHif, g_Hif);
    cudaGetSymbolAddress((void**)&grv,  g_rv);
    cudaGetSymbolAddress((void**)&gc,   g_c);

    embed_kernel<<<BT, DD>>>(seq, tok, pos, gx);

    for (int l = 0; l < 2; l++) {
        ln_kernel<<<BT, DD>>>(gx, ln1g + l*DD, ln1b + l*DD, gh);
        sgemm_kernel<64,4,4,false><<<dim3(12, 8), 256>>>(
            BT, 3*DD, DD, gh, DD, Wqkv + (long)l*DD*3*DD, 3*DD,
            gqkv, 3*DD, nullptr, nullptr);
        attention_kernel<<<dim3(NH, BB, TT/QC), 128>>>(gqkv, gatt);
        sgemm_kernel<64,4,4,false><<<dim3(4, 8), 256>>>(
            BT, DD, DD, gatt, DD, Wo + (long)l*DD*DD, DD,
            gx, DD, nullptr, gx);
        ln_kernel<<<BT, DD>>>(gx, ln2g + l*DD, ln2b + l*DD, gh);
        sgemm_kernel<64,4,4,true><<<dim3(16, 8), 256>>>(
            BT, FF_, DD, gh, DD, W1 + (long)l*DD*FF_, FF_,
            gff, FF_, b1 + l*FF_, nullptr);
        sgemm_kernel<64,4,4,false><<<dim3(4, 8), 256>>>(
            BT, DD, FF_, gff, FF_, W2 + (long)l*FF_*DD, DD,
            gx, DD, b2 + l*DD, gx);
    }

    ln_kernel<<<BT, DD>>>(gx, lnfg, lnfb, ghf);

    sgemm_kernel<64,4,4,false><<<dim3((IFACE + 63)/64, 8), 256>>>(
        BT, IFACE, DD, ghf, DD, Wif, IFACE, gHif, IFACE, bif, nullptr);

    scan_kernel<<<BB, 320>>>(gHif, Wif, grv);

    concat_kernel<<<BT, CDIM>>>(ghf, grv, gc);

    // logits = C @ W_logits + b_logits  — TF32 tensor cores
    gemm_tf32_kernel<<<dim3(VOCAB/128, BT/128), 256>>>(gc, Wlog, out, blog);
}

// round 6
// speedup vs baseline: 1.6790x; 1.1485x over previous
#include <cuda_runtime.h>
#include <cuda_bf16.h>
#include <math.h>

// ---------------------------------------------------------------------------
// Problem constants
// ---------------------------------------------------------------------------
#define BB 4
#define TT 128
#define DD 256
#define FF_ 1024
#define NH 8
#define HD_ATT 32
#define VOCAB 32000
#define MD 128
#define IFACE 516       // MH*(4*HD+1)
#define CDIM 384        // D + MD
#define BT (BB*TT)      // 512

// ---------------------------------------------------------------------------
// Scratch (device globals; no allocation allowed)
// ---------------------------------------------------------------------------
__device__ float g_x  [BT*DD];
__device__ float g_h  [BT*DD];
__device__ float g_qkv[BT*3*DD];
__device__ float g_att[BT*DD];
__device__ float g_ff [BT*FF_];
__device__ float g_hf [BT*DD];
__device__ float g_Hif[BT*IFACE];
__device__ float g_rv [BT*MD];
__device__ float g_c  [BT*CDIM];

// ---------------------------------------------------------------------------
// Embedding
// ---------------------------------------------------------------------------
__global__ void embed_kernel(const int* __restrict__ seq,
                             const float* __restrict__ tok,
                             const float* __restrict__ pos,
                             float* __restrict__ x)
{
    int bt = blockIdx.x;
    int d  = threadIdx.x;
    int t  = bt & (TT-1);
    x[bt*DD + d] = tok[(long)seq[bt]*DD + d] + pos[t*DD + d];
}

// ---------------------------------------------------------------------------
// LayerNorm over D=256
// ---------------------------------------------------------------------------
__global__ void ln_kernel(const float* __restrict__ x,
                          const float* __restrict__ g,
                          const float* __restrict__ b,
                          float* __restrict__ o)
{
    int row = blockIdx.x;
    int tid = threadIdx.x;
    __shared__ float red[8];
    float v = x[row*DD + tid];
    float s = v;
    #pragma unroll
    for (int k = 16; k; k >>= 1) s += __shfl_xor_sync(0xffffffffu, s, k);
    if ((tid & 31) == 0) red[tid >> 5] = s;
    __syncthreads();
    float mean = 0.f;
    #pragma unroll
    for (int i = 0; i < 8; i++) mean += red[i];
    mean *= (1.f/256.f);
    __syncthreads();
    float d = v - mean;
    float s2 = d*d;
    #pragma unroll
    for (int k = 16; k; k >>= 1) s2 += __shfl_xor_sync(0xffffffffu, s2, k);
    if ((tid & 31) == 0) red[tid >> 5] = s2;
    __syncthreads();
    float var = 0.f;
    #pragma unroll
    for (int i = 0; i < 8; i++) var += red[i];
    var *= (1.f/256.f);
    o[row*DD + tid] = d * rsqrtf(var + 1e-5f) * g[tid] + b[tid];
}

// ---------------------------------------------------------------------------
// TF32 helpers
// ---------------------------------------------------------------------------
__device__ __forceinline__ unsigned f2tf32(float x) {
    unsigned r;
    asm("cvt.rna.tf32.f32 %0, %1;" : "=r"(r) : "f"(x));
    return r;
}
__device__ __forceinline__ float4 cvt4(float4 v) {
    float4 w;
    w.x = __uint_as_float(f2tf32(v.x));
    w.y = __uint_as_float(f2tf32(v.y));
    w.z = __uint_as_float(f2tf32(v.z));
    w.w = __uint_as_float(f2tf32(v.w));
    return w;
}
__device__ __forceinline__ void mma_tf32(float* c, const unsigned* a, const unsigned* b) {
    asm volatile(
        "mma.sync.aligned.m16n8k8.row.col.f32.tf32.tf32.f32 "
        "{%0,%1,%2,%3}, {%4,%5,%6,%7}, {%8,%9}, {%0,%1,%2,%3};"
        : "+f"(c[0]), "+f"(c[1]), "+f"(c[2]), "+f"(c[3])
        : "r"(a[0]), "r"(a[1]), "r"(a[2]), "r"(a[3]),
          "r"(b[0]), "r"(b[1]));
}

// ---------------------------------------------------------------------------
// TF32 small GEMM: 64x64 block tile, BK=32, 4 warps (2x2), warp tile 32x32.
// C[M,N] = A[M,K] @ B[K,N] (+bias)(gelu)(+residual). M%64==0, K%32==0,
// N even; N need not be a multiple of 64 (guarded).
// ---------------------------------------------------------------------------
template<bool GELU>
__global__ __launch_bounds__(128) void tc_gemm(
    int N, int K,
    const float* __restrict__ A, int lda,
    const float* __restrict__ B, int ldb,
    float* __restrict__ C, int ldc,
    const float* __restrict__ bias,
    const float* __restrict__ residual)
{
    __shared__ float As[64][36];   // [m][k] pad 36: frag loads conflict-free
    __shared__ float Bs[32][68];   // [k][n] pad 68: frag loads conflict-free

    const int tid  = threadIdx.x;
    const int lane = tid & 31;
    const int wid  = tid >> 5;
    const int wm   = (wid >> 1) * 32;
    const int wn   = (wid & 1) * 32;
    const int m0   = blockIdx.y * 64;
    const int n0   = blockIdx.x * 64;
    const int g    = lane >> 2;
    const int tg   = lane & 3;

    float acc[8][4];
    #pragma unroll
    for (int i = 0; i < 8; i++)
        #pragma unroll
        for (int j = 0; j < 4; j++) acc[i][j] = 0.f;

    for (int k0 = 0; k0 < K; k0 += 32) {
        #pragma unroll
        for (int i = 0; i < 4; i++) {              // A: 64x32
            int idx = i*128 + tid;
            int r  = idx >> 3;
            int c4 = (idx & 7) << 2;
            float4 v = *reinterpret_cast<const float4*>(A + (long)(m0 + r)*lda + k0 + c4);
            *reinterpret_cast<float4*>(&As[r][c4]) = cvt4(v);
        }
        #pragma unroll
        for (int i = 0; i < 4; i++) {              // B: 32x64 (guarded)
            int idx = i*128 + tid;
            int r  = idx >> 4;
            int c4 = (idx & 15) << 2;
            float4 v = make_float4(0.f,0.f,0.f,0.f);
            if (n0 + c4 < N)
                v = *reinterpret_cast<const float4*>(B + (long)(k0 + r)*ldb + n0 + c4);
            *reinterpret_cast<float4*>(&Bs[r][c4]) = cvt4(v);
        }
        __syncthreads();

        #pragma unroll
        for (int ks = 0; ks < 32; ks += 8) {
            unsigned af[2][4], bf[4][2];
            #pragma unroll
            for (int mt = 0; mt < 2; mt++) {
                int mr = wm + mt*16 + g;
                af[mt][0] = __float_as_uint(As[mr  ][ks + tg    ]);
                af[mt][1] = __float_as_uint(As[mr+8][ks + tg    ]);
                af[mt][2] = __float_as_uint(As[mr  ][ks + tg + 4]);
                af[mt][3] = __float_as_uint(As[mr+8][ks + tg + 4]);
            }
            #pragma unroll
            for (int nt = 0; nt < 4; nt++) {
                int nc = wn + nt*8 + g;
                bf[nt][0] = __float_as_uint(Bs[ks + tg    ][nc]);
                bf[nt][1] = __float_as_uint(Bs[ks + tg + 4][nc]);
            }
            #pragma unroll
            for (int mt = 0; mt < 2; mt++)
                #pragma unroll
                for (int nt = 0; nt < 4; nt++)
                    mma_tf32(acc[mt*4 + nt], af[mt], bf[nt]);
        }
        __syncthreads();
    }

    #pragma unroll
    for (int nt = 0; nt < 4; nt++) {
        int n = n0 + wn + nt*8 + 2*tg;
        if (n < N) {
            float2 bz = make_float2(0.f, 0.f);
            if (bias) bz = *reinterpret_cast<const float2*>(bias + n);
            #pragma unroll
            for (int mt = 0; mt < 2; mt++) {
                int m = m0 + wm + mt*16 + g;
                float* c = acc[mt*4 + nt];
                float v[4] = {c[0]+bz.x, c[1]+bz.y, c[2]+bz.x, c[3]+bz.y};
                if (GELU) {
                    #pragma unroll
                    for (int q = 0; q < 4; q++) {
                        float u = v[q];
                        float tt = 0.7978845608028654f * (u + 0.044715f*u*u*u);
                        v[q] = 0.5f*u*(1.f + tanhf(tt));
                    }
                }
                if (residual) {
                    float2 r0 = *reinterpret_cast<const float2*>(residual + (long)m*ldc + n);
                    float2 r1 = *reinterpret_cast<const float2*>(residual + (long)(m+8)*ldc + n);
                    v[0] += r0.x; v[1] += r0.y; v[2] += r1.x; v[3] += r1.y;
                }
                *reinterpret_cast<float2*>(C + (long)m*ldc + n)     = make_float2(v[0], v[1]);
                *reinterpret_cast<float2*>(C + (long)(m+8)*ldc + n) = make_float2(v[2], v[3]);
            }
        }
    }
}

// ---------------------------------------------------------------------------
// TF32 logits GEMM, double-buffered: C[512,32000] = A[512,384] @ B[384,32000]
// Block 128x128, BK=16 ping-pong, 8 warps (2x4), warp tile 64x32, m16n8k8.
// One __syncthreads per k-tile; global loads prefetched into registers.
// ---------------------------------------------------------------------------
__global__ __launch_bounds__(256) void gemm_tf32_big(
    const float* __restrict__ A,
    const float* __restrict__ B,
    float* __restrict__ C,
    const float* __restrict__ bias)
{
    __shared__ float As[2][128][20];   // [m][k] pad 20 (frag banks g*4+tg: CF)
    __shared__ float Bs[2][16][136];   // [k][n] pad 136 (frag banks tg*8+g: CF)

    const int tid  = threadIdx.x;
    const int lane = tid & 31;
    const int wid  = tid >> 5;
    const int wm   = (wid >> 2) * 64;
    const int wn   = (wid & 3) * 32;
    const int m0   = blockIdx.y * 128;
    const int n0   = blockIdx.x * 128;
    const int g    = lane >> 2;
    const int tg   = lane & 3;

    // A fill: idx = i*256+tid, r=idx>>2 (0..127), c4=(idx&3)<<2   (i<2)
    // B fill: idx = i*256+tid, r=idx>>5 (0..15),  c4=(idx&31)<<2  (i<2)
    const int a_r0 = tid >> 2,  a_c = (tid & 3) << 2;
    const int b_r0 = tid >> 5,  b_c = (tid & 31) << 2;

    float acc[16][4];
    #pragma unroll
    for (int i = 0; i < 16; i++)
        #pragma unroll
        for (int j = 0; j < 4; j++) acc[i][j] = 0.f;

    // preload tile 0
    {
        #pragma unroll
        for (int i = 0; i < 2; i++) {
            float4 va = *reinterpret_cast<const float4*>(A + (long)(m0 + a_r0 + i*64)*CDIM + a_c);
            *reinterpret_cast<float4*>(&As[0][a_r0 + i*64][a_c]) = cvt4(va);
            float4 vb = *reinterpret_cast<const float4*>(B + (long)(b_r0 + i*8)*VOCAB + n0 + b_c);
            *reinterpret_cast<float4*>(&Bs[0][b_r0 + i*8][b_c]) = cvt4(vb);
        }
    }
    __syncthreads();

    int buf = 0;
    for (int k0 = 0; k0 < CDIM; k0 += 16) {
        const bool more = (k0 + 16) < CDIM;
        float4 pa[2], pb[2];
        if (more) {
            #pragma unroll
            for (int i = 0; i < 2; i++) {
                pa[i] = *reinterpret_cast<const float4*>(A + (long)(m0 + a_r0 + i*64)*CDIM + k0 + 16 + a_c);
                pb[i] = *reinterpret_cast<const float4*>(B + (long)(k0 + 16 + b_r0 + i*8)*VOCAB + n0 + b_c);
            }
        }
        #pragma unroll
        for (int ks = 0; ks < 16; ks += 8) {
            unsigned af[4][4], bf[4][2];
            #pragma unroll
            for (int mt = 0; mt < 4; mt++) {
                int mr = wm + mt*16 + g;
                af[mt][0] = __float_as_uint(As[buf][mr  ][ks + tg    ]);
                af[mt][1] = __float_as_uint(As[buf][mr+8][ks + tg    ]);
                af[mt][2] = __float_as_uint(As[buf][mr  ][ks + tg + 4]);
                af[mt][3] = __float_as_uint(As[buf][mr+8][ks + tg + 4]);
            }
            #pragma unroll
            for (int nt = 0; nt < 4; nt++) {
                int nc = wn + nt*8 + g;
                bf[nt][0] = __float_as_uint(Bs[buf][ks + tg    ][nc]);
                bf[nt][1] = __float_as_uint(Bs[buf][ks + tg + 4][nc]);
            }
            #pragma unroll
            for (int mt = 0; mt < 4; mt++)
                #pragma unroll
                for (int nt = 0; nt < 4; nt++)
                    mma_tf32(acc[mt*4 + nt], af[mt], bf[nt]);
        }
        if (more) {
            #pragma unroll
            for (int i = 0; i < 2; i++) {
                *reinterpret_cast<float4*>(&As[buf^1][a_r0 + i*64][a_c]) = cvt4(pa[i]);
                *reinterpret_cast<float4*>(&Bs[buf^1][b_r0 + i*8][b_c]) = cvt4(pb[i]);
            }
        }
        __syncthreads();
        buf ^= 1;
    }

    #pragma unroll
    for (int nt = 0; nt < 4; nt++) {
        int n = n0 + wn + nt*8 + 2*tg;
        float2 bz = *reinterpret_cast<const float2*>(bias + n);
        #pragma unroll
        for (int mt = 0; mt < 4; mt++) {
            int m = m0 + wm + mt*16 + g;
            float* c = acc[mt*4 + nt];
            *reinterpret_cast<float2*>(C + (long)m*VOCAB + n)     = make_float2(c[0]+bz.x, c[1]+bz.y);
            *reinterpret_cast<float2*>(C + (long)(m+8)*VOCAB + n) = make_float2(c[2]+bz.x, c[3]+bz.y);
        }
    }
}

// ---------------------------------------------------------------------------
// Causal attention: block = (head, batch, q-chunk of 16). 128 threads.
// ---------------------------------------------------------------------------
#define QC 16
__global__ __launch_bounds__(128) void attention_kernel(
    const float* __restrict__ qkv, float* __restrict__ att_out)
{
    __shared__ float Ks[TT][36];
    __shared__ float Vs[TT][32];
    __shared__ float Ps[QC][129];
    const int h  = blockIdx.x;
    const int b  = blockIdx.y;
    const int qc = blockIdx.z;
    const int tid = threadIdx.x;
    const float scale = 0.17677669529663687f;

    {
        const float* kp = qkv + (long)(b*TT + tid)*(3*DD) + DD + h*HD_ATT;
        const float* vp = kp + DD;
        #pragma unroll
        for (int d = 0; d < 32; d += 4) {
            *reinterpret_cast<float4*>(&Ks[tid][d]) = *reinterpret_cast<const float4*>(kp + d);
            *reinterpret_cast<float4*>(&Vs[tid][d]) = *reinterpret_cast<const float4*>(vp + d);
        }
    }
    __syncthreads();

    const int q = tid >> 3;
    const int j = tid & 7;
    const int qglob = qc*QC + q;

    float qv[32];
    {
        const float* qp = qkv + (long)(b*TT + qglob)*(3*DD) + h*HD_ATT;
        #pragma unroll
        for (int d = 0; d < 32; d += 4) {
            float4 t = *reinterpret_cast<const float4*>(qp + d);
            qv[d]=t.x; qv[d+1]=t.y; qv[d+2]=t.z; qv[d+3]=t.w;
        }
    }

    float s[16];
    float mmax = -1e30f;
    #pragma unroll
    for (int kk = 0; kk < 16; kk++) {
        int k = kk*8 + j;
        float acc = 0.f;
        #pragma unroll
        for (int d = 0; d < 32; d += 4) {
            float4 kv = *reinterpret_cast<const float4*>(&Ks[k][d]);
            acc += qv[d]*kv.x + qv[d+1]*kv.y + qv[d+2]*kv.z + qv[d+3]*kv.w;
        }
        s[kk] = (k <= qglob) ? acc*scale : -1e30f;
        mmax = fmaxf(mmax, s[kk]);
    }
    #pragma unroll
    for (int o = 1; o < 8; o <<= 1)
        mmax = fmaxf(mmax, __shfl_xor_sync(0xffffffffu, mmax, o));

    float l = 0.f;
    #pragma unroll
    for (int kk = 0; kk < 16; kk++) {
        float p = __expf(s[kk] - mmax);
        l += p;
        Ps[q][kk*8 + j] = p;
    }
    #pragma unroll
    for (int o = 1; o < 8; o <<= 1)
        l += __shfl_xor_sync(0xffffffffu, l, o);
    float linv = 1.f / l;
    __syncthreads();

    float ox=0.f, oy=0.f, oz=0.f, ow=0.f;
    #pragma unroll 4
    for (int k = 0; k < TT; k++) {
        float p = Ps[q][k];
        float4 v = *reinterpret_cast<const float4*>(&Vs[k][j*4]);
        ox += p*v.x; oy += p*v.y; oz += p*v.z; ow += p*v.w;
    }
    float4 o4 = make_float4(ox*linv, oy*linv, oz*linv, ow*linv);
    *reinterpret_cast<float4*>(att_out + (long)(b*TT + qglob)*DD + h*HD_ATT + j*4) = o4;
}

// ---------------------------------------------------------------------------
// Memory scan (collapsed; see derivation R2). GEMV via packed fma.rn.f32x2.
// ---------------------------------------------------------------------------
__global__ __launch_bounds__(320) void scan_kernel(
    const float* __restrict__ Hif,
    const float* __restrict__ W_iface,
    float* __restrict__ rv_out)
{
    int b   = blockIdx.x;
    int tid = threadIdx.x;
    __shared__ __align__(16) float rv_s[MD];
    __shared__ float m_s[MD];
    __shared__ float if_s[260];

    unsigned long long w2[64];
    int gcol = 0;
    if (tid < 260) {
        gcol = (tid/65)*129 + 64 + (tid%65);   // wv/erase/add_gate columns
        #pragma unroll
        for (int k = 0; k < 64; k++) {
            float lo = W_iface[(long)(256 + 2*k    )*IFACE + gcol];
            float hi = W_iface[(long)(256 + 2*k + 1)*IFACE + gcol];
            asm("mov.b64 %0, {%1,%2};" : "=l"(w2[k]) : "f"(lo), "f"(hi));
        }
    }
    if (tid < MD) { rv_s[tid] = 0.f; m_s[tid] = 0.f; }
    __syncthreads();

    const unsigned long long* rv2 = reinterpret_cast<const unsigned long long*>(rv_s);

    for (int t = 0; t < TT; t++) {
        if (tid < MD)
            rv_out[(long)(b*TT + t)*MD + tid] = rv_s[tid];
        if (tid < 260) {
            float hbase = Hif[(long)(b*TT + t)*IFACE + gcol];
            unsigned long long acc2 = 0ull;   // packed (0.0f, 0.0f)
            #pragma unroll
            for (int k = 0; k < 64; k++) {
                unsigned long long r = rv2[k];
                asm("fma.rn.f32x2 %0, %1, %2, %0;" : "+l"(acc2) : "l"(r), "l"(w2[k]));
            }
            float lo, hi;
            asm("mov.b64 {%0,%1}, %2;" : "=f"(lo), "=f"(hi) : "l"(acc2));
            if_s[tid] = hbase + lo + hi;
        }
        __syncthreads();
        if (tid < MD) {
            int hh = tid >> 5;
            int d  = tid & 31;
            int base = hh*65;
            float wv = if_s[base + d];
            float er = 1.f / (1.f + __expf(-if_s[base + 32 + d]));
            float ag = 1.f / (1.f + __expf(-if_s[base + 64]));
            float mo = m_s[tid];
            rv_s[tid] = rv_s[tid] + mo;
            m_s[tid]  = mo * (1.f - er*(1.f/512.f)) + (ag*(1.f/512.f))*wv;
        }
        __syncthreads();
    }
}

// ---------------------------------------------------------------------------
// Build C = [hf | rv]  (512 x 384)
// ---------------------------------------------------------------------------
__global__ void concat_kernel(const float* __restrict__ hf,
                              const float* __restrict__ rv,
                              float* __restrict__ c)
{
    int bt = blockIdx.x;
    int j  = threadIdx.x;
    c[bt*CDIM + j] = (j < DD) ? hf[bt*DD + j] : rv[bt*MD + (j - DD)];
}

// ---------------------------------------------------------------------------
// Launch
// ---------------------------------------------------------------------------
extern "C" void kernel_launch(void* const* d_in, const int* in_sizes, int n_in,
                              void* d_out, int out_size)
{
    const int*   seq   = (const int*)  d_in[0];
    const float* tok   = (const float*)d_in[1];
    const float* pos   = (const float*)d_in[2];
    const float* Wqkv  = (const float*)d_in[3];
    const float* Wo    = (const float*)d_in[4];
    const float* ln1g  = (const float*)d_in[5];
    const float* ln1b  = (const float*)d_in[6];
    const float* ln2g  = (const float*)d_in[7];
    const float* ln2b  = (const float*)d_in[8];
    const float* W1    = (const float*)d_in[9];
    const float* b1    = (const float*)d_in[10];
    const float* W2    = (const float*)d_in[11];
    const float* b2    = (const float*)d_in[12];
    const float* lnfg  = (const float*)d_in[13];
    const float* lnfb  = (const float*)d_in[14];
    const float* Wlog  = (const float*)d_in[15];
    const float* blog  = (const float*)d_in[16];
    const float* Wif   = (const float*)d_in[17];
    const float* bif   = (const float*)d_in[18];
    float* out = (float*)d_out;

    float *gx, *gh, *gqkv, *gatt, *gff, *ghf, *gHif, *grv, *gc;
    cudaGetSymbolAddress((void**)&gx,   g_x);
    cudaGetSymbolAddress((void**)&gh,   g_h);
    cudaGetSymbolAddress((void**)&gqkv, g_qkv);
    cudaGetSymbolAddress((void**)&gatt, g_att);
    cudaGetSymbolAddress((void**)&gff,  g_ff);
    cudaGetSymbolAddress((void**)&ghf,  g_hf);
    cudaGetSymbolAddress((void**)&gHif, g_Hif);
    cudaGetSymbolAddress((void**)&grv,  g_rv);
    cudaGetSymbolAddress((void**)&gc,   g_c);

    embed_kernel<<<BT, DD>>>(seq, tok, pos, gx);

    for (int l = 0; l < 2; l++) {
        ln_kernel<<<BT, DD>>>(gx, ln1g + l*DD, ln1b + l*DD, gh);
        tc_gemm<false><<<dim3(12, 8), 128>>>(
            3*DD, DD, gh, DD, Wqkv + (long)l*DD*3*DD, 3*DD,
            gqkv, 3*DD, nullptr, nullptr);
        attention_kernel<<<dim3(NH, BB, TT/QC), 128>>>(gqkv, gatt);
        tc_gemm<false><<<dim3(4, 8), 128>>>(
            DD, DD, gatt, DD, Wo + (long)l*DD*DD, DD,
            gx, DD, nullptr, gx);
        ln_kernel<<<BT, DD>>>(gx, ln2g + l*DD, ln2b + l*DD, gh);
        tc_gemm<true><<<dim3(16, 8), 128>>>(
            FF_, DD, gh, DD, W1 + (long)l*DD*FF_, FF_,
            gff, FF_, b1 + l*FF_, nullptr);
        tc_gemm<false><<<dim3(4, 8), 128>>>(
            DD, FF_, gff, FF_, W2 + (long)l*FF_*DD, DD,
            gx, DD, b2 + l*DD, gx);
    }

    ln_kernel<<<BT, DD>>>(gx, lnfg, lnfb, ghf);

    tc_gemm<false><<<dim3((IFACE + 63)/64, 8), 128>>>(
        IFACE, DD, ghf, DD, Wif, IFACE, gHif, IFACE, bif, nullptr);

    scan_kernel<<<BB, 320>>>(gHif, Wif, grv);

    concat_kernel<<<BT, CDIM>>>(ghf, grv, gc);

    gemm_tf32_big<<<dim3(VOCAB/128, BT/128), 256>>>(gc, Wlog, out, blog);
}

// round 8
// speedup vs baseline: 1.8625x; 1.1093x over previous
#include <cuda_runtime.h>
#include <cuda_bf16.h>
#include <cuda_fp16.h>
#include <math.h>
#include <cstdint>

// ---------------------------------------------------------------------------
// Problem constants
// ---------------------------------------------------------------------------
#define BB 4
#define TT 128
#define DD 256
#define FF_ 1024
#define NH 8
#define HD_ATT 32
#define VOCAB 32000
#define MD 128
#define IFACE 516       // MH*(4*HD+1)
#define CDIM 384        // D + MD
#define BT (BB*TT)      // 512

// ---------------------------------------------------------------------------
// Scratch (device globals; no allocation allowed)
// ---------------------------------------------------------------------------
__device__ float g_x  [BT*DD];
__device__ float g_h  [BT*DD];
__device__ float g_qkv[BT*3*DD];
__device__ float g_att[BT*DD];
__device__ float g_ff [BT*FF_];
__device__ float g_hf [BT*DD];
__device__ float g_Hif[BT*IFACE];
__device__ float g_rv [BT*MD];
__device__ __align__(16) __half g_ch[BT*CDIM];   // concat [hf|rv] in fp16

// ---------------------------------------------------------------------------
// Embedding
// ---------------------------------------------------------------------------
__global__ void embed_kernel(const int* __restrict__ seq,
                             const float* __restrict__ tok,
                             const float* __restrict__ pos,
                             float* __restrict__ x)
{
    int bt = blockIdx.x;
    int d  = threadIdx.x;
    int t  = bt & (TT-1);
    x[bt*DD + d] = tok[(long)seq[bt]*DD + d] + pos[t*DD + d];
}

// ---------------------------------------------------------------------------
// LayerNorm over D=256
// ---------------------------------------------------------------------------
__global__ void ln_kernel(const float* __restrict__ x,
                          const float* __restrict__ g,
                          const float* __restrict__ b,
                          float* __restrict__ o)
{
    int row = blockIdx.x;
    int tid = threadIdx.x;
    __shared__ float red[8];
    float v = x[row*DD + tid];
    float s = v;
    #pragma unroll
    for (int k = 16; k; k >>= 1) s += __shfl_xor_sync(0xffffffffu, s, k);
    if ((tid & 31) == 0) red[tid >> 5] = s;
    __syncthreads();
    float mean = 0.f;
    #pragma unroll
    for (int i = 0; i < 8; i++) mean += red[i];
    mean *= (1.f/256.f);
    __syncthreads();
    float d = v - mean;
    float s2 = d*d;
    #pragma unroll
    for (int k = 16; k; k >>= 1) s2 += __shfl_xor_sync(0xffffffffu, s2, k);
    if ((tid & 31) == 0) red[tid >> 5] = s2;
    __syncthreads();
    float var = 0.f;
    #pragma unroll
    for (int i = 0; i < 8; i++) var += red[i];
    var *= (1.f/256.f);
    o[row*DD + tid] = d * rsqrtf(var + 1e-5f) * g[tid] + b[tid];
}

// ---------------------------------------------------------------------------
// TF32 helpers (small GEMMs)
// ---------------------------------------------------------------------------
__device__ __forceinline__ unsigned f2tf32(float x) {
    unsigned r;
    asm("cvt.rna.tf32.f32 %0, %1;" : "=r"(r) : "f"(x));
    return r;
}
__device__ __forceinline__ float4 cvt4(float4 v) {
    float4 w;
    w.x = __uint_as_float(f2tf32(v.x));
    w.y = __uint_as_float(f2tf32(v.y));
    w.z = __uint_as_float(f2tf32(v.z));
    w.w = __uint_as_float(f2tf32(v.w));
    return w;
}
__device__ __forceinline__ void mma_tf32(float* c, const unsigned* a, const unsigned* b) {
    asm volatile(
        "mma.sync.aligned.m16n8k8.row.col.f32.tf32.tf32.f32 "
        "{%0,%1,%2,%3}, {%4,%5,%6,%7}, {%8,%9}, {%0,%1,%2,%3};"
        : "+f"(c[0]), "+f"(c[1]), "+f"(c[2]), "+f"(c[3])
        : "r"(a[0]), "r"(a[1]), "r"(a[2]), "r"(a[3]),
          "r"(b[0]), "r"(b[1]));
}

// ---------------------------------------------------------------------------
// FP16 mma helpers (logits GEMM)
// ---------------------------------------------------------------------------
__device__ __forceinline__ uint32_t smem_u32(const void* p) {
    uint32_t a;
    asm("{ .reg .u64 t; cvta.to.shared.u64 t, %1; cvt.u32.u64 %0, t; }" : "=r"(a) : "l"(p));
    return a;
}
__device__ __forceinline__ void ldsm_x4(unsigned* r, uint32_t addr) {
    asm volatile("ldmatrix.sync.aligned.m8n8.x4.shared.b16 {%0,%1,%2,%3}, [%4];"
        : "=r"(r[0]), "=r"(r[1]), "=r"(r[2]), "=r"(r[3]) : "r"(addr));
}
__device__ __forceinline__ void ldsm_x4_t(unsigned* r, uint32_t addr) {
    asm volatile("ldmatrix.sync.aligned.m8n8.x4.trans.shared.b16 {%0,%1,%2,%3}, [%4];"
        : "=r"(r[0]), "=r"(r[1]), "=r"(r[2]), "=r"(r[3]) : "r"(addr));
}
__device__ __forceinline__ void mma_f16(float* c, const unsigned* a, unsigned b0, unsigned b1) {
    asm volatile(
        "mma.sync.aligned.m16n8k16.row.col.f32.f16.f16.f32 "
        "{%0,%1,%2,%3}, {%4,%5,%6,%7}, {%8,%9}, {%0,%1,%2,%3};"
        : "+f"(c[0]), "+f"(c[1]), "+f"(c[2]), "+f"(c[3])
        : "r"(a[0]), "r"(a[1]), "r"(a[2]), "r"(a[3]),
          "r"(b0), "r"(b1));
}

// ---------------------------------------------------------------------------
// FP16 logits GEMM: C[512,32000] = A_h[512,384] @ B[384,32000] + bias
// Block 128x128, BK=32 double-buffered, 8 warps (2x4), warp tile 64x32,
// mma m16n8k16.f32.f16.f16.f32.  Fragments via ldmatrix / ldmatrix.trans.
// Grid (4, 250): m fastest -> the 4 m-blocks sharing a B n-strip are
// co-resident, so W_logits is read from L2 after first touch.
// Smem strides: Ah 40 halves (banks 20r%32, conflict-free LDSM),
//               Bh 136 halves (banks 4r%32, conflict-free LDSM.trans).
// ---------------------------------------------------------------------------
__global__ __launch_bounds__(256, 2) void logits_f16_kernel(
    const __half* __restrict__ A,
    const float* __restrict__ B,
    float* __restrict__ C,
    const float* __restrict__ bias)
{
    __shared__ __half Ah[2][128][40];
    __shared__ __half Bh[2][32][136];

    const int tid  = threadIdx.x;
    const int lane = tid & 31;
    const int wid  = tid >> 5;
    const int wm   = (wid >> 2) * 64;
    const int wn   = (wid & 3) * 32;
    const int m0   = blockIdx.x * 128;   // m fastest
    const int n0   = blockIdx.y * 128;

    const int ar = tid >> 2;             // A fill: rows ar, ar+64
    const int ac = (tid & 3) << 3;       // half-offset 0/8/16/24

    float acc[16][4];
    #pragma unroll
    for (int i = 0; i < 16; i++)
        #pragma unroll
        for (int j = 0; j < 4; j++) acc[i][j] = 0.f;

    // ---- preload tile 0 ----
    #pragma unroll
    for (int i = 0; i < 2; i++) {
        uint4 v = *reinterpret_cast<const uint4*>(A + (long)(m0 + ar + i*64)*CDIM + ac);
        *reinterpret_cast<uint4*>(&Ah[0][ar + i*64][ac]) = v;
    }
    #pragma unroll
    for (int p = 0; p < 4; p++) {
        int q = p*256 + tid;
        int r = q >> 5, c4 = (q & 31) << 2;
        float4 v = *reinterpret_cast<const float4*>(B + (long)r*VOCAB + n0 + c4);
        __half2 h0 = __floats2half2_rn(v.x, v.y);
        __half2 h1 = __floats2half2_rn(v.z, v.w);
        uint2 u;
        u.x = *reinterpret_cast<unsigned*>(&h0);
        u.y = *reinterpret_cast<unsigned*>(&h1);
        *reinterpret_cast<uint2*>(&Bh[0][r][c4]) = u;
    }
    __syncthreads();

    int buf = 0;
    #pragma unroll 1
    for (int kt = 0; kt < CDIM/32; kt++) {
        const bool more = (kt + 1) < CDIM/32;
        uint4 pa[2];
        float4 pb[4];
        if (more) {
            const int k0 = (kt + 1) * 32;
            #pragma unroll
            for (int i = 0; i < 2; i++)
                pa[i] = *reinterpret_cast<const uint4*>(A + (long)(m0 + ar + i*64)*CDIM + k0 + ac);
            #pragma unroll
            for (int p = 0; p < 4; p++) {
                int q = p*256 + tid;
                pb[p] = *reinterpret_cast<const float4*>(
                    B + (long)(k0 + (q >> 5))*VOCAB + n0 + ((q & 31) << 2));
            }
        }

        #pragma unroll
        for (int ks = 0; ks < 32; ks += 16) {
            unsigned af[4][4], bf[2][4];
            #pragma unroll
            for (int mt = 0; mt < 4; mt++) {
                int row = wm + mt*16 + (lane & 15);
                int col = ks + ((lane & 16) >> 1);
                ldsm_x4(af[mt], smem_u32(&Ah[buf][row][col]));
            }
            #pragma unroll
            for (int pr = 0; pr < 2; pr++) {
                int row = ks + (lane & 15);
                int col = wn + pr*16 + ((lane & 16) >> 1);
                ldsm_x4_t(bf[pr], smem_u32(&Bh[buf][row][col]));
            }
            #pragma unroll
            for (int mt = 0; mt < 4; mt++)
                #pragma unroll
                for (int nt = 0; nt < 4; nt++)
                    mma_f16(acc[mt*4 + nt], af[mt],
                            bf[nt >> 1][(nt & 1)*2], bf[nt >> 1][(nt & 1)*2 + 1]);
        }

        if (more) {
            #pragma unroll
            for (int i = 0; i < 2; i++)
                *reinterpret_cast<uint4*>(&Ah[buf^1][ar + i*64][ac]) = pa[i];
            #pragma unroll
            for (int p = 0; p < 4; p++) {
                int q = p*256 + tid;
                int r = q >> 5, c4 = (q & 31) << 2;
                __half2 h0 = __floats2half2_rn(pb[p].x, pb[p].y);
                __half2 h1 = __floats2half2_rn(pb[p].z, pb[p].w);
                uint2 u;
                u.x = *reinterpret_cast<unsigned*>(&h0);
                u.y = *reinterpret_cast<unsigned*>(&h1);
                *reinterpret_cast<uint2*>(&Bh[buf^1][r][c4]) = u;
            }
        }
        __syncthreads();
        buf ^= 1;
    }

    // ---- epilogue: C = acc + bias ----
    const int g  = lane >> 2;
    const int tg = lane & 3;
    #pragma unroll
    for (int nt = 0; nt < 4; nt++) {
        int n = n0 + wn + nt*8 + 2*tg;
        float2 bz = *reinterpret_cast<const float2*>(bias + n);
        #pragma unroll
        for (int mt = 0; mt < 4; mt++) {
            int m = m0 + wm + mt*16 + g;
            float* c = acc[mt*4 + nt];
            *reinterpret_cast<float2*>(C + (long)m*VOCAB + n)     = make_float2(c[0]+bz.x, c[1]+bz.y);
            *reinterpret_cast<float2*>(C + (long)(m+8)*VOCAB + n) = make_float2(c[2]+bz.x, c[3]+bz.y);
        }
    }
}

// ---------------------------------------------------------------------------
// TF32 small GEMM (mma.sync): 64x64 tile, BK=32, 4 warps.
// ---------------------------------------------------------------------------
template<bool GELU>
__global__ __launch_bounds__(128) void tc_gemm(
    int N, int K,
    const float* __restrict__ A, int lda,
    const float* __restrict__ B, int ldb,
    float* __restrict__ C, int ldc,
    const float* __restrict__ bias,
    const float* __restrict__ residual)
{
    __shared__ float As[64][36];
    __shared__ float Bs[32][68];

    const int tid  = threadIdx.x;
    const int lane = tid & 31;
    const int wid  = tid >> 5;
    const int wm   = (wid >> 1) * 32;
    const int wn   = (wid & 1) * 32;
    const int m0   = blockIdx.y * 64;
    const int n0   = blockIdx.x * 64;
    const int g    = lane >> 2;
    const int tg   = lane & 3;

    float acc[8][4];
    #pragma unroll
    for (int i = 0; i < 8; i++)
        #pragma unroll
        for (int j = 0; j < 4; j++) acc[i][j] = 0.f;

    for (int k0 = 0; k0 < K; k0 += 32) {
        #pragma unroll
        for (int i = 0; i < 4; i++) {
            int idx = i*128 + tid;
            int r  = idx >> 3;
            int c4 = (idx & 7) << 2;
            float4 v = *reinterpret_cast<const float4*>(A + (long)(m0 + r)*lda + k0 + c4);
            *reinterpret_cast<float4*>(&As[r][c4]) = cvt4(v);
        }
        #pragma unroll
        for (int i = 0; i < 4; i++) {
            int idx = i*128 + tid;
            int r  = idx >> 4;
            int c4 = (idx & 15) << 2;
            float4 v = make_float4(0.f,0.f,0.f,0.f);
            if (n0 + c4 < N)
                v = *reinterpret_cast<const float4*>(B + (long)(k0 + r)*ldb + n0 + c4);
            *reinterpret_cast<float4*>(&Bs[r][c4]) = cvt4(v);
        }
        __syncthreads();

        #pragma unroll
        for (int ks = 0; ks < 32; ks += 8) {
            unsigned af[2][4], bf[4][2];
            #pragma unroll
            for (int mt = 0; mt < 2; mt++) {
                int mr = wm + mt*16 + g;
                af[mt][0] = __float_as_uint(As[mr  ][ks + tg    ]);
                af[mt][1] = __float_as_uint(As[mr+8][ks + tg    ]);
                af[mt][2] = __float_as_uint(As[mr  ][ks + tg + 4]);
                af[mt][3] = __float_as_uint(As[mr+8][ks + tg + 4]);
            }
            #pragma unroll
            for (int nt = 0; nt < 4; nt++) {
                int nc = wn + nt*8 + g;
                bf[nt][0] = __float_as_uint(Bs[ks + tg    ][nc]);
                bf[nt][1] = __float_as_uint(Bs[ks + tg + 4][nc]);
            }
            #pragma unroll
            for (int mt = 0; mt < 2; mt++)
                #pragma unroll
                for (int nt = 0; nt < 4; nt++)
                    mma_tf32(acc[mt*4 + nt], af[mt], bf[nt]);
        }
        __syncthreads();
    }

    #pragma unroll
    for (int nt = 0; nt < 4; nt++) {
        int n = n0 + wn + nt*8 + 2*tg;
        if (n < N) {
            float2 bz = make_float2(0.f, 0.f);
            if (bias) bz = *reinterpret_cast<const float2*>(bias + n);
            #pragma unroll
            for (int mt = 0; mt < 2; mt++) {
                int m = m0 + wm + mt*16 + g;
                float* c = acc[mt*4 + nt];
                float v[4] = {c[0]+bz.x, c[1]+bz.y, c[2]+bz.x, c[3]+bz.y};
                if (GELU) {
                    #pragma unroll
                    for (int q = 0; q < 4; q++) {
                        float u = v[q];
                        float tt = 0.7978845608028654f * (u + 0.044715f*u*u*u);
                        v[q] = 0.5f*u*(1.f + tanhf(tt));
                    }
                }
                if (residual) {
                    float2 r0 = *reinterpret_cast<const float2*>(residual + (long)m*ldc + n);
                    float2 r1 = *reinterpret_cast<const float2*>(residual + (long)(m+8)*ldc + n);
                    v[0] += r0.x; v[1] += r0.y; v[2] += r1.x; v[3] += r1.y;
                }
                *reinterpret_cast<float2*>(C + (long)m*ldc + n)     = make_float2(v[0], v[1]);
                *reinterpret_cast<float2*>(C + (long)(m+8)*ldc + n) = make_float2(v[2], v[3]);
            }
        }
    }
}

// ---------------------------------------------------------------------------
// Causal attention: block = (head, batch, q-chunk of 16). 128 threads.
// ---------------------------------------------------------------------------
#define QC 16
__global__ __launch_bounds__(128) void attention_kernel(
    const float* __restrict__ qkv, float* __restrict__ att_out)
{
    __shared__ float Ks[TT][36];
    __shared__ float Vs[TT][32];
    __shared__ float Ps[QC][129];
    const int h  = blockIdx.x;
    const int b  = blockIdx.y;
    const int qc = blockIdx.z;
    const int tid = threadIdx.x;
    const float scale = 0.17677669529663687f;

    {
        const float* kp = qkv + (long)(b*TT + tid)*(3*DD) + DD + h*HD_ATT;
        const float* vp = kp + DD;
        #pragma unroll
        for (int d = 0; d < 32; d += 4) {
            *reinterpret_cast<float4*>(&Ks[tid][d]) = *reinterpret_cast<const float4*>(kp + d);
            *reinterpret_cast<float4*>(&Vs[tid][d]) = *reinterpret_cast<const float4*>(vp + d);
        }
    }
    __syncthreads();

    const int q = tid >> 3;
    const int j = tid & 7;
    const int qglob = qc*QC + q;

    float qv[32];
    {
        const float* qp = qkv + (long)(b*TT + qglob)*(3*DD) + h*HD_ATT;
        #pragma unroll
        for (int d = 0; d < 32; d += 4) {
            float4 t = *reinterpret_cast<const float4*>(qp + d);
            qv[d]=t.x; qv[d+1]=t.y; qv[d+2]=t.z; qv[d+3]=t.w;
        }
    }

    float s[16];
    float mmax = -1e30f;
    #pragma unroll
    for (int kk = 0; kk < 16; kk++) {
        int k = kk*8 + j;
        float acc = 0.f;
        #pragma unroll
        for (int d = 0; d < 32; d += 4) {
            float4 kv = *reinterpret_cast<const float4*>(&Ks[k][d]);
            acc += qv[d]*kv.x + qv[d+1]*kv.y + qv[d+2]*kv.z + qv[d+3]*kv.w;
        }
        s[kk] = (k <= qglob) ? acc*scale : -1e30f;
        mmax = fmaxf(mmax, s[kk]);
    }
    #pragma unroll
    for (int o = 1; o < 8; o <<= 1)
        mmax = fmaxf(mmax, __shfl_xor_sync(0xffffffffu, mmax, o));

    float l = 0.f;
    #pragma unroll
    for (int kk = 0; kk < 16; kk++) {
        float p = __expf(s[kk] - mmax);
        l += p;
        Ps[q][kk*8 + j] = p;
    }
    #pragma unroll
    for (int o = 1; o < 8; o <<= 1)
        l += __shfl_xor_sync(0xffffffffu, l, o);
    float linv = 1.f / l;
    __syncthreads();

    float ox=0.f, oy=0.f, oz=0.f, ow=0.f;
    #pragma unroll 4
    for (int k = 0; k < TT; k++) {
        float p = Ps[q][k];
        float4 v = *reinterpret_cast<const float4*>(&Vs[k][j*4]);
        ox += p*v.x; oy += p*v.y; oz += p*v.z; ow += p*v.w;
    }
    float4 o4 = make_float4(ox*linv, oy*linv, oz*linv, ow*linv);
    *reinterpret_cast<float4*>(att_out + (long)(b*TT + qglob)*DD + h*HD_ATT + j*4) = o4;
}

// ---------------------------------------------------------------------------
// Memory scan (collapsed; see derivation R2). GEMV via packed fma.rn.f32x2.
// ---------------------------------------------------------------------------
__global__ __launch_bounds__(320) void scan_kernel(
    const float* __restrict__ Hif,
    const float* __restrict__ W_iface,
    float* __restrict__ rv_out)
{
    int b   = blockIdx.x;
    int tid = threadIdx.x;
    __shared__ __align__(16) float rv_s[MD];
    __shared__ float m_s[MD];
    __shared__ float if_s[260];

    unsigned long long w2[64];
    int gcol = 0;
    if (tid < 260) {
        gcol = (tid/65)*129 + 64 + (tid%65);
        #pragma unroll
        for (int k = 0; k < 64; k++) {
            float lo = W_iface[(long)(256 + 2*k    )*IFACE + gcol];
            float hi = W_iface[(long)(256 + 2*k + 1)*IFACE + gcol];
            asm("mov.b64 %0, {%1,%2};" : "=l"(w2[k]) : "f"(lo), "f"(hi));
        }
    }
    if (tid < MD) { rv_s[tid] = 0.f; m_s[tid] = 0.f; }
    __syncthreads();

    const unsigned long long* rv2 = reinterpret_cast<const unsigned long long*>(rv_s);

    for (int t = 0; t < TT; t++) {
        if (tid < MD)
            rv_out[(long)(b*TT + t)*MD + tid] = rv_s[tid];
        if (tid < 260) {
            float hbase = Hif[(long)(b*TT + t)*IFACE + gcol];
            unsigned long long acc2 = 0ull;
            #pragma unroll
            for (int k = 0; k < 64; k++) {
                unsigned long long r = rv2[k];
                asm("fma.rn.f32x2 %0, %1, %2, %0;" : "+l"(acc2) : "l"(r), "l"(w2[k]));
            }
            float lo, hi;
            asm("mov.b64 {%0,%1}, %2;" : "=f"(lo), "=f"(hi) : "l"(acc2));
            if_s[tid] = hbase + lo + hi;
        }
        __syncthreads();
        if (tid < MD) {
            int hh = tid >> 5;
            int d  = tid & 31;
            int base = hh*65;
            float wv = if_s[base + d];
            float er = 1.f / (1.f + __expf(-if_s[base + 32 + d]));
            float ag = 1.f / (1.f + __expf(-if_s[base + 64]));
            float mo = m_s[tid];
            rv_s[tid] = rv_s[tid] + mo;
            m_s[tid]  = mo * (1.f - er*(1.f/512.f)) + (ag*(1.f/512.f))*wv;
        }
        __syncthreads();
    }
}

// ---------------------------------------------------------------------------
// Build C_h = [hf | rv] in fp16  (512 x 384)
// ---------------------------------------------------------------------------
__global__ void concat_kernel(const float* __restrict__ hf,
                              const float* __restrict__ rv,
                              __half* __restrict__ ch)
{
    int bt = blockIdx.x;
    int j  = threadIdx.x;
    float v = (j < DD) ? hf[bt*DD + j] : rv[bt*MD + (j - DD)];
    ch[bt*CDIM + j] = __float2half(v);
}

// ---------------------------------------------------------------------------
// Launch
// ---------------------------------------------------------------------------
extern "C" void kernel_launch(void* const* d_in, const int* in_sizes, int n_in,
                              void* d_out, int out_size)
{
    const int*   seq   = (const int*)  d_in[0];
    const float* tok   = (const float*)d_in[1];
    const float* pos   = (const float*)d_in[2];
    const float* Wqkv  = (const float*)d_in[3];
    const float* Wo    = (const float*)d_in[4];
    const float* ln1g  = (const float*)d_in[5];
    const float* ln1b  = (const float*)d_in[6];
    const float* ln2g  = (const float*)d_in[7];
    const float* ln2b  = (const float*)d_in[8];
    const float* W1    = (const float*)d_in[9];
    const float* b1    = (const float*)d_in[10];
    const float* W2    = (const float*)d_in[11];
    const float* b2    = (const float*)d_in[12];
    const float* lnfg  = (const float*)d_in[13];
    const float* lnfb  = (const float*)d_in[14];
    const float* Wlog  = (const float*)d_in[15];
    const float* blog  = (const float*)d_in[16];
    const float* Wif   = (const float*)d_in[17];
    const float* bif   = (const float*)d_in[18];
    float* out = (float*)d_out;

    float *gx, *gh, *gqkv, *gatt, *gff, *ghf, *gHif, *grv;
    __half* gch;
    cudaGetSymbolAddress((void**)&gx,   g_x);
    cudaGetSymbolAddress((void**)&gh,   g_h);
    cudaGetSymbolAddress((void**)&gqkv, g_qkv);
    cudaGetSymbolAddress((void**)&gatt, g_att);
    cudaGetSymbolAddress((void**)&gff,  g_ff);
    cudaGetSymbolAddress((void**)&ghf,  g_hf);
    cudaGetSymbolAddress((void**)&gHif, g_Hif);
    cudaGetSymbolAddress((void**)&grv,  g_rv);
    cudaGetSymbolAddress((void**)&gch,  g_ch);

    embed_kernel<<<BT, DD>>>(seq, tok, pos, gx);

    for (int l = 0; l < 2; l++) {
        ln_kernel<<<BT, DD>>>(gx, ln1g + l*DD, ln1b + l*DD, gh);
        tc_gemm<false><<<dim3(12, 8), 128>>>(
            3*DD, DD, gh, DD, Wqkv + (long)l*DD*3*DD, 3*DD,
            gqkv, 3*DD, nullptr, nullptr);
        attention_kernel<<<dim3(NH, BB, TT/QC), 128>>>(gqkv, gatt);
        tc_gemm<false><<<dim3(4, 8), 128>>>(
            DD, DD, gatt, DD, Wo + (long)l*DD*DD, DD,
            gx, DD, nullptr, gx);
        ln_kernel<<<BT, DD>>>(gx, ln2g + l*DD, ln2b + l*DD, gh);
        tc_gemm<true><<<dim3(16, 8), 128>>>(
            FF_, DD, gh, DD, W1 + (long)l*DD*FF_, FF_,
            gff, FF_, b1 + l*FF_, nullptr);
        tc_gemm<false><<<dim3(4, 8), 128>>>(
            DD, FF_, gff, FF_, W2 + (long)l*FF_*DD, DD,
            gx, DD, b2 + l*DD, gx);
    }

    ln_kernel<<<BT, DD>>>(gx, lnfg, lnfb, ghf);

    tc_gemm<false><<<dim3((IFACE + 63)/64, 8), 128>>>(
        IFACE, DD, ghf, DD, Wif, IFACE, gHif, IFACE, bif, nullptr);

    scan_kernel<<<BB, 320>>>(gHif, Wif, grv);

    concat_kernel<<<BT, CDIM>>>(ghf, grv, gch);

    // logits = C @ W_logits + b_logits — fp16 mma.sync m16n8k16
    logits_f16_kernel<<<dim3(4, VOCAB/128), 256>>>(gch, Wlog, out, blog);
}

// round 9
// speedup vs baseline: 1.8889x; 1.0142x over previous
#include <cuda_runtime.h>
#include <cuda_bf16.h>
#include <cuda_fp16.h>
#include <math.h>
#include <cstdint>

// ---------------------------------------------------------------------------
// Problem constants
// ---------------------------------------------------------------------------
#define BB 4
#define TT 128
#define DD 256
#define FF_ 1024
#define NH 8
#define HD_ATT 32
#define VOCAB 32000
#define MD 128
#define IFACE 516       // MH*(4*HD+1)
#define CDIM 384        // D + MD
#define BT (BB*TT)      // 512

// ---------------------------------------------------------------------------
// Scratch (device globals; no allocation allowed)
// ---------------------------------------------------------------------------
__device__ float g_x  [BT*DD];
__device__ float g_qkv[BT*3*DD];
__device__ float g_att[BT*DD];
__device__ float g_ff [BT*FF_];
__device__ float g_Hif[BT*IFACE];
__device__ __align__(16) __half g_ch[BT*CDIM];   // concat [lnf(x) | rv] in fp16

// ---------------------------------------------------------------------------
// Embedding
// ---------------------------------------------------------------------------
__global__ void embed_kernel(const int* __restrict__ seq,
                             const float* __restrict__ tok,
                             const float* __restrict__ pos,
                             float* __restrict__ x)
{
    int bt = blockIdx.x;
    int d  = threadIdx.x;
    int t  = bt & (TT-1);
    x[bt*DD + d] = tok[(long)seq[bt]*DD + d] + pos[t*DD + d];
}

// ---------------------------------------------------------------------------
// Final LayerNorm -> fp16 into g_ch left half (stride CDIM)
// ---------------------------------------------------------------------------
__global__ void lnf_half_kernel(const float* __restrict__ x,
                                const float* __restrict__ g,
                                const float* __restrict__ b,
                                __half* __restrict__ ch)
{
    int row = blockIdx.x;
    int tid = threadIdx.x;
    __shared__ float red[8];
    float v = x[row*DD + tid];
    float s = v;
    #pragma unroll
    for (int k = 16; k; k >>= 1) s += __shfl_xor_sync(0xffffffffu, s, k);
    if ((tid & 31) == 0) red[tid >> 5] = s;
    __syncthreads();
    float mean = 0.f;
    #pragma unroll
    for (int i = 0; i < 8; i++) mean += red[i];
    mean *= (1.f/256.f);
    __syncthreads();
    float d = v - mean;
    float s2 = d*d;
    #pragma unroll
    for (int k = 16; k; k >>= 1) s2 += __shfl_xor_sync(0xffffffffu, s2, k);
    if ((tid & 31) == 0) red[tid >> 5] = s2;
    __syncthreads();
    float var = 0.f;
    #pragma unroll
    for (int i = 0; i < 8; i++) var += red[i];
    var *= (1.f/256.f);
    ch[row*CDIM + tid] = __float2half(d * rsqrtf(var + 1e-5f) * g[tid] + b[tid]);
}

// ---------------------------------------------------------------------------
// TF32 helpers
// ---------------------------------------------------------------------------
__device__ __forceinline__ unsigned f2tf32(float x) {
    unsigned r;
    asm("cvt.rna.tf32.f32 %0, %1;" : "=r"(r) : "f"(x));
    return r;
}
__device__ __forceinline__ float4 cvt4(float4 v) {
    float4 w;
    w.x = __uint_as_float(f2tf32(v.x));
    w.y = __uint_as_float(f2tf32(v.y));
    w.z = __uint_as_float(f2tf32(v.z));
    w.w = __uint_as_float(f2tf32(v.w));
    return w;
}
__device__ __forceinline__ void mma_tf32(float* c, const unsigned* a, const unsigned* b) {
    asm volatile(
        "mma.sync.aligned.m16n8k8.row.col.f32.tf32.tf32.f32 "
        "{%0,%1,%2,%3}, {%4,%5,%6,%7}, {%8,%9}, {%0,%1,%2,%3};"
        : "+f"(c[0]), "+f"(c[1]), "+f"(c[2]), "+f"(c[3])
        : "r"(a[0]), "r"(a[1]), "r"(a[2]), "r"(a[3]),
          "r"(b[0]), "r"(b[1]));
}

// ---------------------------------------------------------------------------
// FP16 mma helpers (logits GEMM)
// ---------------------------------------------------------------------------
__device__ __forceinline__ uint32_t smem_u32(const void* p) {
    uint32_t a;
    asm("{ .reg .u64 t; cvta.to.shared.u64 t, %1; cvt.u32.u64 %0, t; }" : "=r"(a) : "l"(p));
    return a;
}
__device__ __forceinline__ void ldsm_x4(unsigned* r, uint32_t addr) {
    asm volatile("ldmatrix.sync.aligned.m8n8.x4.shared.b16 {%0,%1,%2,%3}, [%4];"
        : "=r"(r[0]), "=r"(r[1]), "=r"(r[2]), "=r"(r[3]) : "r"(addr));
}
__device__ __forceinline__ void ldsm_x4_t(unsigned* r, uint32_t addr) {
    asm volatile("ldmatrix.sync.aligned.m8n8.x4.trans.shared.b16 {%0,%1,%2,%3}, [%4];"
        : "=r"(r[0]), "=r"(r[1]), "=r"(r[2]), "=r"(r[3]) : "r"(addr));
}
__device__ __forceinline__ void mma_f16(float* c, const unsigned* a, unsigned b0, unsigned b1) {
    asm volatile(
        "mma.sync.aligned.m16n8k16.row.col.f32.f16.f16.f32 "
        "{%0,%1,%2,%3}, {%4,%5,%6,%7}, {%8,%9}, {%0,%1,%2,%3};"
        : "+f"(c[0]), "+f"(c[1]), "+f"(c[2]), "+f"(c[3])
        : "r"(a[0]), "r"(a[1]), "r"(a[2]), "r"(a[3]),
          "r"(b0), "r"(b1));
}

// ---------------------------------------------------------------------------
// FP16 logits GEMM (unchanged from R7): C[512,32000]=A_h[512,384]@B + bias
// ---------------------------------------------------------------------------
__global__ __launch_bounds__(256, 2) void logits_f16_kernel(
    const __half* __restrict__ A,
    const float* __restrict__ B,
    float* __restrict__ C,
    const float* __restrict__ bias)
{
    __shared__ __half Ah[2][128][40];
    __shared__ __half Bh[2][32][136];

    const int tid  = threadIdx.x;
    const int lane = tid & 31;
    const int wid  = tid >> 5;
    const int wm   = (wid >> 2) * 64;
    const int wn   = (wid & 3) * 32;
    const int m0   = blockIdx.x * 128;   // m fastest
    const int n0   = blockIdx.y * 128;

    const int ar = tid >> 2;
    const int ac = (tid & 3) << 3;

    float acc[16][4];
    #pragma unroll
    for (int i = 0; i < 16; i++)
        #pragma unroll
        for (int j = 0; j < 4; j++) acc[i][j] = 0.f;

    #pragma unroll
    for (int i = 0; i < 2; i++) {
        uint4 v = *reinterpret_cast<const uint4*>(A + (long)(m0 + ar + i*64)*CDIM + ac);
        *reinterpret_cast<uint4*>(&Ah[0][ar + i*64][ac]) = v;
    }
    #pragma unroll
    for (int p = 0; p < 4; p++) {
        int q = p*256 + tid;
        int r = q >> 5, c4 = (q & 31) << 2;
        float4 v = *reinterpret_cast<const float4*>(B + (long)r*VOCAB + n0 + c4);
        __half2 h0 = __floats2half2_rn(v.x, v.y);
        __half2 h1 = __floats2half2_rn(v.z, v.w);
        uint2 u;
        u.x = *reinterpret_cast<unsigned*>(&h0);
        u.y = *reinterpret_cast<unsigned*>(&h1);
        *reinterpret_cast<uint2*>(&Bh[0][r][c4]) = u;
    }
    __syncthreads();

    int buf = 0;
    #pragma unroll 1
    for (int kt = 0; kt < CDIM/32; kt++) {
        const bool more = (kt + 1) < CDIM/32;
        uint4 pa[2];
        float4 pb[4];
        if (more) {
            const int k0 = (kt + 1) * 32;
            #pragma unroll
            for (int i = 0; i < 2; i++)
                pa[i] = *reinterpret_cast<const uint4*>(A + (long)(m0 + ar + i*64)*CDIM + k0 + ac);
            #pragma unroll
            for (int p = 0; p < 4; p++) {
                int q = p*256 + tid;
                pb[p] = *reinterpret_cast<const float4*>(
                    B + (long)(k0 + (q >> 5))*VOCAB + n0 + ((q & 31) << 2));
            }
        }

        #pragma unroll
        for (int ks = 0; ks < 32; ks += 16) {
            unsigned af[4][4], bf[2][4];
            #pragma unroll
            for (int mt = 0; mt < 4; mt++) {
                int row = wm + mt*16 + (lane & 15);
                int col = ks + ((lane & 16) >> 1);
                ldsm_x4(af[mt], smem_u32(&Ah[buf][row][col]));
            }
            #pragma unroll
            for (int pr = 0; pr < 2; pr++) {
                int row = ks + (lane & 15);
                int col = wn + pr*16 + ((lane & 16) >> 1);
                ldsm_x4_t(bf[pr], smem_u32(&Bh[buf][row][col]));
            }
            #pragma unroll
            for (int mt = 0; mt < 4; mt++)
                #pragma unroll
                for (int nt = 0; nt < 4; nt++)
                    mma_f16(acc[mt*4 + nt], af[mt],
                            bf[nt >> 1][(nt & 1)*2], bf[nt >> 1][(nt & 1)*2 + 1]);
        }

        if (more) {
            #pragma unroll
            for (int i = 0; i < 2; i++)
                *reinterpret_cast<uint4*>(&Ah[buf^1][ar + i*64][ac]) = pa[i];
            #pragma unroll
            for (int p = 0; p < 4; p++) {
                int q = p*256 + tid;
                int r = q >> 5, c4 = (q & 31) << 2;
                __half2 h0 = __floats2half2_rn(pb[p].x, pb[p].y);
                __half2 h1 = __floats2half2_rn(pb[p].z, pb[p].w);
                uint2 u;
                u.x = *reinterpret_cast<unsigned*>(&h0);
                u.y = *reinterpret_cast<unsigned*>(&h1);
                *reinterpret_cast<uint2*>(&Bh[buf^1][r][c4]) = u;
            }
        }
        __syncthreads();
        buf ^= 1;
    }

    const int g  = lane >> 2;
    const int tg = lane & 3;
    #pragma unroll
    for (int nt = 0; nt < 4; nt++) {
        int n = n0 + wn + nt*8 + 2*tg;
        float2 bz = *reinterpret_cast<const float2*>(bias + n);
        #pragma unroll
        for (int mt = 0; mt < 4; mt++) {
            int m = m0 + wm + mt*16 + g;
            float* c = acc[mt*4 + nt];
            *reinterpret_cast<float2*>(C + (long)m*VOCAB + n)     = make_float2(c[0]+bz.x, c[1]+bz.y);
            *reinterpret_cast<float2*>(C + (long)(m+8)*VOCAB + n) = make_float2(c[2]+bz.x, c[3]+bz.y);
        }
    }
}

// ---------------------------------------------------------------------------
// TF32 small GEMM with optional fused LayerNorm on A.
// 64x64 tile, BK=32, 4 warps.  When LN: A holds raw activations; each block
// computes mean/rstd for its 64 rows (2 threads/row + shfl), then normalizes
// with gamma/beta during the A-tile fill.
// ---------------------------------------------------------------------------
template<bool GELU, bool LN>
__global__ __launch_bounds__(128) void tc_gemm(
    int N, int K,
    const float* __restrict__ A, int lda,
    const float* __restrict__ B, int ldb,
    float* __restrict__ C, int ldc,
    const float* __restrict__ bias,
    const float* __restrict__ residual,
    const float* __restrict__ ln_g,
    const float* __restrict__ ln_b)
{
    __shared__ float As[64][36];
    __shared__ float Bs[32][68];
    __shared__ float smean[64];
    __shared__ float srstd[64];

    const int tid  = threadIdx.x;
    const int lane = tid & 31;
    const int wid  = tid >> 5;
    const int wm   = (wid >> 1) * 32;
    const int wn   = (wid & 1) * 32;
    const int m0   = blockIdx.y * 64;
    const int n0   = blockIdx.x * 64;
    const int g    = lane >> 2;
    const int tg   = lane & 3;

    if (LN) {
        // stats: rows m0 .. m0+63, 2 threads per row
        int r  = tid >> 1;
        int hf = tid & 1;
        const float* rowp = A + (long)(m0 + r)*lda;
        float s = 0.f, s2 = 0.f;
        for (int i = hf*4; i < K; i += 8) {
            float4 u = *reinterpret_cast<const float4*>(rowp + i);
            s  += u.x + u.y + u.z + u.w;
            s2 += u.x*u.x + u.y*u.y + u.z*u.z + u.w*u.w;
        }
        s  += __shfl_xor_sync(0xffffffffu, s, 1);
        s2 += __shfl_xor_sync(0xffffffffu, s2, 1);
        if (!hf) {
            float inv = 1.f / (float)K;
            float mu  = s * inv;
            float var = s2 * inv - mu*mu;
            smean[r] = mu;
            srstd[r] = rsqrtf(var + 1e-5f);
        }
        __syncthreads();
    }

    float acc[8][4];
    #pragma unroll
    for (int i = 0; i < 8; i++)
        #pragma unroll
        for (int j = 0; j < 4; j++) acc[i][j] = 0.f;

    for (int k0 = 0; k0 < K; k0 += 32) {
        #pragma unroll
        for (int i = 0; i < 4; i++) {
            int idx = i*128 + tid;
            int r  = idx >> 3;
            int c4 = (idx & 7) << 2;
            float4 v = *reinterpret_cast<const float4*>(A + (long)(m0 + r)*lda + k0 + c4);
            if (LN) {
                float4 gm = *reinterpret_cast<const float4*>(ln_g + k0 + c4);
                float4 bt = *reinterpret_cast<const float4*>(ln_b + k0 + c4);
                float mu = smean[r], rs = srstd[r];
                v.x = (v.x - mu)*rs*gm.x + bt.x;
                v.y = (v.y - mu)*rs*gm.y + bt.y;
                v.z = (v.z - mu)*rs*gm.z + bt.z;
                v.w = (v.w - mu)*rs*gm.w + bt.w;
            }
            *reinterpret_cast<float4*>(&As[r][c4]) = cvt4(v);
        }
        #pragma unroll
        for (int i = 0; i < 4; i++) {
            int idx = i*128 + tid;
            int r  = idx >> 4;
            int c4 = (idx & 15) << 2;
            float4 v = make_float4(0.f,0.f,0.f,0.f);
            if (n0 + c4 < N)
                v = *reinterpret_cast<const float4*>(B + (long)(k0 + r)*ldb + n0 + c4);
            *reinterpret_cast<float4*>(&Bs[r][c4]) = cvt4(v);
        }
        __syncthreads();

        #pragma unroll
        for (int ks = 0; ks < 32; ks += 8) {
            unsigned af[2][4], bf[4][2];
            #pragma unroll
            for (int mt = 0; mt < 2; mt++) {
                int mr = wm + mt*16 + g;
                af[mt][0] = __float_as_uint(As[mr  ][ks + tg    ]);
                af[mt][1] = __float_as_uint(As[mr+8][ks + tg    ]);
                af[mt][2] = __float_as_uint(As[mr  ][ks + tg + 4]);
                af[mt][3] = __float_as_uint(As[mr+8][ks + tg + 4]);
            }
            #pragma unroll
            for (int nt = 0; nt < 4; nt++) {
                int nc = wn + nt*8 + g;
                bf[nt][0] = __float_as_uint(Bs[ks + tg    ][nc]);
                bf[nt][1] = __float_as_uint(Bs[ks + tg + 4][nc]);
            }
            #pragma unroll
            for (int mt = 0; mt < 2; mt++)
                #pragma unroll
                for (int nt = 0; nt < 4; nt++)
                    mma_tf32(acc[mt*4 + nt], af[mt], bf[nt]);
        }
        __syncthreads();
    }

    #pragma unroll
    for (int nt = 0; nt < 4; nt++) {
        int n = n0 + wn + nt*8 + 2*tg;
        if (n < N) {
            float2 bz = make_float2(0.f, 0.f);
            if (bias) bz = *reinterpret_cast<const float2*>(bias + n);
            #pragma unroll
            for (int mt = 0; mt < 2; mt++) {
                int m = m0 + wm + mt*16 + g;
                float* c = acc[mt*4 + nt];
                float v[4] = {c[0]+bz.x, c[1]+bz.y, c[2]+bz.x, c[3]+bz.y};
                if (GELU) {
                    #pragma unroll
                    for (int q = 0; q < 4; q++) {
                        float u = v[q];
                        float tt = 0.7978845608028654f * (u + 0.044715f*u*u*u);
                        v[q] = 0.5f*u*(1.f + tanhf(tt));
                    }
                }
                if (residual) {
                    float2 r0 = *reinterpret_cast<const float2*>(residual + (long)m*ldc + n);
                    float2 r1 = *reinterpret_cast<const float2*>(residual + (long)(m+8)*ldc + n);
                    v[0] += r0.x; v[1] += r0.y; v[2] += r1.x; v[3] += r1.y;
                }
                *reinterpret_cast<float2*>(C + (long)m*ldc + n)     = make_float2(v[0], v[1]);
                *reinterpret_cast<float2*>(C + (long)(m+8)*ldc + n) = make_float2(v[2], v[3]);
            }
        }
    }
}

// ---------------------------------------------------------------------------
// Causal attention: block = (head, batch, q-chunk of 16). 128 threads.
// ---------------------------------------------------------------------------
#define QC 16
__global__ __launch_bounds__(128) void attention_kernel(
    const float* __restrict__ qkv, float* __restrict__ att_out)
{
    __shared__ float Ks[TT][36];
    __shared__ float Vs[TT][32];
    __shared__ float Ps[QC][129];
    const int h  = blockIdx.x;
    const int b  = blockIdx.y;
    const int qc = blockIdx.z;
    const int tid = threadIdx.x;
    const float scale = 0.17677669529663687f;

    {
        const float* kp = qkv + (long)(b*TT + tid)*(3*DD) + DD + h*HD_ATT;
        const float* vp = kp + DD;
        #pragma unroll
        for (int d = 0; d < 32; d += 4) {
            *reinterpret_cast<float4*>(&Ks[tid][d]) = *reinterpret_cast<const float4*>(kp + d);
            *reinterpret_cast<float4*>(&Vs[tid][d]) = *reinterpret_cast<const float4*>(vp + d);
        }
    }
    __syncthreads();

    const int q = tid >> 3;
    const int j = tid & 7;
    const int qglob = qc*QC + q;

    float qv[32];
    {
        const float* qp = qkv + (long)(b*TT + qglob)*(3*DD) + h*HD_ATT;
        #pragma unroll
        for (int d = 0; d < 32; d += 4) {
            float4 t = *reinterpret_cast<const float4*>(qp + d);
            qv[d]=t.x; qv[d+1]=t.y; qv[d+2]=t.z; qv[d+3]=t.w;
        }
    }

    float s[16];
    float mmax = -1e30f;
    #pragma unroll
    for (int kk = 0; kk < 16; kk++) {
        int k = kk*8 + j;
        float acc = 0.f;
        #pragma unroll
        for (int d = 0; d < 32; d += 4) {
            float4 kv = *reinterpret_cast<const float4*>(&Ks[k][d]);
            acc += qv[d]*kv.x + qv[d+1]*kv.y + qv[d+2]*kv.z + qv[d+3]*kv.w;
        }
        s[kk] = (k <= qglob) ? acc*scale : -1e30f;
        mmax = fmaxf(mmax, s[kk]);
    }
    #pragma unroll
    for (int o = 1; o < 8; o <<= 1)
        mmax = fmaxf(mmax, __shfl_xor_sync(0xffffffffu, mmax, o));

    float l = 0.f;
    #pragma unroll
    for (int kk = 0; kk < 16; kk++) {
        float p = __expf(s[kk] - mmax);
        l += p;
        Ps[q][kk*8 + j] = p;
    }
    #pragma unroll
    for (int o = 1; o < 8; o <<= 1)
        l += __shfl_xor_sync(0xffffffffu, l, o);
    float linv = 1.f / l;
    __syncthreads();

    float ox=0.f, oy=0.f, oz=0.f, ow=0.f;
    #pragma unroll 4
    for (int k = 0; k < TT; k++) {
        float p = Ps[q][k];
        float4 v = *reinterpret_cast<const float4*>(&Vs[k][j*4]);
        ox += p*v.x; oy += p*v.y; oz += p*v.z; ow += p*v.w;
    }
    float4 o4 = make_float4(ox*linv, oy*linv, oz*linv, ow*linv);
    *reinterpret_cast<float4*>(att_out + (long)(b*TT + qglob)*DD + h*HD_ATT + j*4) = o4;
}

// ---------------------------------------------------------------------------
// Memory scan (collapsed; see derivation R2).  GEMV via packed fma.rn.f32x2
// with 4 independent accumulators (breaks the RAW latency chain).
// Writes carry-in rv directly as fp16 into g_ch right half.
// ---------------------------------------------------------------------------
__global__ __launch_bounds__(320) void scan_kernel(
    const float* __restrict__ Hif,
    const float* __restrict__ W_iface,
    __half* __restrict__ ch)
{
    int b   = blockIdx.x;
    int tid = threadIdx.x;
    __shared__ __align__(16) float rv_s[MD];
    __shared__ float m_s[MD];
    __shared__ float if_s[260];

    unsigned long long w2[64];
    int gcol = 0;
    if (tid < 260) {
        gcol = (tid/65)*129 + 64 + (tid%65);
        #pragma unroll
        for (int k = 0; k < 64; k++) {
            float lo = W_iface[(long)(256 + 2*k    )*IFACE + gcol];
            float hi = W_iface[(long)(256 + 2*k + 1)*IFACE + gcol];
            asm("mov.b64 %0, {%1,%2};" : "=l"(w2[k]) : "f"(lo), "f"(hi));
        }
    }
    if (tid < MD) { rv_s[tid] = 0.f; m_s[tid] = 0.f; }
    __syncthreads();

    const unsigned long long* rv2 = reinterpret_cast<const unsigned long long*>(rv_s);

    for (int t = 0; t < TT; t++) {
        if (tid < MD)
            ch[(long)(b*TT + t)*CDIM + DD + tid] = __float2half(rv_s[tid]);
        if (tid < 260) {
            float hbase = Hif[(long)(b*TT + t)*IFACE + gcol];
            unsigned long long a0 = 0ull, a1 = 0ull, a2 = 0ull, a3 = 0ull;
            #pragma unroll
            for (int k = 0; k < 64; k += 4) {
                asm("fma.rn.f32x2 %0, %1, %2, %0;" : "+l"(a0) : "l"(rv2[k  ]), "l"(w2[k  ]));
                asm("fma.rn.f32x2 %0, %1, %2, %0;" : "+l"(a1) : "l"(rv2[k+1]), "l"(w2[k+1]));
                asm("fma.rn.f32x2 %0, %1, %2, %0;" : "+l"(a2) : "l"(rv2[k+2]), "l"(w2[k+2]));
                asm("fma.rn.f32x2 %0, %1, %2, %0;" : "+l"(a3) : "l"(rv2[k+3]), "l"(w2[k+3]));
            }
            float l0, h0, l1, h1, l2, h2, l3, h3;
            asm("mov.b64 {%0,%1}, %2;" : "=f"(l0), "=f"(h0) : "l"(a0));
            asm("mov.b64 {%0,%1}, %2;" : "=f"(l1), "=f"(h1) : "l"(a1));
            asm("mov.b64 {%0,%1}, %2;" : "=f"(l2), "=f"(h2) : "l"(a2));
            asm("mov.b64 {%0,%1}, %2;" : "=f"(l3), "=f"(h3) : "l"(a3));
            if_s[tid] = hbase + ((l0 + h0) + (l1 + h1)) + ((l2 + h2) + (l3 + h3));
        }
        __syncthreads();
        if (tid < MD) {
            int hh = tid >> 5;
            int d  = tid & 31;
            int base = hh*65;
            float wv = if_s[base + d];
            float er = 1.f / (1.f + __expf(-if_s[base + 32 + d]));
            float ag = 1.f / (1.f + __expf(-if_s[base + 64]));
            float mo = m_s[tid];
            rv_s[tid] = rv_s[tid] + mo;
            m_s[tid]  = mo * (1.f - er*(1.f/512.f)) + (ag*(1.f/512.f))*wv;
        }
        __syncthreads();
    }
}

// ---------------------------------------------------------------------------
// Launch
// ---------------------------------------------------------------------------
extern "C" void kernel_launch(void* const* d_in, const int* in_sizes, int n_in,
                              void* d_out, int out_size)
{
    const int*   seq   = (const int*)  d_in[0];
    const float* tok   = (const float*)d_in[1];
    const float* pos   = (const float*)d_in[2];
    const float* Wqkv  = (const float*)d_in[3];
    const float* Wo    = (const float*)d_in[4];
    const float* ln1g  = (const float*)d_in[5];
    const float* ln1b  = (const float*)d_in[6];
    const float* ln2g  = (const float*)d_in[7];
    const float* ln2b  = (const float*)d_in[8];
    const float* W1    = (const float*)d_in[9];
    const float* b1    = (const float*)d_in[10];
    const float* W2    = (const float*)d_in[11];
    const float* b2    = (const float*)d_in[12];
    const float* lnfg  = (const float*)d_in[13];
    const float* lnfb  = (const float*)d_in[14];
    const float* Wlog  = (const float*)d_in[15];
    const float* blog  = (const float*)d_in[16];
    const float* Wif   = (const float*)d_in[17];
    const float* bif   = (const float*)d_in[18];
    float* out = (float*)d_out;

    float *gx, *gqkv, *gatt, *gff, *gHif;
    __half* gch;
    cudaGetSymbolAddress((void**)&gx,   g_x);
    cudaGetSymbolAddress((void**)&gqkv, g_qkv);
    cudaGetSymbolAddress((void**)&gatt, g_att);
    cudaGetSymbolAddress((void**)&gff,  g_ff);
    cudaGetSymbolAddress((void**)&gHif, g_Hif);
    cudaGetSymbolAddress((void**)&gch,  g_ch);

    embed_kernel<<<BT, DD>>>(seq, tok, pos, gx);

    for (int l = 0; l < 2; l++) {
        // QKV with fused ln1
        tc_gemm<false, true><<<dim3(12, 8), 128>>>(
            3*DD, DD, gx, DD, Wqkv + (long)l*DD*3*DD, 3*DD,
            gqkv, 3*DD, nullptr, nullptr, ln1g + l*DD, ln1b + l*DD);
        attention_kernel<<<dim3(NH, BB, TT/QC), 128>>>(gqkv, gatt);
        tc_gemm<false, false><<<dim3(4, 8), 128>>>(
            DD, DD, gatt, DD, Wo + (long)l*DD*DD, DD,
            gx, DD, nullptr, gx, nullptr, nullptr);
        // FF1 with fused ln2 + gelu
        tc_gemm<true, true><<<dim3(16, 8), 128>>>(
            FF_, DD, gx, DD, W1 + (long)l*DD*FF_, FF_,
            gff, FF_, b1 + l*FF_, nullptr, ln2g + l*DD, ln2b + l*DD);
        tc_gemm<false, false><<<dim3(4, 8), 128>>>(
            DD, FF_, gff, FF_, W2 + (long)l*FF_*DD, DD,
            gx, DD, b2 + l*DD, gx, nullptr, nullptr);
    }

    // interface projection with fused final LN
    tc_gemm<false, true><<<dim3((IFACE + 63)/64, 8), 128>>>(
        IFACE, DD, gx, DD, Wif, IFACE, gHif, IFACE, bif, nullptr, lnfg, lnfb);

    // final LN -> fp16 concat left half
    lnf_half_kernel<<<BT, DD>>>(gx, lnfg, lnfb, gch);

    // scan -> fp16 concat right half
    scan_kernel<<<BB, 320>>>(gHif, Wif, gch);

    // logits = [lnf|rv] @ W_logits + b_logits — fp16 mma.sync m16n8k16
    logits_f16_kernel<<<dim3(4, VOCAB/128), 256>>>(gch, Wlog, out, blog);
}

// round 11
// speedup vs baseline: 2.7383x; 1.4497x over previous
#include <cuda_runtime.h>
#include <cuda_bf16.h>
#include <cuda_fp16.h>
#include <math.h>
#include <cstdint>

// ---------------------------------------------------------------------------
// Problem constants
// ---------------------------------------------------------------------------
#define BB 4
#define TT 128
#define DD 256
#define FF_ 1024
#define NH 8
#define HD_ATT 32
#define VOCAB 32000
#define MD 128
#define IFACE 516       // MH*(4*HD+1)
#define CDIM 384        // D + MD
#define BT (BB*TT)      // 512

// ---------------------------------------------------------------------------
// Scratch (device globals; no allocation allowed)
// ---------------------------------------------------------------------------
__device__ float g_x  [BT*DD];
__device__ float g_qkv[BT*3*DD];
__device__ float g_att[BT*DD];
__device__ float g_ff [BT*FF_];
__device__ float g_Hif[BT*IFACE];
__device__ __align__(16) __half g_ch[BT*CDIM];   // concat [lnf(x) | rv] in fp16

// ---------------------------------------------------------------------------
// Embedding
// ---------------------------------------------------------------------------
__global__ void embed_kernel(const int* __restrict__ seq,
                             const float* __restrict__ tok,
                             const float* __restrict__ pos,
                             float* __restrict__ x)
{
    int bt = blockIdx.x;
    int d  = threadIdx.x;
    int t  = bt & (TT-1);
    x[bt*DD + d] = tok[(long)seq[bt]*DD + d] + pos[t*DD + d];
}

// ---------------------------------------------------------------------------
// Final LayerNorm -> fp16 into g_ch left half (stride CDIM)
// ---------------------------------------------------------------------------
__global__ void lnf_half_kernel(const float* __restrict__ x,
                                const float* __restrict__ g,
                                const float* __restrict__ b,
                                __half* __restrict__ ch)
{
    int row = blockIdx.x;
    int tid = threadIdx.x;
    __shared__ float red[8];
    float v = x[row*DD + tid];
    float s = v;
    #pragma unroll
    for (int k = 16; k; k >>= 1) s += __shfl_xor_sync(0xffffffffu, s, k);
    if ((tid & 31) == 0) red[tid >> 5] = s;
    __syncthreads();
    float mean = 0.f;
    #pragma unroll
    for (int i = 0; i < 8; i++) mean += red[i];
    mean *= (1.f/256.f);
    __syncthreads();
    float d = v - mean;
    float s2 = d*d;
    #pragma unroll
    for (int k = 16; k; k >>= 1) s2 += __shfl_xor_sync(0xffffffffu, s2, k);
    if ((tid & 31) == 0) red[tid >> 5] = s2;
    __syncthreads();
    float var = 0.f;
    #pragma unroll
    for (int i = 0; i < 8; i++) var += red[i];
    var *= (1.f/256.f);
    ch[row*CDIM + tid] = __float2half(d * rsqrtf(var + 1e-5f) * g[tid] + b[tid]);
}

// ---------------------------------------------------------------------------
// TF32 / cp.async helpers
// ---------------------------------------------------------------------------
__device__ __forceinline__ unsigned f2tf32(float x) {
    unsigned r;
    asm("cvt.rna.tf32.f32 %0, %1;" : "=r"(r) : "f"(x));
    return r;
}
__device__ __forceinline__ void mma_tf32(float* c, const unsigned* a, const unsigned* b) {
    asm volatile(
        "mma.sync.aligned.m16n8k8.row.col.f32.tf32.tf32.f32 "
        "{%0,%1,%2,%3}, {%4,%5,%6,%7}, {%8,%9}, {%0,%1,%2,%3};"
        : "+f"(c[0]), "+f"(c[1]), "+f"(c[2]), "+f"(c[3])
        : "r"(a[0]), "r"(a[1]), "r"(a[2]), "r"(a[3]),
          "r"(b[0]), "r"(b[1]));
}
__device__ __forceinline__ uint32_t smem_u32(const void* p) {
    uint32_t a;
    asm("{ .reg .u64 t; cvta.to.shared.u64 t, %1; cvt.u32.u64 %0, t; }" : "=r"(a) : "l"(p));
    return a;
}
__device__ __forceinline__ void cp_async16(uint32_t saddr, const void* gptr) {
    asm volatile("cp.async.cg.shared.global [%0], [%1], 16;" :: "r"(saddr), "l"(gptr));
}
__device__ __forceinline__ void cp_commit() {
    asm volatile("cp.async.commit_group;" ::: "memory");
}
__device__ __forceinline__ void cp_wait1() {
    asm volatile("cp.async.wait_group 1;" ::: "memory");
}
__device__ __forceinline__ void cp_wait0() {
    asm volatile("cp.async.wait_group 0;" ::: "memory");
}

// ---------------------------------------------------------------------------
// FP16 mma helpers (logits GEMM)
// ---------------------------------------------------------------------------
__device__ __forceinline__ void ldsm_x4(unsigned* r, uint32_t addr) {
    asm volatile("ldmatrix.sync.aligned.m8n8.x4.shared.b16 {%0,%1,%2,%3}, [%4];"
        : "=r"(r[0]), "=r"(r[1]), "=r"(r[2]), "=r"(r[3]) : "r"(addr));
}
__device__ __forceinline__ void ldsm_x4_t(unsigned* r, uint32_t addr) {
    asm volatile("ldmatrix.sync.aligned.m8n8.x4.trans.shared.b16 {%0,%1,%2,%3}, [%4];"
        : "=r"(r[0]), "=r"(r[1]), "=r"(r[2]), "=r"(r[3]) : "r"(addr));
}
__device__ __forceinline__ void mma_f16(float* c, const unsigned* a, unsigned b0, unsigned b1) {
    asm volatile(
        "mma.sync.aligned.m16n8k16.row.col.f32.f16.f16.f32 "
        "{%0,%1,%2,%3}, {%4,%5,%6,%7}, {%8,%9}, {%0,%1,%2,%3};"
        : "+f"(c[0]), "+f"(c[1]), "+f"(c[2]), "+f"(c[3])
        : "r"(a[0]), "r"(a[1]), "r"(a[2]), "r"(a[3]),
          "r"(b0), "r"(b1));
}

// ---------------------------------------------------------------------------
// FP16 logits GEMM (unchanged): C[512,32000]=A_h[512,384]@B + bias
// ---------------------------------------------------------------------------
__global__ __launch_bounds__(256, 2) void logits_f16_kernel(
    const __half* __restrict__ A,
    const float* __restrict__ B,
    float* __restrict__ C,
    const float* __restrict__ bias)
{
    __shared__ __half Ah[2][128][40];
    __shared__ __half Bh[2][32][136];

    const int tid  = threadIdx.x;
    const int lane = tid & 31;
    const int wid  = tid >> 5;
    const int wm   = (wid >> 2) * 64;
    const int wn   = (wid & 3) * 32;
    const int m0   = blockIdx.x * 128;   // m fastest
    const int n0   = blockIdx.y * 128;

    const int ar = tid >> 2;
    const int ac = (tid & 3) << 3;

    float acc[16][4];
    #pragma unroll
    for (int i = 0; i < 16; i++)
        #pragma unroll
        for (int j = 0; j < 4; j++) acc[i][j] = 0.f;

    #pragma unroll
    for (int i = 0; i < 2; i++) {
        uint4 v = *reinterpret_cast<const uint4*>(A + (long)(m0 + ar + i*64)*CDIM + ac);
        *reinterpret_cast<uint4*>(&Ah[0][ar + i*64][ac]) = v;
    }
    #pragma unroll
    for (int p = 0; p < 4; p++) {
        int q = p*256 + tid;
        int r = q >> 5, c4 = (q & 31) << 2;
        float4 v = *reinterpret_cast<const float4*>(B + (long)r*VOCAB + n0 + c4);
        __half2 h0 = __floats2half2_rn(v.x, v.y);
        __half2 h1 = __floats2half2_rn(v.z, v.w);
        uint2 u;
        u.x = *reinterpret_cast<unsigned*>(&h0);
        u.y = *reinterpret_cast<unsigned*>(&h1);
        *reinterpret_cast<uint2*>(&Bh[0][r][c4]) = u;
    }
    __syncthreads();

    int buf = 0;
    #pragma unroll 1
    for (int kt = 0; kt < CDIM/32; kt++) {
        const bool more = (kt + 1) < CDIM/32;
        uint4 pa[2];
        float4 pb[4];
        if (more) {
            const int k0 = (kt + 1) * 32;
            #pragma unroll
            for (int i = 0; i < 2; i++)
                pa[i] = *reinterpret_cast<const uint4*>(A + (long)(m0 + ar + i*64)*CDIM + k0 + ac);
            #pragma unroll
            for (int p = 0; p < 4; p++) {
                int q = p*256 + tid;
                pb[p] = *reinterpret_cast<const float4*>(
                    B + (long)(k0 + (q >> 5))*VOCAB + n0 + ((q & 31) << 2));
            }
        }

        #pragma unroll
        for (int ks = 0; ks < 32; ks += 16) {
            unsigned af[4][4], bf[2][4];
            #pragma unroll
            for (int mt = 0; mt < 4; mt++) {
                int row = wm + mt*16 + (lane & 15);
                int col = ks + ((lane & 16) >> 1);
                ldsm_x4(af[mt], smem_u32(&Ah[buf][row][col]));
            }
            #pragma unroll
            for (int pr = 0; pr < 2; pr++) {
                int row = ks + (lane & 15);
                int col = wn + pr*16 + ((lane & 16) >> 1);
                ldsm_x4_t(bf[pr], smem_u32(&Bh[buf][row][col]));
            }
            #pragma unroll
            for (int mt = 0; mt < 4; mt++)
                #pragma unroll
                for (int nt = 0; nt < 4; nt++)
                    mma_f16(acc[mt*4 + nt], af[mt],
                            bf[nt >> 1][(nt & 1)*2], bf[nt >> 1][(nt & 1)*2 + 1]);
        }

        if (more) {
            #pragma unroll
            for (int i = 0; i < 2; i++)
                *reinterpret_cast<uint4*>(&Ah[buf^1][ar + i*64][ac]) = pa[i];
            #pragma unroll
            for (int p = 0; p < 4; p++) {
                int q = p*256 + tid;
                int r = q >> 5, c4 = (q & 31) << 2;
                __half2 h0 = __floats2half2_rn(pb[p].x, pb[p].y);
                __half2 h1 = __floats2half2_rn(pb[p].z, pb[p].w);
                uint2 u;
                u.x = *reinterpret_cast<unsigned*>(&h0);
                u.y = *reinterpret_cast<unsigned*>(&h1);
                *reinterpret_cast<uint2*>(&Bh[buf^1][r][c4]) = u;
            }
        }
        __syncthreads();
        buf ^= 1;
    }

    const int g  = lane >> 2;
    const int tg = lane & 3;
    #pragma unroll
    for (int nt = 0; nt < 4; nt++) {
        int n = n0 + wn + nt*8 + 2*tg;
        float2 bz = *reinterpret_cast<const float2*>(bias + n);
        #pragma unroll
        for (int mt = 0; mt < 4; mt++) {
            int m = m0 + wm + mt*16 + g;
            float* c = acc[mt*4 + nt];
            *reinterpret_cast<float2*>(C + (long)m*VOCAB + n)     = make_float2(c[0]+bz.x, c[1]+bz.y);
            *reinterpret_cast<float2*>(C + (long)(m+8)*VOCAB + n) = make_float2(c[2]+bz.x, c[3]+bz.y);
        }
    }
}

// ---------------------------------------------------------------------------
// TF32 small GEMM, 2-stage cp.async pipeline, optional fused LayerNorm on A.
// 64x64 tile, BK=32, 4 warps.  Raw fp32 tiles streamed via cp.async.cg into
// double-buffered smem; tf32 cvt (and LN transform) applied at fragment load.
// Static smem: 2*(64*36 + 32*68)*4 + LN arrays = 38.4 KB (< 48 KB limit).
// ---------------------------------------------------------------------------
template<bool GELU, bool LN>
__global__ __launch_bounds__(128) void tc_gemm(
    int N, int K,
    const float* __restrict__ A, int lda,
    const float* __restrict__ B, int ldb,
    float* __restrict__ C, int ldc,
    const float* __restrict__ bias,
    const float* __restrict__ residual,
    const float* __restrict__ ln_g,
    const float* __restrict__ ln_b)
{
    __shared__ float As[2][64][36];
    __shared__ float Bs[2][32][68];
    __shared__ float smean[64];
    __shared__ float srstd[64];
    __shared__ float sg[256];
    __shared__ float sb[256];

    const int tid  = threadIdx.x;
    const int lane = tid & 31;
    const int wid  = tid >> 5;
    const int wm   = (wid >> 1) * 32;
    const int wn   = (wid & 1) * 32;
    const int m0   = blockIdx.y * 64;
    const int n0   = blockIdx.x * 64;
    const int g    = lane >> 2;
    const int tg   = lane & 3;
    const int nt   = K >> 5;

    const uint32_t asBase = smem_u32(&As[0][0][0]);
    const uint32_t bsBase = smem_u32(&Bs[0][0][0]);

    const int a_r  = tid >> 3;
    const int a_c4 = (tid & 7) << 2;
    const int b_r  = tid >> 4;
    const int b_c4 = (tid & 15) << 2;

    // fill one k-tile (stage s) via cp.async; one commit group per call
    auto fill = [&](int s, int k0) {
        #pragma unroll
        for (int i = 0; i < 4; i++) {
            int r = a_r + i*16;
            cp_async16(asBase + (uint32_t)(((s*64 + r)*36 + a_c4) << 2),
                       A + (long)(m0 + r)*lda + k0 + a_c4);
        }
        #pragma unroll
        for (int i = 0; i < 4; i++) {
            int r = b_r + i*8;
            if (n0 + b_c4 < N) {
                cp_async16(bsBase + (uint32_t)(((s*32 + r)*68 + b_c4) << 2),
                           B + (long)(k0 + r)*ldb + n0 + b_c4);
            } else {
                *reinterpret_cast<float4*>(&Bs[s][r][b_c4]) = make_float4(0.f,0.f,0.f,0.f);
            }
        }
        cp_commit();
    };

    fill(0, 0);

    if (LN) {
        // per-row stats (2 threads/row) on raw A rows (L2-resident)
        int r  = tid >> 1;
        int hf = tid & 1;
        const float* rowp = A + (long)(m0 + r)*lda;
        float s = 0.f, s2 = 0.f;
        for (int i = hf*4; i < K; i += 8) {
            float4 u = *reinterpret_cast<const float4*>(rowp + i);
            s  += u.x + u.y + u.z + u.w;
            s2 += u.x*u.x + u.y*u.y + u.z*u.z + u.w*u.w;
        }
        s  += __shfl_xor_sync(0xffffffffu, s, 1);
        s2 += __shfl_xor_sync(0xffffffffu, s2, 1);
        if (!hf) {
            float inv = 1.f / (float)K;
            float mu  = s * inv;
            float var = s2 * inv - mu*mu;
            smean[r] = mu;
            srstd[r] = rsqrtf(var + 1e-5f);
        }
        // gamma/beta to smem (K == 256 for all LN GEMMs)
        if (tid < 64) {
            *reinterpret_cast<float4*>(&sg[tid*4]) = *reinterpret_cast<const float4*>(ln_g + tid*4);
        } else {
            int t = tid - 64;
            *reinterpret_cast<float4*>(&sb[t*4]) = *reinterpret_cast<const float4*>(ln_b + t*4);
        }
        __syncthreads();
    }

    // hoist per-row LN constants (4 rows per lane: wm+g, +8, +16, +24)
    float rs_[4], mrs_[4];
    if (LN) {
        #pragma unroll
        for (int q = 0; q < 4; q++) {
            int r = wm + q*8 + g;
            rs_[q]  = srstd[r];
            mrs_[q] = smean[r] * rs_[q];
        }
    }

    float acc[8][4];
    #pragma unroll
    for (int i = 0; i < 8; i++)
        #pragma unroll
        for (int j = 0; j < 4; j++) acc[i][j] = 0.f;

    #pragma unroll 1
    for (int kt = 0; kt < nt; kt++) {
        const bool more = (kt + 1) < nt;
        if (more) fill((kt + 1) & 1, (kt + 1) * 32);   // prefetch next
        if (more) cp_wait1(); else cp_wait0();          // tile kt resident
        __syncthreads();

        const int buf = kt & 1;
        const int k0  = kt * 32;

        #pragma unroll
        for (int ks = 0; ks < 32; ks += 8) {
            unsigned af[2][4], bf[4][2];
            float gm0 = 0.f, gm4 = 0.f, bt0 = 0.f, bt4 = 0.f;
            if (LN) {
                gm0 = sg[k0 + ks + tg];   gm4 = sg[k0 + ks + tg + 4];
                bt0 = sb[k0 + ks + tg];   bt4 = sb[k0 + ks + tg + 4];
            }
            #pragma unroll
            for (int mt = 0; mt < 2; mt++) {
                int mr = wm + mt*16 + g;
                float r00 = As[buf][mr  ][ks + tg    ];
                float r10 = As[buf][mr+8][ks + tg    ];
                float r04 = As[buf][mr  ][ks + tg + 4];
                float r14 = As[buf][mr+8][ks + tg + 4];
                if (LN) {
                    float rsa = rs_[mt*2],   ma = mrs_[mt*2];
                    float rsb = rs_[mt*2+1], mb = mrs_[mt*2+1];
                    r00 = fmaf(fmaf(r00, rsa, -ma), gm0, bt0);
                    r10 = fmaf(fmaf(r10, rsb, -mb), gm0, bt0);
                    r04 = fmaf(fmaf(r04, rsa, -ma), gm4, bt4);
                    r14 = fmaf(fmaf(r14, rsb, -mb), gm4, bt4);
                }
                af[mt][0] = f2tf32(r00);
                af[mt][1] = f2tf32(r10);
                af[mt][2] = f2tf32(r04);
                af[mt][3] = f2tf32(r14);
            }
            #pragma unroll
            for (int nt2 = 0; nt2 < 4; nt2++) {
                int nc = wn + nt2*8 + g;
                bf[nt2][0] = f2tf32(Bs[buf][ks + tg    ][nc]);
                bf[nt2][1] = f2tf32(Bs[buf][ks + tg + 4][nc]);
            }
            #pragma unroll
            for (int mt = 0; mt < 2; mt++)
                #pragma unroll
                for (int nt2 = 0; nt2 < 4; nt2++)
                    mma_tf32(acc[mt*4 + nt2], af[mt], bf[nt2]);
        }
        __syncthreads();   // all warps done with buf before it is refilled
    }

    #pragma unroll
    for (int nt2 = 0; nt2 < 4; nt2++) {
        int n = n0 + wn + nt2*8 + 2*tg;
        if (n < N) {
            float2 bz = make_float2(0.f, 0.f);
            if (bias) bz = *reinterpret_cast<const float2*>(bias + n);
            #pragma unroll
            for (int mt = 0; mt < 2; mt++) {
                int m = m0 + wm + mt*16 + g;
                float* c = acc[mt*4 + nt2];
                float v[4] = {c[0]+bz.x, c[1]+bz.y, c[2]+bz.x, c[3]+bz.y};
                if (GELU) {
                    #pragma unroll
                    for (int q = 0; q < 4; q++) {
                        float u = v[q];
                        float tt = 0.7978845608028654f * (u + 0.044715f*u*u*u);
                        v[q] = 0.5f*u*(1.f + tanhf(tt));
                    }
                }
                if (residual) {
                    float2 r0 = *reinterpret_cast<const float2*>(residual + (long)m*ldc + n);
                    float2 r1 = *reinterpret_cast<const float2*>(residual + (long)(m+8)*ldc + n);
                    v[0] += r0.x; v[1] += r0.y; v[2] += r1.x; v[3] += r1.y;
                }
                *reinterpret_cast<float2*>(C + (long)m*ldc + n)     = make_float2(v[0], v[1]);
                *reinterpret_cast<float2*>(C + (long)(m+8)*ldc + n) = make_float2(v[2], v[3]);
            }
        }
    }
}

// ---------------------------------------------------------------------------
// Causal attention: block = (head, batch, q-chunk of 16). 128 threads.
// ---------------------------------------------------------------------------
#define QC 16
__global__ __launch_bounds__(128) void attention_kernel(
    const float* __restrict__ qkv, float* __restrict__ att_out)
{
    __shared__ float Ks[TT][36];
    __shared__ float Vs[TT][32];
    __shared__ float Ps[QC][129];
    const int h  = blockIdx.x;
    const int b  = blockIdx.y;
    const int qc = blockIdx.z;
    const int tid = threadIdx.x;
    const float scale = 0.17677669529663687f;

    {
        const float* kp = qkv + (long)(b*TT + tid)*(3*DD) + DD + h*HD_ATT;
        const float* vp = kp + DD;
        #pragma unroll
        for (int d = 0; d < 32; d += 4) {
            *reinterpret_cast<float4*>(&Ks[tid][d]) = *reinterpret_cast<const float4*>(kp + d);
            *reinterpret_cast<float4*>(&Vs[tid][d]) = *reinterpret_cast<const float4*>(vp + d);
        }
    }
    __syncthreads();

    const int q = tid >> 3;
    const int j = tid & 7;
    const int qglob = qc*QC + q;

    float qv[32];
    {
        const float* qp = qkv + (long)(b*TT + qglob)*(3*DD) + h*HD_ATT;
        #pragma unroll
        for (int d = 0; d < 32; d += 4) {
            float4 t = *reinterpret_cast<const float4*>(qp + d);
            qv[d]=t.x; qv[d+1]=t.y; qv[d+2]=t.z; qv[d+3]=t.w;
        }
    }

    float s[16];
    float mmax = -1e30f;
    #pragma unroll
    for (int kk = 0; kk < 16; kk++) {
        int k = kk*8 + j;
        float acc = 0.f;
        #pragma unroll
        for (int d = 0; d < 32; d += 4) {
            float4 kv = *reinterpret_cast<const float4*>(&Ks[k][d]);
            acc += qv[d]*kv.x + qv[d+1]*kv.y + qv[d+2]*kv.z + qv[d+3]*kv.w;
        }
        s[kk] = (k <= qglob) ? acc*scale : -1e30f;
        mmax = fmaxf(mmax, s[kk]);
    }
    #pragma unroll
    for (int o = 1; o < 8; o <<= 1)
        mmax = fmaxf(mmax, __shfl_xor_sync(0xffffffffu, mmax, o));

    float l = 0.f;
    #pragma unroll
    for (int kk = 0; kk < 16; kk++) {
        float p = __expf(s[kk] - mmax);
        l += p;
        Ps[q][kk*8 + j] = p;
    }
    #pragma unroll
    for (int o = 1; o < 8; o <<= 1)
        l += __shfl_xor_sync(0xffffffffu, l, o);
    float linv = 1.f / l;
    __syncthreads();

    float ox=0.f, oy=0.f, oz=0.f, ow=0.f;
    #pragma unroll 4
    for (int k = 0; k < TT; k++) {
        float p = Ps[q][k];
        float4 v = *reinterpret_cast<const float4*>(&Vs[k][j*4]);
        ox += p*v.x; oy += p*v.y; oz += p*v.z; ow += p*v.w;
    }
    float4 o4 = make_float4(ox*linv, oy*linv, oz*linv, ow*linv);
    *reinterpret_cast<float4*>(att_out + (long)(b*TT + qglob)*DD + h*HD_ATT + j*4) = o4;
}

// ---------------------------------------------------------------------------
// Memory scan (collapsed; see derivation R2).  fma.rn.f32x2 GEMV, 4 accs.
// ---------------------------------------------------------------------------
__global__ __launch_bounds__(320) void scan_kernel(
    const float* __restrict__ Hif,
    const float* __restrict__ W_iface,
    __half* __restrict__ ch)
{
    int b   = blockIdx.x;
    int tid = threadIdx.x;
    __shared__ __align__(16) float rv_s[MD];
    __shared__ float m_s[MD];
    __shared__ float if_s[260];

    unsigned long long w2[64];
    int gcol = 0;
    if (tid < 260) {
        gcol = (tid/65)*129 + 64 + (tid%65);
        #pragma unroll
        for (int k = 0; k < 64; k++) {
            float lo = W_iface[(long)(256 + 2*k    )*IFACE + gcol];
            float hi = W_iface[(long)(256 + 2*k + 1)*IFACE + gcol];
            asm("mov.b64 %0, {%1,%2};" : "=l"(w2[k]) : "f"(lo), "f"(hi));
        }
    }
    if (tid < MD) { rv_s[tid] = 0.f; m_s[tid] = 0.f; }
    __syncthreads();

    const unsigned long long* rv2 = reinterpret_cast<const unsigned long long*>(rv_s);

    for (int t = 0; t < TT; t++) {
        if (tid < MD)
            ch[(long)(b*TT + t)*CDIM + DD + tid] = __float2half(rv_s[tid]);
        if (tid < 260) {
            float hbase = Hif[(long)(b*TT + t)*IFACE + gcol];
            unsigned long long a0 = 0ull, a1 = 0ull, a2 = 0ull, a3 = 0ull;
            #pragma unroll
            for (int k = 0; k < 64; k += 4) {
                asm("fma.rn.f32x2 %0, %1, %2, %0;" : "+l"(a0) : "l"(rv2[k  ]), "l"(w2[k  ]));
                asm("fma.rn.f32x2 %0, %1, %2, %0;" : "+l"(a1) : "l"(rv2[k+1]), "l"(w2[k+1]));
                asm("fma.rn.f32x2 %0, %1, %2, %0;" : "+l"(a2) : "l"(rv2[k+2]), "l"(w2[k+2]));
                asm("fma.rn.f32x2 %0, %1, %2, %0;" : "+l"(a3) : "l"(rv2[k+3]), "l"(w2[k+3]));
            }
            float l0, h0, l1, h1, l2, h2, l3, h3;
            asm("mov.b64 {%0,%1}, %2;" : "=f"(l0), "=f"(h0) : "l"(a0));
            asm("mov.b64 {%0,%1}, %2;" : "=f"(l1), "=f"(h1) : "l"(a1));
            asm("mov.b64 {%0,%1}, %2;" : "=f"(l2), "=f"(h2) : "l"(a2));
            asm("mov.b64 {%0,%1}, %2;" : "=f"(l3), "=f"(h3) : "l"(a3));
            if_s[tid] = hbase + ((l0 + h0) + (l1 + h1)) + ((l2 + h2) + (l3 + h3));
        }
        __syncthreads();
        if (tid < MD) {
            int hh = tid >> 5;
            int d  = tid & 31;
            int base = hh*65;
            float wv = if_s[base + d];
            float er = 1.f / (1.f + __expf(-if_s[base + 32 + d]));
            float ag = 1.f / (1.f + __expf(-if_s[base + 64]));
            float mo = m_s[tid];
            rv_s[tid] = rv_s[tid] + mo;
            m_s[tid]  = mo * (1.f - er*(1.f/512.f)) + (ag*(1.f/512.f))*wv;
        }
        __syncthreads();
    }
}

// ---------------------------------------------------------------------------
// Launch
// ---------------------------------------------------------------------------
extern "C" void kernel_launch(void* const* d_in, const int* in_sizes, int n_in,
                              void* d_out, int out_size)
{
    const int*   seq   = (const int*)  d_in[0];
    const float* tok   = (const float*)d_in[1];
    const float* pos   = (const float*)d_in[2];
    const float* Wqkv  = (const float*)d_in[3];
    const float* Wo    = (const float*)d_in[4];
    const float* ln1g  = (const float*)d_in[5];
    const float* ln1b  = (const float*)d_in[6];
    const float* ln2g  = (const float*)d_in[7];
    const float* ln2b  = (const float*)d_in[8];
    const float* W1    = (const float*)d_in[9];
    const float* b1    = (const float*)d_in[10];
    const float* W2    = (const float*)d_in[11];
    const float* b2    = (const float*)d_in[12];
    const float* lnfg  = (const float*)d_in[13];
    const float* lnfb  = (const float*)d_in[14];
    const float* Wlog  = (const float*)d_in[15];
    const float* blog  = (const float*)d_in[16];
    const float* Wif   = (const float*)d_in[17];
    const float* bif   = (const float*)d_in[18];
    float* out = (float*)d_out;

    float *gx, *gqkv, *gatt, *gff, *gHif;
    __half* gch;
    cudaGetSymbolAddress((void**)&gx,   g_x);
    cudaGetSymbolAddress((void**)&gqkv, g_qkv);
    cudaGetSymbolAddress((void**)&gatt, g_att);
    cudaGetSymbolAddress((void**)&gff,  g_ff);
    cudaGetSymbolAddress((void**)&gHif, g_Hif);
    cudaGetSymbolAddress((void**)&gch,  g_ch);

    embed_kernel<<<BT, DD>>>(seq, tok, pos, gx);

    for (int l = 0; l < 2; l++) {
        tc_gemm<false, true><<<dim3(12, 8), 128>>>(
            3*DD, DD, gx, DD, Wqkv + (long)l*DD*3*DD, 3*DD,
            gqkv, 3*DD, nullptr, nullptr, ln1g + l*DD, ln1b + l*DD);
        attention_kernel<<<dim3(NH, BB, TT/QC), 128>>>(gqkv, gatt);
        tc_gemm<false, false><<<dim3(4, 8), 128>>>(
            DD, DD, gatt, DD, Wo + (long)l*DD*DD, DD,
            gx, DD, nullptr, gx, nullptr, nullptr);
        tc_gemm<true, true><<<dim3(16, 8), 128>>>(
            FF_, DD, gx, DD, W1 + (long)l*DD*FF_, FF_,
            gff, FF_, b1 + l*FF_, nullptr, ln2g + l*DD, ln2b + l*DD);
        tc_gemm<false, false><<<dim3(4, 8), 128>>>(
            DD, FF_, gff, FF_, W2 + (long)l*FF_*DD, DD,
            gx, DD, b2 + l*DD, gx, nullptr, nullptr);
    }

    tc_gemm<false, true><<<dim3((IFACE + 63)/64, 8), 128>>>(
        IFACE, DD, gx, DD, Wif, IFACE, gHif, IFACE, bif, nullptr, lnfg, lnfb);

    lnf_half_kernel<<<BT, DD>>>(gx, lnfg, lnfb, gch);

    scan_kernel<<<BB, 320>>>(gHif, Wif, gch);

    logits_f16_kernel<<<dim3(4, VOCAB/128), 256>>>(gch, Wlog, out, blog);
}

// round 12
// speedup vs baseline: 2.8528x; 1.0418x over previous
#include <cuda_runtime.h>
#include <cuda_bf16.h>
#include <cuda_fp16.h>
#include <math.h>
#include <cstdint>

// ---------------------------------------------------------------------------
// Problem constants
// ---------------------------------------------------------------------------
#define BB 4
#define TT 128
#define DD 256
#define FF_ 1024
#define NH 8
#define HD_ATT 32
#define VOCAB 32000
#define MD 128
#define IFACE 516       // MH*(4*HD+1)
#define CDIM 384        // D + MD
#define BT (BB*TT)      // 512

// ---------------------------------------------------------------------------
// Scratch (device globals; no allocation allowed)
// ---------------------------------------------------------------------------
__device__ float g_x  [BT*DD];
__device__ float g_qkv[BT*3*DD];
__device__ float g_att[BT*DD];
__device__ float g_ff [BT*FF_];
__device__ float g_Hif[BT*IFACE];
__device__ __align__(16) __half g_ch[BT*CDIM];   // concat [lnf(x) | rv] in fp16

// ---------------------------------------------------------------------------
// Embedding
// ---------------------------------------------------------------------------
__global__ void embed_kernel(const int* __restrict__ seq,
                             const float* __restrict__ tok,
                             const float* __restrict__ pos,
                             float* __restrict__ x)
{
    int bt = blockIdx.x;
    int d  = threadIdx.x;
    int t  = bt & (TT-1);
    x[bt*DD + d] = tok[(long)seq[bt]*DD + d] + pos[t*DD + d];
}

// ---------------------------------------------------------------------------
// Final LayerNorm -> fp16 into g_ch left half (stride CDIM)
// ---------------------------------------------------------------------------
__global__ void lnf_half_kernel(const float* __restrict__ x,
                                const float* __restrict__ g,
                                const float* __restrict__ b,
                                __half* __restrict__ ch)
{
    int row = blockIdx.x;
    int tid = threadIdx.x;
    __shared__ float red[8];
    float v = x[row*DD + tid];
    float s = v;
    #pragma unroll
    for (int k = 16; k; k >>= 1) s += __shfl_xor_sync(0xffffffffu, s, k);
    if ((tid & 31) == 0) red[tid >> 5] = s;
    __syncthreads();
    float mean = 0.f;
    #pragma unroll
    for (int i = 0; i < 8; i++) mean += red[i];
    mean *= (1.f/256.f);
    __syncthreads();
    float d = v - mean;
    float s2 = d*d;
    #pragma unroll
    for (int k = 16; k; k >>= 1) s2 += __shfl_xor_sync(0xffffffffu, s2, k);
    if ((tid & 31) == 0) red[tid >> 5] = s2;
    __syncthreads();
    float var = 0.f;
    #pragma unroll
    for (int i = 0; i < 8; i++) var += red[i];
    var *= (1.f/256.f);
    ch[row*CDIM + tid] = __float2half(d * rsqrtf(var + 1e-5f) * g[tid] + b[tid]);
}

// ---------------------------------------------------------------------------
// TF32 / cp.async helpers
// ---------------------------------------------------------------------------
__device__ __forceinline__ unsigned f2tf32(float x) {
    unsigned r;
    asm("cvt.rna.tf32.f32 %0, %1;" : "=r"(r) : "f"(x));
    return r;
}
__device__ __forceinline__ void mma_tf32(float* c, const unsigned* a, const unsigned* b) {
    asm volatile(
        "mma.sync.aligned.m16n8k8.row.col.f32.tf32.tf32.f32 "
        "{%0,%1,%2,%3}, {%4,%5,%6,%7}, {%8,%9}, {%0,%1,%2,%3};"
        : "+f"(c[0]), "+f"(c[1]), "+f"(c[2]), "+f"(c[3])
        : "r"(a[0]), "r"(a[1]), "r"(a[2]), "r"(a[3]),
          "r"(b[0]), "r"(b[1]));
}
__device__ __forceinline__ uint32_t smem_u32(const void* p) {
    uint32_t a;
    asm("{ .reg .u64 t; cvta.to.shared.u64 t, %1; cvt.u32.u64 %0, t; }" : "=r"(a) : "l"(p));
    return a;
}
__device__ __forceinline__ void cp_async16(uint32_t saddr, const void* gptr) {
    asm volatile("cp.async.cg.shared.global [%0], [%1], 16;" :: "r"(saddr), "l"(gptr));
}
__device__ __forceinline__ void cp_commit() {
    asm volatile("cp.async.commit_group;" ::: "memory");
}
__device__ __forceinline__ void cp_wait1() {
    asm volatile("cp.async.wait_group 1;" ::: "memory");
}
__device__ __forceinline__ void cp_wait0() {
    asm volatile("cp.async.wait_group 0;" ::: "memory");
}

// ---------------------------------------------------------------------------
// FP16 mma helpers (logits GEMM)
// ---------------------------------------------------------------------------
__device__ __forceinline__ void ldsm_x4(unsigned* r, uint32_t addr) {
    asm volatile("ldmatrix.sync.aligned.m8n8.x4.shared.b16 {%0,%1,%2,%3}, [%4];"
        : "=r"(r[0]), "=r"(r[1]), "=r"(r[2]), "=r"(r[3]) : "r"(addr));
}
__device__ __forceinline__ void ldsm_x4_t(unsigned* r, uint32_t addr) {
    asm volatile("ldmatrix.sync.aligned.m8n8.x4.trans.shared.b16 {%0,%1,%2,%3}, [%4];"
        : "=r"(r[0]), "=r"(r[1]), "=r"(r[2]), "=r"(r[3]) : "r"(addr));
}
__device__ __forceinline__ void mma_f16(float* c, const unsigned* a, unsigned b0, unsigned b1) {
    asm volatile(
        "mma.sync.aligned.m16n8k16.row.col.f32.f16.f16.f32 "
        "{%0,%1,%2,%3}, {%4,%5,%6,%7}, {%8,%9}, {%0,%1,%2,%3};"
        : "+f"(c[0]), "+f"(c[1]), "+f"(c[2]), "+f"(c[3])
        : "r"(a[0]), "r"(a[1]), "r"(a[2]), "r"(a[3]),
          "r"(b0), "r"(b1));
}

// ---------------------------------------------------------------------------
// FP16 logits GEMM (unchanged): C[512,32000]=A_h[512,384]@B + bias
// ---------------------------------------------------------------------------
__global__ __launch_bounds__(256, 2) void logits_f16_kernel(
    const __half* __restrict__ A,
    const float* __restrict__ B,
    float* __restrict__ C,
    const float* __restrict__ bias)
{
    __shared__ __half Ah[2][128][40];
    __shared__ __half Bh[2][32][136];

    const int tid  = threadIdx.x;
    const int lane = tid & 31;
    const int wid  = tid >> 5;
    const int wm   = (wid >> 2) * 64;
    const int wn   = (wid & 3) * 32;
    const int m0   = blockIdx.x * 128;   // m fastest
    const int n0   = blockIdx.y * 128;

    const int ar = tid >> 2;
    const int ac = (tid & 3) << 3;

    float acc[16][4];
    #pragma unroll
    for (int i = 0; i < 16; i++)
        #pragma unroll
        for (int j = 0; j < 4; j++) acc[i][j] = 0.f;

    #pragma unroll
    for (int i = 0; i < 2; i++) {
        uint4 v = *reinterpret_cast<const uint4*>(A + (long)(m0 + ar + i*64)*CDIM + ac);
        *reinterpret_cast<uint4*>(&Ah[0][ar + i*64][ac]) = v;
    }
    #pragma unroll
    for (int p = 0; p < 4; p++) {
        int q = p*256 + tid;
        int r = q >> 5, c4 = (q & 31) << 2;
        float4 v = *reinterpret_cast<const float4*>(B + (long)r*VOCAB + n0 + c4);
        __half2 h0 = __floats2half2_rn(v.x, v.y);
        __half2 h1 = __floats2half2_rn(v.z, v.w);
        uint2 u;
        u.x = *reinterpret_cast<unsigned*>(&h0);
        u.y = *reinterpret_cast<unsigned*>(&h1);
        *reinterpret_cast<uint2*>(&Bh[0][r][c4]) = u;
    }
    __syncthreads();

    int buf = 0;
    #pragma unroll 1
    for (int kt = 0; kt < CDIM/32; kt++) {
        const bool more = (kt + 1) < CDIM/32;
        uint4 pa[2];
        float4 pb[4];
        if (more) {
            const int k0 = (kt + 1) * 32;
            #pragma unroll
            for (int i = 0; i < 2; i++)
                pa[i] = *reinterpret_cast<const uint4*>(A + (long)(m0 + ar + i*64)*CDIM + k0 + ac);
            #pragma unroll
            for (int p = 0; p < 4; p++) {
                int q = p*256 + tid;
                pb[p] = *reinterpret_cast<const float4*>(
                    B + (long)(k0 + (q >> 5))*VOCAB + n0 + ((q & 31) << 2));
            }
        }

        #pragma unroll
        for (int ks = 0; ks < 32; ks += 16) {
            unsigned af[4][4], bf[2][4];
            #pragma unroll
            for (int mt = 0; mt < 4; mt++) {
                int row = wm + mt*16 + (lane & 15);
                int col = ks + ((lane & 16) >> 1);
                ldsm_x4(af[mt], smem_u32(&Ah[buf][row][col]));
            }
            #pragma unroll
            for (int pr = 0; pr < 2; pr++) {
                int row = ks + (lane & 15);
                int col = wn + pr*16 + ((lane & 16) >> 1);
                ldsm_x4_t(bf[pr], smem_u32(&Bh[buf][row][col]));
            }
            #pragma unroll
            for (int mt = 0; mt < 4; mt++)
                #pragma unroll
                for (int nt = 0; nt < 4; nt++)
                    mma_f16(acc[mt*4 + nt], af[mt],
                            bf[nt >> 1][(nt & 1)*2], bf[nt >> 1][(nt & 1)*2 + 1]);
        }

        if (more) {
            #pragma unroll
            for (int i = 0; i < 2; i++)
                *reinterpret_cast<uint4*>(&Ah[buf^1][ar + i*64][ac]) = pa[i];
            #pragma unroll
            for (int p = 0; p < 4; p++) {
                int q = p*256 + tid;
                int r = q >> 5, c4 = (q & 31) << 2;
                __half2 h0 = __floats2half2_rn(pb[p].x, pb[p].y);
                __half2 h1 = __floats2half2_rn(pb[p].z, pb[p].w);
                uint2 u;
                u.x = *reinterpret_cast<unsigned*>(&h0);
                u.y = *reinterpret_cast<unsigned*>(&h1);
                *reinterpret_cast<uint2*>(&Bh[buf^1][r][c4]) = u;
            }
        }
        __syncthreads();
        buf ^= 1;
    }

    const int g  = lane >> 2;
    const int tg = lane & 3;
    #pragma unroll
    for (int nt = 0; nt < 4; nt++) {
        int n = n0 + wn + nt*8 + 2*tg;
        float2 bz = *reinterpret_cast<const float2*>(bias + n);
        #pragma unroll
        for (int mt = 0; mt < 4; mt++) {
            int m = m0 + wm + mt*16 + g;
            float* c = acc[mt*4 + nt];
            *reinterpret_cast<float2*>(C + (long)m*VOCAB + n)     = make_float2(c[0]+bz.x, c[1]+bz.y);
            *reinterpret_cast<float2*>(C + (long)(m+8)*VOCAB + n) = make_float2(c[2]+bz.x, c[3]+bz.y);
        }
    }
}

// ---------------------------------------------------------------------------
// TF32 small GEMM, 2-stage cp.async pipeline, optional fused LayerNorm on A.
// 64x64 tile, BK=32, 4 warps.  (QKV / FF1 / iface — grids >= 72 blocks.)
// ---------------------------------------------------------------------------
template<bool GELU, bool LN>
__global__ __launch_bounds__(128) void tc_gemm(
    int N, int K,
    const float* __restrict__ A, int lda,
    const float* __restrict__ B, int ldb,
    float* __restrict__ C, int ldc,
    const float* __restrict__ bias,
    const float* __restrict__ residual,
    const float* __restrict__ ln_g,
    const float* __restrict__ ln_b)
{
    __shared__ float As[2][64][36];
    __shared__ float Bs[2][32][68];
    __shared__ float smean[64];
    __shared__ float srstd[64];
    __shared__ float sg[256];
    __shared__ float sb[256];

    const int tid  = threadIdx.x;
    const int lane = tid & 31;
    const int wid  = tid >> 5;
    const int wm   = (wid >> 1) * 32;
    const int wn   = (wid & 1) * 32;
    const int m0   = blockIdx.y * 64;
    const int n0   = blockIdx.x * 64;
    const int g    = lane >> 2;
    const int tg   = lane & 3;
    const int nt   = K >> 5;

    const uint32_t asBase = smem_u32(&As[0][0][0]);
    const uint32_t bsBase = smem_u32(&Bs[0][0][0]);

    const int a_r  = tid >> 3;
    const int a_c4 = (tid & 7) << 2;
    const int b_r  = tid >> 4;
    const int b_c4 = (tid & 15) << 2;

    auto fill = [&](int s, int k0) {
        #pragma unroll
        for (int i = 0; i < 4; i++) {
            int r = a_r + i*16;
            cp_async16(asBase + (uint32_t)(((s*64 + r)*36 + a_c4) << 2),
                       A + (long)(m0 + r)*lda + k0 + a_c4);
        }
        #pragma unroll
        for (int i = 0; i < 4; i++) {
            int r = b_r + i*8;
            if (n0 + b_c4 < N) {
                cp_async16(bsBase + (uint32_t)(((s*32 + r)*68 + b_c4) << 2),
                           B + (long)(k0 + r)*ldb + n0 + b_c4);
            } else {
                *reinterpret_cast<float4*>(&Bs[s][r][b_c4]) = make_float4(0.f,0.f,0.f,0.f);
            }
        }
        cp_commit();
    };

    fill(0, 0);

    if (LN) {
        int r  = tid >> 1;
        int hf = tid & 1;
        const float* rowp = A + (long)(m0 + r)*lda;
        float s = 0.f, s2 = 0.f;
        for (int i = hf*4; i < K; i += 8) {
            float4 u = *reinterpret_cast<const float4*>(rowp + i);
            s  += u.x + u.y + u.z + u.w;
            s2 += u.x*u.x + u.y*u.y + u.z*u.z + u.w*u.w;
        }
        s  += __shfl_xor_sync(0xffffffffu, s, 1);
        s2 += __shfl_xor_sync(0xffffffffu, s2, 1);
        if (!hf) {
            float inv = 1.f / (float)K;
            float mu  = s * inv;
            float var = s2 * inv - mu*mu;
            smean[r] = mu;
            srstd[r] = rsqrtf(var + 1e-5f);
        }
        if (tid < 64) {
            *reinterpret_cast<float4*>(&sg[tid*4]) = *reinterpret_cast<const float4*>(ln_g + tid*4);
        } else {
            int t = tid - 64;
            *reinterpret_cast<float4*>(&sb[t*4]) = *reinterpret_cast<const float4*>(ln_b + t*4);
        }
        __syncthreads();
    }

    float rs_[4], mrs_[4];
    if (LN) {
        #pragma unroll
        for (int q = 0; q < 4; q++) {
            int r = wm + q*8 + g;
            rs_[q]  = srstd[r];
            mrs_[q] = smean[r] * rs_[q];
        }
    }

    float acc[8][4];
    #pragma unroll
    for (int i = 0; i < 8; i++)
        #pragma unroll
        for (int j = 0; j < 4; j++) acc[i][j] = 0.f;

    #pragma unroll 1
    for (int kt = 0; kt < nt; kt++) {
        const bool more = (kt + 1) < nt;
        if (more) fill((kt + 1) & 1, (kt + 1) * 32);
        if (more) cp_wait1(); else cp_wait0();
        __syncthreads();

        const int buf = kt & 1;
        const int k0  = kt * 32;

        #pragma unroll
        for (int ks = 0; ks < 32; ks += 8) {
            unsigned af[2][4], bf[4][2];
            float gm0 = 0.f, gm4 = 0.f, bt0 = 0.f, bt4 = 0.f;
            if (LN) {
                gm0 = sg[k0 + ks + tg];   gm4 = sg[k0 + ks + tg + 4];
                bt0 = sb[k0 + ks + tg];   bt4 = sb[k0 + ks + tg + 4];
            }
            #pragma unroll
            for (int mt = 0; mt < 2; mt++) {
                int mr = wm + mt*16 + g;
                float r00 = As[buf][mr  ][ks + tg    ];
                float r10 = As[buf][mr+8][ks + tg    ];
                float r04 = As[buf][mr  ][ks + tg + 4];
                float r14 = As[buf][mr+8][ks + tg + 4];
                if (LN) {
                    float rsa = rs_[mt*2],   ma = mrs_[mt*2];
                    float rsb = rs_[mt*2+1], mb = mrs_[mt*2+1];
                    r00 = fmaf(fmaf(r00, rsa, -ma), gm0, bt0);
                    r10 = fmaf(fmaf(r10, rsb, -mb), gm0, bt0);
                    r04 = fmaf(fmaf(r04, rsa, -ma), gm4, bt4);
                    r14 = fmaf(fmaf(r14, rsb, -mb), gm4, bt4);
                }
                af[mt][0] = f2tf32(r00);
                af[mt][1] = f2tf32(r10);
                af[mt][2] = f2tf32(r04);
                af[mt][3] = f2tf32(r14);
            }
            #pragma unroll
            for (int nt2 = 0; nt2 < 4; nt2++) {
                int nc = wn + nt2*8 + g;
                bf[nt2][0] = f2tf32(Bs[buf][ks + tg    ][nc]);
                bf[nt2][1] = f2tf32(Bs[buf][ks + tg + 4][nc]);
            }
            #pragma unroll
            for (int mt = 0; mt < 2; mt++)
                #pragma unroll
                for (int nt2 = 0; nt2 < 4; nt2++)
                    mma_tf32(acc[mt*4 + nt2], af[mt], bf[nt2]);
        }
        __syncthreads();
    }

    #pragma unroll
    for (int nt2 = 0; nt2 < 4; nt2++) {
        int n = n0 + wn + nt2*8 + 2*tg;
        if (n < N) {
            float2 bz = make_float2(0.f, 0.f);
            if (bias) bz = *reinterpret_cast<const float2*>(bias + n);
            #pragma unroll
            for (int mt = 0; mt < 2; mt++) {
                int m = m0 + wm + mt*16 + g;
                float* c = acc[mt*4 + nt2];
                float v[4] = {c[0]+bz.x, c[1]+bz.y, c[2]+bz.x, c[3]+bz.y};
                if (GELU) {
                    #pragma unroll
                    for (int q = 0; q < 4; q++) {
                        float u = v[q];
                        float tt = 0.7978845608028654f * (u + 0.044715f*u*u*u);
                        v[q] = 0.5f*u*(1.f + tanhf(tt));
                    }
                }
                if (residual) {
                    float2 r0 = *reinterpret_cast<const float2*>(residual + (long)m*ldc + n);
                    float2 r1 = *reinterpret_cast<const float2*>(residual + (long)(m+8)*ldc + n);
                    v[0] += r0.x; v[1] += r0.y; v[2] += r1.x; v[3] += r1.y;
                }
                *reinterpret_cast<float2*>(C + (long)m*ldc + n)     = make_float2(v[0], v[1]);
                *reinterpret_cast<float2*>(C + (long)(m+8)*ldc + n) = make_float2(v[2], v[3]);
            }
        }
    }
}

// ---------------------------------------------------------------------------
// TF32 tiny-tile GEMM for the grid-starved projections (Wo, FF2):
// 32x32 tile, BK=32, 4 warps (2x2), warp tile 16x16, 2-stage cp.async.
// Grid (N/32, M/32) = 128 blocks -> nearly all SMs busy.
// Requires N % 32 == 0, K % 32 == 0 (Wo: N=256,K=256; FF2: N=256,K=1024).
// C += bias? + residual (residual may alias C; read-before-write per thread).
// ---------------------------------------------------------------------------
__global__ __launch_bounds__(128) void tc_gemm_small(
    int N, int K,
    const float* __restrict__ A, int lda,
    const float* __restrict__ B, int ldb,
    float* __restrict__ C, int ldc,
    const float* __restrict__ bias,
    const float* __restrict__ residual)
{
    __shared__ float As[2][32][36];
    __shared__ float Bs[2][32][36];

    const int tid  = threadIdx.x;
    const int lane = tid & 31;
    const int wid  = tid >> 5;
    const int wm   = (wid >> 1) * 16;
    const int wn   = (wid & 1) * 16;
    const int m0   = blockIdx.y * 32;
    const int n0   = blockIdx.x * 32;
    const int g    = lane >> 2;
    const int tg   = lane & 3;
    const int nt   = K >> 5;

    const uint32_t asBase = smem_u32(&As[0][0][0]);
    const uint32_t bsBase = smem_u32(&Bs[0][0][0]);
    const int r_  = tid >> 3;             // 0..15
    const int c4  = (tid & 7) << 2;       // 0..28

    auto fill = [&](int s, int k0) {
        #pragma unroll
        for (int i = 0; i < 2; i++) {
            int r = r_ + i*16;
            cp_async16(asBase + (uint32_t)(((s*32 + r)*36 + c4) << 2),
                       A + (long)(m0 + r)*lda + k0 + c4);
            cp_async16(bsBase + (uint32_t)(((s*32 + r)*36 + c4) << 2),
                       B + (long)(k0 + r)*ldb + n0 + c4);
        }
        cp_commit();
    };

    fill(0, 0);

    float acc[2][4];
    #pragma unroll
    for (int i = 0; i < 2; i++)
        #pragma unroll
        for (int j = 0; j < 4; j++) acc[i][j] = 0.f;

    #pragma unroll 1
    for (int kt = 0; kt < nt; kt++) {
        const bool more = (kt + 1) < nt;
        if (more) fill((kt + 1) & 1, (kt + 1) * 32);
        if (more) cp_wait1(); else cp_wait0();
        __syncthreads();

        const int buf = kt & 1;
        #pragma unroll
        for (int ks = 0; ks < 32; ks += 8) {
            unsigned af[4], bf[2][2];
            af[0] = f2tf32(As[buf][wm + g    ][ks + tg    ]);
            af[1] = f2tf32(As[buf][wm + g + 8][ks + tg    ]);
            af[2] = f2tf32(As[buf][wm + g    ][ks + tg + 4]);
            af[3] = f2tf32(As[buf][wm + g + 8][ks + tg + 4]);
            #pragma unroll
            for (int nt2 = 0; nt2 < 2; nt2++) {
                int nc = wn + nt2*8 + g;
                bf[nt2][0] = f2tf32(Bs[buf][ks + tg    ][nc]);
                bf[nt2][1] = f2tf32(Bs[buf][ks + tg + 4][nc]);
            }
            #pragma unroll
            for (int nt2 = 0; nt2 < 2; nt2++)
                mma_tf32(acc[nt2], af, bf[nt2]);
        }
        __syncthreads();
    }

    #pragma unroll
    for (int nt2 = 0; nt2 < 2; nt2++) {
        int n = n0 + wn + nt2*8 + 2*tg;
        float2 bz = make_float2(0.f, 0.f);
        if (bias) bz = *reinterpret_cast<const float2*>(bias + n);
        int m = m0 + wm + g;
        float* c = acc[nt2];
        float v[4] = {c[0]+bz.x, c[1]+bz.y, c[2]+bz.x, c[3]+bz.y};
        if (residual) {
            float2 r0 = *reinterpret_cast<const float2*>(residual + (long)m*ldc + n);
            float2 r1 = *reinterpret_cast<const float2*>(residual + (long)(m+8)*ldc + n);
            v[0] += r0.x; v[1] += r0.y; v[2] += r1.x; v[3] += r1.y;
        }
        *reinterpret_cast<float2*>(C + (long)m*ldc + n)     = make_float2(v[0], v[1]);
        *reinterpret_cast<float2*>(C + (long)(m+8)*ldc + n) = make_float2(v[2], v[3]);
    }
}

// ---------------------------------------------------------------------------
// Causal attention: block = (head, batch, q-chunk of 8). 512 blocks total.
// 128 threads: q = tid>>4 (0..7), j = tid&15 (16 lanes per query).
// ---------------------------------------------------------------------------
#define QC 8
__global__ __launch_bounds__(128) void attention_kernel(
    const float* __restrict__ qkv, float* __restrict__ att_out)
{
    __shared__ float Ks[TT][36];
    __shared__ float Vs[TT][32];
    __shared__ float Ps[QC][129];
    const int h  = blockIdx.x;
    const int b  = blockIdx.y;
    const int qc = blockIdx.z;
    const int tid = threadIdx.x;
    const float scale = 0.17677669529663687f;

    {
        const float* kp = qkv + (long)(b*TT + tid)*(3*DD) + DD + h*HD_ATT;
        const float* vp = kp + DD;
        #pragma unroll
        for (int d = 0; d < 32; d += 4) {
            *reinterpret_cast<float4*>(&Ks[tid][d]) = *reinterpret_cast<const float4*>(kp + d);
            *reinterpret_cast<float4*>(&Vs[tid][d]) = *reinterpret_cast<const float4*>(vp + d);
        }
    }
    __syncthreads();

    const int q = tid >> 4;          // 0..7
    const int j = tid & 15;          // 0..15
    const int qglob = qc*QC + q;

    float qv[32];
    {
        const float* qp = qkv + (long)(b*TT + qglob)*(3*DD) + h*HD_ATT;
        #pragma unroll
        for (int d = 0; d < 32; d += 4) {
            float4 t = *reinterpret_cast<const float4*>(qp + d);
            qv[d]=t.x; qv[d+1]=t.y; qv[d+2]=t.z; qv[d+3]=t.w;
        }
    }

    float s[8];
    float mmax = -1e30f;
    #pragma unroll
    for (int kk = 0; kk < 8; kk++) {
        int k = kk*16 + j;
        float acc = 0.f;
        #pragma unroll
        for (int d = 0; d < 32; d += 4) {
            float4 kv = *reinterpret_cast<const float4*>(&Ks[k][d]);
            acc += qv[d]*kv.x + qv[d+1]*kv.y + qv[d+2]*kv.z + qv[d+3]*kv.w;
        }
        s[kk] = (k <= qglob) ? acc*scale : -1e30f;
        mmax = fmaxf(mmax, s[kk]);
    }
    #pragma unroll
    for (int o = 1; o < 16; o <<= 1)
        mmax = fmaxf(mmax, __shfl_xor_sync(0xffffffffu, mmax, o));

    float l = 0.f;
    #pragma unroll
    for (int kk = 0; kk < 8; kk++) {
        float p = __expf(s[kk] - mmax);
        l += p;
        Ps[q][kk*16 + j] = p;
    }
    #pragma unroll
    for (int o = 1; o < 16; o <<= 1)
        l += __shfl_xor_sync(0xffffffffu, l, o);
    float linv = 1.f / l;
    __syncthreads();

    // output dims j*2, j*2+1
    float ox = 0.f, oy = 0.f;
    #pragma unroll 4
    for (int k = 0; k < TT; k++) {
        float p = Ps[q][k];
        float2 v = *reinterpret_cast<const float2*>(&Vs[k][j*2]);
        ox += p*v.x; oy += p*v.y;
    }
    float2 o2 = make_float2(ox*linv, oy*linv);
    *reinterpret_cast<float2*>(att_out + (long)(b*TT + qglob)*DD + h*HD_ATT + j*2) = o2;
}

// ---------------------------------------------------------------------------
// Memory scan (collapsed; see derivation R2).  fma.rn.f32x2 GEMV, 4 accs.
// ---------------------------------------------------------------------------
__global__ __launch_bounds__(320) void scan_kernel(
    const float* __restrict__ Hif,
    const float* __restrict__ W_iface,
    __half* __restrict__ ch)
{
    int b   = blockIdx.x;
    int tid = threadIdx.x;
    __shared__ __align__(16) float rv_s[MD];
    __shared__ float m_s[MD];
    __shared__ float if_s[260];

    unsigned long long w2[64];
    int gcol = 0;
    if (tid < 260) {
        gcol = (tid/65)*129 + 64 + (tid%65);
        #pragma unroll
        for (int k = 0; k < 64; k++) {
            float lo = W_iface[(long)(256 + 2*k    )*IFACE + gcol];
            float hi = W_iface[(long)(256 + 2*k + 1)*IFACE + gcol];
            asm("mov.b64 %0, {%1,%2};" : "=l"(w2[k]) : "f"(lo), "f"(hi));
        }
    }
    if (tid < MD) { rv_s[tid] = 0.f; m_s[tid] = 0.f; }
    __syncthreads();

    const unsigned long long* rv2 = reinterpret_cast<const unsigned long long*>(rv_s);

    for (int t = 0; t < TT; t++) {
        if (tid < MD)
            ch[(long)(b*TT + t)*CDIM + DD + tid] = __float2half(rv_s[tid]);
        if (tid < 260) {
            float hbase = Hif[(long)(b*TT + t)*IFACE + gcol];
            unsigned long long a0 = 0ull, a1 = 0ull, a2 = 0ull, a3 = 0ull;
            #pragma unroll
            for (int k = 0; k < 64; k += 4) {
                asm("fma.rn.f32x2 %0, %1, %2, %0;" : "+l"(a0) : "l"(rv2[k  ]), "l"(w2[k  ]));
                asm("fma.rn.f32x2 %0, %1, %2, %0;" : "+l"(a1) : "l"(rv2[k+1]), "l"(w2[k+1]));
                asm("fma.rn.f32x2 %0, %1, %2, %0;" : "+l"(a2) : "l"(rv2[k+2]), "l"(w2[k+2]));
                asm("fma.rn.f32x2 %0, %1, %2, %0;" : "+l"(a3) : "l"(rv2[k+3]), "l"(w2[k+3]));
            }
            float l0, h0, l1, h1, l2, h2, l3, h3;
            asm("mov.b64 {%0,%1}, %2;" : "=f"(l0), "=f"(h0) : "l"(a0));
            asm("mov.b64 {%0,%1}, %2;" : "=f"(l1), "=f"(h1) : "l"(a1));
            asm("mov.b64 {%0,%1}, %2;" : "=f"(l2), "=f"(h2) : "l"(a2));
            asm("mov.b64 {%0,%1}, %2;" : "=f"(l3), "=f"(h3) : "l"(a3));
            if_s[tid] = hbase + ((l0 + h0) + (l1 + h1)) + ((l2 + h2) + (l3 + h3));
        }
        __syncthreads();
        if (tid < MD) {
            int hh = tid >> 5;
            int d  = tid & 31;
            int base = hh*65;
            float wv = if_s[base + d];
            float er = 1.f / (1.f + __expf(-if_s[base + 32 + d]));
            float ag = 1.f / (1.f + __expf(-if_s[base + 64]));
            float mo = m_s[tid];
            rv_s[tid] = rv_s[tid] + mo;
            m_s[tid]  = mo * (1.f - er*(1.f/512.f)) + (ag*(1.f/512.f))*wv;
        }
        __syncthreads();
    }
}

// ---------------------------------------------------------------------------
// Launch
// ---------------------------------------------------------------------------
extern "C" void kernel_launch(void* const* d_in, const int* in_sizes, int n_in,
                              void* d_out, int out_size)
{
    const int*   seq   = (const int*)  d_in[0];
    const float* tok   = (const float*)d_in[1];
    const float* pos   = (const float*)d_in[2];
    const float* Wqkv  = (const float*)d_in[3];
    const float* Wo    = (const float*)d_in[4];
    const float* ln1g  = (const float*)d_in[5];
    const float* ln1b  = (const float*)d_in[6];
    const float* ln2g  = (const float*)d_in[7];
    const float* ln2b  = (const float*)d_in[8];
    const float* W1    = (const float*)d_in[9];
    const float* b1    = (const float*)d_in[10];
    const float* W2    = (const float*)d_in[11];
    const float* b2    = (const float*)d_in[12];
    const float* lnfg  = (const float*)d_in[13];
    const float* lnfb  = (const float*)d_in[14];
    const float* Wlog  = (const float*)d_in[15];
    const float* blog  = (const float*)d_in[16];
    const float* Wif   = (const float*)d_in[17];
    const float* bif   = (const float*)d_in[18];
    float* out = (float*)d_out;

    float *gx, *gqkv, *gatt, *gff, *gHif;
    __half* gch;
    cudaGetSymbolAddress((void**)&gx,   g_x);
    cudaGetSymbolAddress((void**)&gqkv, g_qkv);
    cudaGetSymbolAddress((void**)&gatt, g_att);
    cudaGetSymbolAddress((void**)&gff,  g_ff);
    cudaGetSymbolAddress((void**)&gHif, g_Hif);
    cudaGetSymbolAddress((void**)&gch,  g_ch);

    embed_kernel<<<BT, DD>>>(seq, tok, pos, gx);

    for (int l = 0; l < 2; l++) {
        tc_gemm<false, true><<<dim3(12, 8), 128>>>(
            3*DD, DD, gx, DD, Wqkv + (long)l*DD*3*DD, 3*DD,
            gqkv, 3*DD, nullptr, nullptr, ln1g + l*DD, ln1b + l*DD);
        attention_kernel<<<dim3(NH, BB, TT/QC), 128>>>(gqkv, gatt);
        tc_gemm_small<<<dim3(8, 16), 128>>>(
            DD, DD, gatt, DD, Wo + (long)l*DD*DD, DD,
            gx, DD, nullptr, gx);
        tc_gemm<true, true><<<dim3(16, 8), 128>>>(
            FF_, DD, gx, DD, W1 + (long)l*DD*FF_, FF_,
            gff, FF_, b1 + l*FF_, nullptr, ln2g + l*DD, ln2b + l*DD);
        tc_gemm_small<<<dim3(8, 16), 128>>>(
            DD, FF_, gff, FF_, W2 + (long)l*FF_*DD, DD,
            gx, DD, b2 + l*DD, gx);
    }

    tc_gemm<false, true><<<dim3((IFACE + 63)/64, 8), 128>>>(
        IFACE, DD, gx, DD, Wif, IFACE, gHif, IFACE, bif, nullptr, lnfg, lnfb);

    lnf_half_kernel<<<BT, DD>>>(gx, lnfg, lnfb, gch);

    scan_kernel<<<BB, 320>>>(gHif, Wif, gch);

    logits_f16_kernel<<<dim3(4, VOCAB/128), 256>>>(gch, Wlog, out, blog);
}

// round 13
// speedup vs baseline: 2.9369x; 1.0295x over previous
#include <cuda_runtime.h>
#include <cuda_bf16.h>
#include <cuda_fp16.h>
#include <math.h>
#include <cstdint>

// ---------------------------------------------------------------------------
// Problem constants
// ---------------------------------------------------------------------------
#define BB 4
#define TT 128
#define DD 256
#define FF_ 1024
#define NH 8
#define HD_ATT 32
#define VOCAB 32000
#define MD 128
#define IFACE 516       // MH*(4*HD+1)
#define CDIM 384        // D + MD
#define BT (BB*TT)      // 512

// ---------------------------------------------------------------------------
// Scratch (device globals; no allocation allowed)
// ---------------------------------------------------------------------------
__device__ float g_x  [BT*DD];
__device__ float g_qkv[BT*3*DD];
__device__ float g_att[BT*DD];
__device__ float g_ff [BT*FF_];
__device__ float g_Hif[BT*IFACE];
__device__ __align__(16) __half g_ch[BT*CDIM];      // concat [lnf(x) | rv] fp16
__device__ __align__(16) __half g_wlh[CDIM*VOCAB];  // W_logits pre-converted fp16

// ---------------------------------------------------------------------------
// W_logits fp32 -> fp16 (one-time per launch; no deps, runs first)
// ---------------------------------------------------------------------------
__global__ void wconv_kernel(const float* __restrict__ W, __half* __restrict__ Wh)
{
    long i = ((long)blockIdx.x * 256 + threadIdx.x) * 4;
    float4 v = *reinterpret_cast<const float4*>(W + i);
    __half2 h0 = __floats2half2_rn(v.x, v.y);
    __half2 h1 = __floats2half2_rn(v.z, v.w);
    uint2 u;
    u.x = *reinterpret_cast<unsigned*>(&h0);
    u.y = *reinterpret_cast<unsigned*>(&h1);
    *reinterpret_cast<uint2*>(Wh + i) = u;
}

// ---------------------------------------------------------------------------
// Embedding
// ---------------------------------------------------------------------------
__global__ void embed_kernel(const int* __restrict__ seq,
                             const float* __restrict__ tok,
                             const float* __restrict__ pos,
                             float* __restrict__ x)
{
    int bt = blockIdx.x;
    int d  = threadIdx.x;
    int t  = bt & (TT-1);
    x[bt*DD + d] = tok[(long)seq[bt]*DD + d] + pos[t*DD + d];
}

// ---------------------------------------------------------------------------
// Final LayerNorm -> fp16 into g_ch left half (stride CDIM)
// ---------------------------------------------------------------------------
__global__ void lnf_half_kernel(const float* __restrict__ x,
                                const float* __restrict__ g,
                                const float* __restrict__ b,
                                __half* __restrict__ ch)
{
    int row = blockIdx.x;
    int tid = threadIdx.x;
    __shared__ float red[8];
    float v = x[row*DD + tid];
    float s = v;
    #pragma unroll
    for (int k = 16; k; k >>= 1) s += __shfl_xor_sync(0xffffffffu, s, k);
    if ((tid & 31) == 0) red[tid >> 5] = s;
    __syncthreads();
    float mean = 0.f;
    #pragma unroll
    for (int i = 0; i < 8; i++) mean += red[i];
    mean *= (1.f/256.f);
    __syncthreads();
    float d = v - mean;
    float s2 = d*d;
    #pragma unroll
    for (int k = 16; k; k >>= 1) s2 += __shfl_xor_sync(0xffffffffu, s2, k);
    if ((tid & 31) == 0) red[tid >> 5] = s2;
    __syncthreads();
    float var = 0.f;
    #pragma unroll
    for (int i = 0; i < 8; i++) var += red[i];
    var *= (1.f/256.f);
    ch[row*CDIM + tid] = __float2half(d * rsqrtf(var + 1e-5f) * g[tid] + b[tid]);
}

// ---------------------------------------------------------------------------
// TF32 / cp.async helpers
// ---------------------------------------------------------------------------
__device__ __forceinline__ unsigned f2tf32(float x) {
    unsigned r;
    asm("cvt.rna.tf32.f32 %0, %1;" : "=r"(r) : "f"(x));
    return r;
}
__device__ __forceinline__ void mma_tf32(float* c, const unsigned* a, const unsigned* b) {
    asm volatile(
        "mma.sync.aligned.m16n8k8.row.col.f32.tf32.tf32.f32 "
        "{%0,%1,%2,%3}, {%4,%5,%6,%7}, {%8,%9}, {%0,%1,%2,%3};"
        : "+f"(c[0]), "+f"(c[1]), "+f"(c[2]), "+f"(c[3])
        : "r"(a[0]), "r"(a[1]), "r"(a[2]), "r"(a[3]),
          "r"(b[0]), "r"(b[1]));
}
__device__ __forceinline__ uint32_t smem_u32(const void* p) {
    uint32_t a;
    asm("{ .reg .u64 t; cvta.to.shared.u64 t, %1; cvt.u32.u64 %0, t; }" : "=r"(a) : "l"(p));
    return a;
}
__device__ __forceinline__ void cp_async16(uint32_t saddr, const void* gptr) {
    asm volatile("cp.async.cg.shared.global [%0], [%1], 16;" :: "r"(saddr), "l"(gptr));
}
__device__ __forceinline__ void cp_commit() {
    asm volatile("cp.async.commit_group;" ::: "memory");
}
__device__ __forceinline__ void cp_wait3() {
    asm volatile("cp.async.wait_group 3;" ::: "memory");
}
__device__ __forceinline__ void cp_wait2() {
    asm volatile("cp.async.wait_group 2;" ::: "memory");
}
__device__ __forceinline__ void cp_wait1() {
    asm volatile("cp.async.wait_group 1;" ::: "memory");
}
__device__ __forceinline__ void cp_wait0() {
    asm volatile("cp.async.wait_group 0;" ::: "memory");
}
__device__ __forceinline__ void cp_wait_n(int n) {
    if (n >= 3) cp_wait3();
    else if (n == 2) cp_wait2();
    else if (n == 1) cp_wait1();
    else cp_wait0();
}

// ---------------------------------------------------------------------------
// FP16 mma helpers (logits GEMM)
// ---------------------------------------------------------------------------
__device__ __forceinline__ void ldsm_x4(unsigned* r, uint32_t addr) {
    asm volatile("ldmatrix.sync.aligned.m8n8.x4.shared.b16 {%0,%1,%2,%3}, [%4];"
        : "=r"(r[0]), "=r"(r[1]), "=r"(r[2]), "=r"(r[3]) : "r"(addr));
}
__device__ __forceinline__ void ldsm_x4_t(unsigned* r, uint32_t addr) {
    asm volatile("ldmatrix.sync.aligned.m8n8.x4.trans.shared.b16 {%0,%1,%2,%3}, [%4];"
        : "=r"(r[0]), "=r"(r[1]), "=r"(r[2]), "=r"(r[3]) : "r"(addr));
}
__device__ __forceinline__ void mma_f16(float* c, const unsigned* a, unsigned b0, unsigned b1) {
    asm volatile(
        "mma.sync.aligned.m16n8k16.row.col.f32.f16.f16.f32 "
        "{%0,%1,%2,%3}, {%4,%5,%6,%7}, {%8,%9}, {%0,%1,%2,%3};"
        : "+f"(c[0]), "+f"(c[1]), "+f"(c[2]), "+f"(c[3])
        : "r"(a[0]), "r"(a[1]), "r"(a[2]), "r"(a[3]),
          "r"(b0), "r"(b1));
}

// ---------------------------------------------------------------------------
// FP16 logits GEMM, cp.async 2-stage: C[512,32000] = A_h @ Wh + bias
// Both operands already fp16 in global; no in-loop conversion.
// ---------------------------------------------------------------------------
__global__ __launch_bounds__(256, 2) void logits_f16_kernel(
    const __half* __restrict__ A,
    const __half* __restrict__ Bh_g,
    float* __restrict__ C,
    const float* __restrict__ bias)
{
    __shared__ __half Ah[2][128][40];
    __shared__ __half Bh[2][32][136];

    const int tid  = threadIdx.x;
    const int lane = tid & 31;
    const int wid  = tid >> 5;
    const int wm   = (wid >> 2) * 64;
    const int wn   = (wid & 3) * 32;
    const int m0   = blockIdx.x * 128;   // m fastest: 4 m-blocks share B n-strip
    const int n0   = blockIdx.y * 128;

    const uint32_t ahBase = smem_u32(&Ah[0][0][0]);
    const uint32_t bhBase = smem_u32(&Bh[0][0][0]);

    // A tile: 128 rows x 32 halves = 512 x 16B chunks; 2 per thread
    // B tile: 32 rows x 128 halves = 512 x 16B chunks; 2 per thread
    auto fill = [&](int s, int k0) {
        #pragma unroll
        for (int i = 0; i < 2; i++) {
            int id = i*256 + tid;
            int r  = id >> 2;
            int c  = (id & 3) << 3;
            cp_async16(ahBase + (uint32_t)(((s*128 + r)*40 + c) << 1),
                       A + (long)(m0 + r)*CDIM + k0 + c);
        }
        #pragma unroll
        for (int i = 0; i < 2; i++) {
            int id = i*256 + tid;
            int r  = id >> 4;
            int c  = (id & 15) << 3;
            cp_async16(bhBase + (uint32_t)(((s*32 + r)*136 + c) << 1),
                       Bh_g + (long)(k0 + r)*VOCAB + n0 + c);
        }
        cp_commit();
    };

    float acc[16][4];
    #pragma unroll
    for (int i = 0; i < 16; i++)
        #pragma unroll
        for (int j = 0; j < 4; j++) acc[i][j] = 0.f;

    fill(0, 0);

    #pragma unroll 1
    for (int kt = 0; kt < CDIM/32; kt++) {
        const bool more = (kt + 1) < CDIM/32;
        if (more) fill((kt + 1) & 1, (kt + 1) * 32);
        if (more) cp_wait1(); else cp_wait0();
        __syncthreads();

        const int buf = kt & 1;
        #pragma unroll
        for (int ks = 0; ks < 32; ks += 16) {
            unsigned af[4][4], bf[2][4];
            #pragma unroll
            for (int mt = 0; mt < 4; mt++) {
                int row = wm + mt*16 + (lane & 15);
                int col = ks + ((lane & 16) >> 1);
                ldsm_x4(af[mt], smem_u32(&Ah[buf][row][col]));
            }
            #pragma unroll
            for (int pr = 0; pr < 2; pr++) {
                int row = ks + (lane & 15);
                int col = wn + pr*16 + ((lane & 16) >> 1);
                ldsm_x4_t(bf[pr], smem_u32(&Bh[buf][row][col]));
            }
            #pragma unroll
            for (int mt = 0; mt < 4; mt++)
                #pragma unroll
                for (int nt = 0; nt < 4; nt++)
                    mma_f16(acc[mt*4 + nt], af[mt],
                            bf[nt >> 1][(nt & 1)*2], bf[nt >> 1][(nt & 1)*2 + 1]);
        }
        __syncthreads();
    }

    const int g  = lane >> 2;
    const int tg = lane & 3;
    #pragma unroll
    for (int nt = 0; nt < 4; nt++) {
        int n = n0 + wn + nt*8 + 2*tg;
        float2 bz = *reinterpret_cast<const float2*>(bias + n);
        #pragma unroll
        for (int mt = 0; mt < 4; mt++) {
            int m = m0 + wm + mt*16 + g;
            float* c = acc[mt*4 + nt];
            *reinterpret_cast<float2*>(C + (long)m*VOCAB + n)     = make_float2(c[0]+bz.x, c[1]+bz.y);
            *reinterpret_cast<float2*>(C + (long)(m+8)*VOCAB + n) = make_float2(c[2]+bz.x, c[3]+bz.y);
        }
    }
}

// ---------------------------------------------------------------------------
// TF32 small GEMM, 2-stage cp.async pipeline, optional fused LayerNorm on A.
// 64x64 tile, BK=32, 4 warps.  (QKV / FF1 / iface — grids >= 72 blocks.)
// ---------------------------------------------------------------------------
template<bool GELU, bool LN>
__global__ __launch_bounds__(128) void tc_gemm(
    int N, int K,
    const float* __restrict__ A, int lda,
    const float* __restrict__ B, int ldb,
    float* __restrict__ C, int ldc,
    const float* __restrict__ bias,
    const float* __restrict__ residual,
    const float* __restrict__ ln_g,
    const float* __restrict__ ln_b)
{
    __shared__ float As[2][64][36];
    __shared__ float Bs[2][32][68];
    __shared__ float smean[64];
    __shared__ float srstd[64];
    __shared__ float sg[256];
    __shared__ float sb[256];

    const int tid  = threadIdx.x;
    const int lane = tid & 31;
    const int wid  = tid >> 5;
    const int wm   = (wid >> 1) * 32;
    const int wn   = (wid & 1) * 32;
    const int m0   = blockIdx.y * 64;
    const int n0   = blockIdx.x * 64;
    const int g    = lane >> 2;
    const int tg   = lane & 3;
    const int nt   = K >> 5;

    const uint32_t asBase = smem_u32(&As[0][0][0]);
    const uint32_t bsBase = smem_u32(&Bs[0][0][0]);

    const int a_r  = tid >> 3;
    const int a_c4 = (tid & 7) << 2;
    const int b_r  = tid >> 4;
    const int b_c4 = (tid & 15) << 2;

    auto fill = [&](int s, int k0) {
        #pragma unroll
        for (int i = 0; i < 4; i++) {
            int r = a_r + i*16;
            cp_async16(asBase + (uint32_t)(((s*64 + r)*36 + a_c4) << 2),
                       A + (long)(m0 + r)*lda + k0 + a_c4);
        }
        #pragma unroll
        for (int i = 0; i < 4; i++) {
            int r = b_r + i*8;
            if (n0 + b_c4 < N) {
                cp_async16(bsBase + (uint32_t)(((s*32 + r)*68 + b_c4) << 2),
                           B + (long)(k0 + r)*ldb + n0 + b_c4);
            } else {
                *reinterpret_cast<float4*>(&Bs[s][r][b_c4]) = make_float4(0.f,0.f,0.f,0.f);
            }
        }
        cp_commit();
    };

    fill(0, 0);

    if (LN) {
        int r  = tid >> 1;
        int hf = tid & 1;
        const float* rowp = A + (long)(m0 + r)*lda;
        float s = 0.f, s2 = 0.f;
        for (int i = hf*4; i < K; i += 8) {
            float4 u = *reinterpret_cast<const float4*>(rowp + i);
            s  += u.x + u.y + u.z + u.w;
            s2 += u.x*u.x + u.y*u.y + u.z*u.z + u.w*u.w;
        }
        s  += __shfl_xor_sync(0xffffffffu, s, 1);
        s2 += __shfl_xor_sync(0xffffffffu, s2, 1);
        if (!hf) {
            float inv = 1.f / (float)K;
            float mu  = s * inv;
            float var = s2 * inv - mu*mu;
            smean[r] = mu;
            srstd[r] = rsqrtf(var + 1e-5f);
        }
        if (tid < 64) {
            *reinterpret_cast<float4*>(&sg[tid*4]) = *reinterpret_cast<const float4*>(ln_g + tid*4);
        } else {
            int t = tid - 64;
            *reinterpret_cast<float4*>(&sb[t*4]) = *reinterpret_cast<const float4*>(ln_b + t*4);
        }
        __syncthreads();
    }

    float rs_[4], mrs_[4];
    if (LN) {
        #pragma unroll
        for (int q = 0; q < 4; q++) {
            int r = wm + q*8 + g;
            rs_[q]  = srstd[r];
            mrs_[q] = smean[r] * rs_[q];
        }
    }

    float acc[8][4];
    #pragma unroll
    for (int i = 0; i < 8; i++)
        #pragma unroll
        for (int j = 0; j < 4; j++) acc[i][j] = 0.f;

    #pragma unroll 1
    for (int kt = 0; kt < nt; kt++) {
        const bool more = (kt + 1) < nt;
        if (more) fill((kt + 1) & 1, (kt + 1) * 32);
        if (more) cp_wait1(); else cp_wait0();
        __syncthreads();

        const int buf = kt & 1;
        const int k0  = kt * 32;

        #pragma unroll
        for (int ks = 0; ks < 32; ks += 8) {
            unsigned af[2][4], bf[4][2];
            float gm0 = 0.f, gm4 = 0.f, bt0 = 0.f, bt4 = 0.f;
            if (LN) {
                gm0 = sg[k0 + ks + tg];   gm4 = sg[k0 + ks + tg + 4];
                bt0 = sb[k0 + ks + tg];   bt4 = sb[k0 + ks + tg + 4];
            }
            #pragma unroll
            for (int mt = 0; mt < 2; mt++) {
                int mr = wm + mt*16 + g;
                float r00 = As[buf][mr  ][ks + tg    ];
                float r10 = As[buf][mr+8][ks + tg    ];
                float r04 = As[buf][mr  ][ks + tg + 4];
                float r14 = As[buf][mr+8][ks + tg + 4];
                if (LN) {
                    float rsa = rs_[mt*2],   ma = mrs_[mt*2];
                    float rsb = rs_[mt*2+1], mb = mrs_[mt*2+1];
                    r00 = fmaf(fmaf(r00, rsa, -ma), gm0, bt0);
                    r10 = fmaf(fmaf(r10, rsb, -mb), gm0, bt0);
                    r04 = fmaf(fmaf(r04, rsa, -ma), gm4, bt4);
                    r14 = fmaf(fmaf(r14, rsb, -mb), gm4, bt4);
                }
                af[mt][0] = f2tf32(r00);
                af[mt][1] = f2tf32(r10);
                af[mt][2] = f2tf32(r04);
                af[mt][3] = f2tf32(r14);
            }
            #pragma unroll
            for (int nt2 = 0; nt2 < 4; nt2++) {
                int nc = wn + nt2*8 + g;
                bf[nt2][0] = f2tf32(Bs[buf][ks + tg    ][nc]);
                bf[nt2][1] = f2tf32(Bs[buf][ks + tg + 4][nc]);
            }
            #pragma unroll
            for (int mt = 0; mt < 2; mt++)
                #pragma unroll
                for (int nt2 = 0; nt2 < 4; nt2++)
                    mma_tf32(acc[mt*4 + nt2], af[mt], bf[nt2]);
        }
        __syncthreads();
    }

    #pragma unroll
    for (int nt2 = 0; nt2 < 4; nt2++) {
        int n = n0 + wn + nt2*8 + 2*tg;
        if (n < N) {
            float2 bz = make_float2(0.f, 0.f);
            if (bias) bz = *reinterpret_cast<const float2*>(bias + n);
            #pragma unroll
            for (int mt = 0; mt < 2; mt++) {
                int m = m0 + wm + mt*16 + g;
                float* c = acc[mt*4 + nt2];
                float v[4] = {c[0]+bz.x, c[1]+bz.y, c[2]+bz.x, c[3]+bz.y};
                if (GELU) {
                    #pragma unroll
                    for (int q = 0; q < 4; q++) {
                        float u = v[q];
                        float tt = 0.7978845608028654f * (u + 0.044715f*u*u*u);
                        v[q] = 0.5f*u*(1.f + tanhf(tt));
                    }
                }
                if (residual) {
                    float2 r0 = *reinterpret_cast<const float2*>(residual + (long)m*ldc + n);
                    float2 r1 = *reinterpret_cast<const float2*>(residual + (long)(m+8)*ldc + n);
                    v[0] += r0.x; v[1] += r0.y; v[2] += r1.x; v[3] += r1.y;
                }
                *reinterpret_cast<float2*>(C + (long)m*ldc + n)     = make_float2(v[0], v[1]);
                *reinterpret_cast<float2*>(C + (long)(m+8)*ldc + n) = make_float2(v[2], v[3]);
            }
        }
    }
}

// ---------------------------------------------------------------------------
// TF32 tiny-tile GEMM (Wo, FF2): 32x32 tile, BK=32, 4-stage cp.async.
// Grid (N/32, M/32) = 128 blocks.  N%32==0, K%32==0.
// ---------------------------------------------------------------------------
__global__ __launch_bounds__(128) void tc_gemm_small(
    int N, int K,
    const float* __restrict__ A, int lda,
    const float* __restrict__ B, int ldb,
    float* __restrict__ C, int ldc,
    const float* __restrict__ bias,
    const float* __restrict__ residual)
{
    __shared__ float As[4][32][36];
    __shared__ float Bs[4][32][36];

    const int tid  = threadIdx.x;
    const int lane = tid & 31;
    const int wid  = tid >> 5;
    const int wm   = (wid >> 1) * 16;
    const int wn   = (wid & 1) * 16;
    const int m0   = blockIdx.y * 32;
    const int n0   = blockIdx.x * 32;
    const int g    = lane >> 2;
    const int tg   = lane & 3;
    const int nt   = K >> 5;

    const uint32_t asBase = smem_u32(&As[0][0][0]);
    const uint32_t bsBase = smem_u32(&Bs[0][0][0]);
    const int r_  = tid >> 3;
    const int c4  = (tid & 7) << 2;

    auto fill = [&](int s, int k0) {
        #pragma unroll
        for (int i = 0; i < 2; i++) {
            int r = r_ + i*16;
            cp_async16(asBase + (uint32_t)(((s*32 + r)*36 + c4) << 2),
                       A + (long)(m0 + r)*lda + k0 + c4);
            cp_async16(bsBase + (uint32_t)(((s*32 + r)*36 + c4) << 2),
                       B + (long)(k0 + r)*ldb + n0 + c4);
        }
        cp_commit();
    };

    // prologue: fill up to 3 tiles ahead
    const int pre = (nt < 3) ? nt : 3;
    for (int s = 0; s < pre; s++) fill(s, s*32);

    float acc[2][4];
    #pragma unroll
    for (int i = 0; i < 2; i++)
        #pragma unroll
        for (int j = 0; j < 4; j++) acc[i][j] = 0.f;

    #pragma unroll 1
    for (int kt = 0; kt < nt; kt++) {
        if (kt + 3 < nt) fill((kt + 3) & 3, (kt + 3) * 32);
        int ahead = nt - 1 - kt;             // groups newer than kt
        cp_wait_n(ahead < 3 ? ahead : 3);
        __syncthreads();

        const int buf = kt & 3;
        #pragma unroll
        for (int ks = 0; ks < 32; ks += 8) {
            unsigned af[4], bf[2][2];
            af[0] = f2tf32(As[buf][wm + g    ][ks + tg    ]);
            af[1] = f2tf32(As[buf][wm + g + 8][ks + tg    ]);
            af[2] = f2tf32(As[buf][wm + g    ][ks + tg + 4]);
            af[3] = f2tf32(As[buf][wm + g + 8][ks + tg + 4]);
            #pragma unroll
            for (int nt2 = 0; nt2 < 2; nt2++) {
                int nc = wn + nt2*8 + g;
                bf[nt2][0] = f2tf32(Bs[buf][ks + tg    ][nc]);
                bf[nt2][1] = f2tf32(Bs[buf][ks + tg + 4][nc]);
            }
            #pragma unroll
            for (int nt2 = 0; nt2 < 2; nt2++)
                mma_tf32(acc[nt2], af, bf[nt2]);
        }
        __syncthreads();
    }

    #pragma unroll
    for (int nt2 = 0; nt2 < 2; nt2++) {
        int n = n0 + wn + nt2*8 + 2*tg;
        float2 bz = make_float2(0.f, 0.f);
        if (bias) bz = *reinterpret_cast<const float2*>(bias + n);
        int m = m0 + wm + g;
        float* c = acc[nt2];
        float v[4] = {c[0]+bz.x, c[1]+bz.y, c[2]+bz.x, c[3]+bz.y};
        if (residual) {
            float2 r0 = *reinterpret_cast<const float2*>(residual + (long)m*ldc + n);
            float2 r1 = *reinterpret_cast<const float2*>(residual + (long)(m+8)*ldc + n);
            v[0] += r0.x; v[1] += r0.y; v[2] += r1.x; v[3] += r1.y;
        }
        *reinterpret_cast<float2*>(C + (long)m*ldc + n)     = make_float2(v[0], v[1]);
        *reinterpret_cast<float2*>(C + (long)(m+8)*ldc + n) = make_float2(v[2], v[3]);
    }
}

// ---------------------------------------------------------------------------
// Causal attention: block = (head, batch, q-chunk of 8). 512 blocks total.
// ---------------------------------------------------------------------------
#define QC 8
__global__ __launch_bounds__(128) void attention_kernel(
    const float* __restrict__ qkv, float* __restrict__ att_out)
{
    __shared__ float Ks[TT][36];
    __shared__ float Vs[TT][32];
    __shared__ float Ps[QC][129];
    const int h  = blockIdx.x;
    const int b  = blockIdx.y;
    const int qc = blockIdx.z;
    const int tid = threadIdx.x;
    const float scale = 0.17677669529663687f;

    {
        const float* kp = qkv + (long)(b*TT + tid)*(3*DD) + DD + h*HD_ATT;
        const float* vp = kp + DD;
        #pragma unroll
        for (int d = 0; d < 32; d += 4) {
            *reinterpret_cast<float4*>(&Ks[tid][d]) = *reinterpret_cast<const float4*>(kp + d);
            *reinterpret_cast<float4*>(&Vs[tid][d]) = *reinterpret_cast<const float4*>(vp + d);
        }
    }
    __syncthreads();

    const int q = tid >> 4;
    const int j = tid & 15;
    const int qglob = qc*QC + q;

    float qv[32];
    {
        const float* qp = qkv + (long)(b*TT + qglob)*(3*DD) + h*HD_ATT;
        #pragma unroll
        for (int d = 0; d < 32; d += 4) {
            float4 t = *reinterpret_cast<const float4*>(qp + d);
            qv[d]=t.x; qv[d+1]=t.y; qv[d+2]=t.z; qv[d+3]=t.w;
        }
    }

    float s[8];
    float mmax = -1e30f;
    #pragma unroll
    for (int kk = 0; kk < 8; kk++) {
        int k = kk*16 + j;
        float acc = 0.f;
        #pragma unroll
        for (int d = 0; d < 32; d += 4) {
            float4 kv = *reinterpret_cast<const float4*>(&Ks[k][d]);
            acc += qv[d]*kv.x + qv[d+1]*kv.y + qv[d+2]*kv.z + qv[d+3]*kv.w;
        }
        s[kk] = (k <= qglob) ? acc*scale : -1e30f;
        mmax = fmaxf(mmax, s[kk]);
    }
    #pragma unroll
    for (int o = 1; o < 16; o <<= 1)
        mmax = fmaxf(mmax, __shfl_xor_sync(0xffffffffu, mmax, o));

    float l = 0.f;
    #pragma unroll
    for (int kk = 0; kk < 8; kk++) {
        float p = __expf(s[kk] - mmax);
        l += p;
        Ps[q][kk*16 + j] = p;
    }
    #pragma unroll
    for (int o = 1; o < 16; o <<= 1)
        l += __shfl_xor_sync(0xffffffffu, l, o);
    float linv = 1.f / l;
    __syncthreads();

    float ox = 0.f, oy = 0.f;
    #pragma unroll 4
    for (int k = 0; k < TT; k++) {
        float p = Ps[q][k];
        float2 v = *reinterpret_cast<const float2*>(&Vs[k][j*2]);
        ox += p*v.x; oy += p*v.y;
    }
    float2 o2 = make_float2(ox*linv, oy*linv);
    *reinterpret_cast<float2*>(att_out + (long)(b*TT + qglob)*DD + h*HD_ATT + j*2) = o2;
}

// ---------------------------------------------------------------------------
// Memory scan (collapsed; see derivation R2).  fma.rn.f32x2 GEMV, 4 accs.
// ---------------------------------------------------------------------------
__global__ __launch_bounds__(320) void scan_kernel(
    const float* __restrict__ Hif,
    const float* __restrict__ W_iface,
    __half* __restrict__ ch)
{
    int b   = blockIdx.x;
    int tid = threadIdx.x;
    __shared__ __align__(16) float rv_s[MD];
    __shared__ float m_s[MD];
    __shared__ float if_s[260];

    unsigned long long w2[64];
    int gcol = 0;
    if (tid < 260) {
        gcol = (tid/65)*129 + 64 + (tid%65);
        #pragma unroll
        for (int k = 0; k < 64; k++) {
            float lo = W_iface[(long)(256 + 2*k    )*IFACE + gcol];
            float hi = W_iface[(long)(256 + 2*k + 1)*IFACE + gcol];
            asm("mov.b64 %0, {%1,%2};" : "=l"(w2[k]) : "f"(lo), "f"(hi));
        }
    }
    if (tid < MD) { rv_s[tid] = 0.f; m_s[tid] = 0.f; }
    __syncthreads();

    const unsigned long long* rv2 = reinterpret_cast<const unsigned long long*>(rv_s);

    for (int t = 0; t < TT; t++) {
        if (tid < MD)
            ch[(long)(b*TT + t)*CDIM + DD + tid] = __float2half(rv_s[tid]);
        if (tid < 260) {
            float hbase = Hif[(long)(b*TT + t)*IFACE + gcol];
            unsigned long long a0 = 0ull, a1 = 0ull, a2 = 0ull, a3 = 0ull;
            #pragma unroll
            for (int k = 0; k < 64; k += 4) {
                asm("fma.rn.f32x2 %0, %1, %2, %0;" : "+l"(a0) : "l"(rv2[k  ]), "l"(w2[k  ]));
                asm("fma.rn.f32x2 %0, %1, %2, %0;" : "+l"(a1) : "l"(rv2[k+1]), "l"(w2[k+1]));
                asm("fma.rn.f32x2 %0, %1, %2, %0;" : "+l"(a2) : "l"(rv2[k+2]), "l"(w2[k+2]));
                asm("fma.rn.f32x2 %0, %1, %2, %0;" : "+l"(a3) : "l"(rv2[k+3]), "l"(w2[k+3]));
            }
            float l0, h0, l1, h1, l2, h2, l3, h3;
            asm("mov.b64 {%0,%1}, %2;" : "=f"(l0), "=f"(h0) : "l"(a0));
            asm("mov.b64 {%0,%1}, %2;" : "=f"(l1), "=f"(h1) : "l"(a1));
            asm("mov.b64 {%0,%1}, %2;" : "=f"(l2), "=f"(h2) : "l"(a2));
            asm("mov.b64 {%0,%1}, %2;" : "=f"(l3), "=f"(h3) : "l"(a3));
            if_s[tid] = hbase + ((l0 + h0) + (l1 + h1)) + ((l2 + h2) + (l3 + h3));
        }
        __syncthreads();
        if (tid < MD) {
            int hh = tid >> 5;
            int d  = tid & 31;
            int base = hh*65;
            float wv = if_s[base + d];
            float er = 1.f / (1.f + __expf(-if_s[base + 32 + d]));
            float ag = 1.f / (1.f + __expf(-if_s[base + 64]));
            float mo = m_s[tid];
            rv_s[tid] = rv_s[tid] + mo;
            m_s[tid]  = mo * (1.f - er*(1.f/512.f)) + (ag*(1.f/512.f))*wv;
        }
        __syncthreads();
    }
}

// ---------------------------------------------------------------------------
// Launch
// ---------------------------------------------------------------------------
extern "C" void kernel_launch(void* const* d_in, const int* in_sizes, int n_in,
                              void* d_out, int out_size)
{
    const int*   seq   = (const int*)  d_in[0];
    const float* tok   = (const float*)d_in[1];
    const float* pos   = (const float*)d_in[2];
    const float* Wqkv  = (const float*)d_in[3];
    const float* Wo    = (const float*)d_in[4];
    const float* ln1g  = (const float*)d_in[5];
    const float* ln1b  = (const float*)d_in[6];
    const float* ln2g  = (const float*)d_in[7];
    const float* ln2b  = (const float*)d_in[8];
    const float* W1    = (const float*)d_in[9];
    const float* b1    = (const float*)d_in[10];
    const float* W2    = (const float*)d_in[11];
    const float* b2    = (const float*)d_in[12];
    const float* lnfg  = (const float*)d_in[13];
    const float* lnfb  = (const float*)d_in[14];
    const float* Wlog  = (const float*)d_in[15];
    const float* blog  = (const float*)d_in[16];
    const float* Wif   = (const float*)d_in[17];
    const float* bif   = (const float*)d_in[18];
    float* out = (float*)d_out;

    float *gx, *gqkv, *gatt, *gff, *gHif;
    __half *gch, *gwlh;
    cudaGetSymbolAddress((void**)&gx,   g_x);
    cudaGetSymbolAddress((void**)&gqkv, g_qkv);
    cudaGetSymbolAddress((void**)&gatt, g_att);
    cudaGetSymbolAddress((void**)&gff,  g_ff);
    cudaGetSymbolAddress((void**)&gHif, g_Hif);
    cudaGetSymbolAddress((void**)&gch,  g_ch);
    cudaGetSymbolAddress((void**)&gwlh, g_wlh);

    // W_logits -> fp16 (independent; done early)
    wconv_kernel<<<(CDIM*VOCAB)/1024, 256>>>(Wlog, gwlh);

    embed_kernel<<<BT, DD>>>(seq, tok, pos, gx);

    for (int l = 0; l < 2; l++) {
        tc_gemm<false, true><<<dim3(12, 8), 128>>>(
            3*DD, DD, gx, DD, Wqkv + (long)l*DD*3*DD, 3*DD,
            gqkv, 3*DD, nullptr, nullptr, ln1g + l*DD, ln1b + l*DD);
        attention_kernel<<<dim3(NH, BB, TT/QC), 128>>>(gqkv, gatt);
        tc_gemm_small<<<dim3(8, 16), 128>>>(
            DD, DD, gatt, DD, Wo + (long)l*DD*DD, DD,
            gx, DD, nullptr, gx);
        tc_gemm<true, true><<<dim3(16, 8), 128>>>(
            FF_, DD, gx, DD, W1 + (long)l*DD*FF_, FF_,
            gff, FF_, b1 + l*FF_, nullptr, ln2g + l*DD, ln2b + l*DD);
        tc_gemm_small<<<dim3(8, 16), 128>>>(
            DD, FF_, gff, FF_, W2 + (long)l*FF_*DD, DD,
            gx, DD, b2 + l*DD, gx);
    }

    tc_gemm<false, true><<<dim3((IFACE + 63)/64, 8), 128>>>(
        IFACE, DD, gx, DD, Wif, IFACE, gHif, IFACE, bif, nullptr, lnfg, lnfb);

    lnf_half_kernel<<<BT, DD>>>(gx, lnfg, lnfb, gch);

    scan_kernel<<<BB, 320>>>(gHif, Wif, gch);

    logits_f16_kernel<<<dim3(4, VOCAB/128), 256>>>(gch, gwlh, out, blog);
}